// round 1
// baseline (speedup 1.0000x reference)
#include <cuda_runtime.h>
#include <math.h>

// ---------------- problem constants ----------------
#define L_       4096
#define HIDD     2048
#define Hh       64
#define Pp       64
#define Nn       128
#define CHh      256
#define NC       16
#define INTER    4096
#define CONV_DIM 4352            // INTER + 2N
#define OUT_IN   8512            // 2*(INTER+N) + H
#define XBC_OFF  INTER           // xBC col offset in zxbcdt
#define DTRAW_OFF (2*INTER + 2*Nn)  // 8448
#define Bcol_OFF INTER           // within xbc buffer
#define Ccol_OFF (INTER + Nn)

// ---------------- device scratch (static; no runtime alloc) ----------------
__device__ float g_zx[L_ * OUT_IN];          // 4096 x 8512
__device__ float g_xbc[L_ * CONV_DIM];       // conv+silu output
__device__ float g_dt[NC * Hh * CHh];        // dt per (c,h,l)
__device__ float g_acs[NC * Hh * CHh];       // inclusive cumsum of dt*A
__device__ float g_states[NC * Hh * Pp * Nn];
__device__ float g_stin[NC * Hh * Pp * Nn];  // state entering each chunk
__device__ float g_y[L_ * INTER];            // pre/post norm y (in-place)

// ---------------- generic tiled fp32 GEMM: C[M,N] = A[M,K] @ B[K,N] ----------------
// 128x128 block tile, K-tile 16, 256 threads, 8x8 microtile. M % 128 == 0, K % 16 == 0 assumed.
__global__ void gemm_f32(const float* __restrict__ A, const float* __restrict__ B,
                         float* __restrict__ C, int M, int N, int K) {
    __shared__ __align__(16) float As[16][132];
    __shared__ __align__(16) float Bs[16][132];
    const int tid = threadIdx.x;
    const int tx = tid & 15, ty = tid >> 4;
    const int row0 = blockIdx.y * 128, col0 = blockIdx.x * 128;

    float acc[8][8];
#pragma unroll
    for (int i = 0; i < 8; i++)
#pragma unroll
        for (int j = 0; j < 8; j++) acc[i][j] = 0.f;

    for (int k0 = 0; k0 < K; k0 += 16) {
#pragma unroll
        for (int i = 0; i < 8; i++) {            // A tile: 128 x 16
            int e = i * 256 + tid;
            int m = e >> 4, kk = e & 15;
            As[kk][m] = A[(size_t)(row0 + m) * K + (k0 + kk)];
        }
#pragma unroll
        for (int i = 0; i < 8; i++) {            // B tile: 16 x 128
            int e = i * 256 + tid;
            int kk = e >> 7, n = e & 127;
            int col = col0 + n;
            Bs[kk][n] = (col < N) ? B[(size_t)(k0 + kk) * N + col] : 0.f;
        }
        __syncthreads();
#pragma unroll
        for (int kk = 0; kk < 16; kk++) {
            float4 a0 = *(const float4*)&As[kk][ty * 8];
            float4 a1 = *(const float4*)&As[kk][ty * 8 + 4];
            float4 b0 = *(const float4*)&Bs[kk][tx * 8];
            float4 b1 = *(const float4*)&Bs[kk][tx * 8 + 4];
            float a[8] = {a0.x, a0.y, a0.z, a0.w, a1.x, a1.y, a1.z, a1.w};
            float b[8] = {b0.x, b0.y, b0.z, b0.w, b1.x, b1.y, b1.z, b1.w};
#pragma unroll
            for (int i = 0; i < 8; i++)
#pragma unroll
                for (int j = 0; j < 8; j++) acc[i][j] = fmaf(a[i], b[j], acc[i][j]);
        }
        __syncthreads();
    }
#pragma unroll
    for (int i = 0; i < 8; i++) {
        int r = row0 + ty * 8 + i;
#pragma unroll
        for (int j = 0; j < 8; j++) {
            int cc = col0 + tx * 8 + j;
            if (cc < N) C[(size_t)r * N + cc] = acc[i][j];
        }
    }
}

// ---------------- causal depthwise conv (K=4) + bias + silu ----------------
__global__ void conv_silu_kernel(const float* __restrict__ cw, const float* __restrict__ cb) {
    int c = blockIdx.x * 256 + threadIdx.x;   // gridDim.x = 17 -> 4352 exactly
    int l = blockIdx.y;
    float acc = cb[c];
#pragma unroll
    for (int k = 0; k < 4; k++) {
        int ll = l + k - 3;
        if (ll >= 0) acc = fmaf(g_zx[(size_t)ll * OUT_IN + XBC_OFF + c], cw[k * CONV_DIM + c], acc);
    }
    float s = acc / (1.f + expf(-acc));
    g_xbc[(size_t)l * CONV_DIM + c] = s;
}

// ---------------- dt (softplus+clip) and per-chunk inclusive cumsum of dt*A ----------------
__global__ void dtcs_kernel(const float* __restrict__ dt_bias, const float* __restrict__ A_log) {
    int c = blockIdx.x, h = blockIdx.y;
    int t = threadIdx.x;                     // local position in chunk
    int Lg = c * CHh + t;
    float raw = g_zx[(size_t)Lg * OUT_IN + DTRAW_OFF + h] + dt_bias[h];
    float sp = (raw > 20.f) ? raw : log1pf(expf(raw));
    float dt = fminf(fmaxf(sp, 0.f), 100.f);
    float A = -expf(A_log[h]);
    __shared__ float s[256];
    s[t] = dt * A;
    __syncthreads();
    for (int off = 1; off < 256; off <<= 1) {
        float v = (t >= off) ? s[t - off] : 0.f;
        __syncthreads();
        s[t] += v;
        __syncthreads();
    }
    int base = (c * Hh + h) * CHh;
    g_dt[base + t] = dt;
    g_acs[base + t] = s[t];
}

// ---------------- per-(chunk,head) states: states[p][n] = sum_l x*dt*decay * B ----------------
__global__ void states_kernel() {
    __shared__ float Xs[32][68];
    __shared__ float Bs[32][132];
    __shared__ float wv[32];
    int c = blockIdx.x, h = blockIdx.y;
    int tid = threadIdx.x;
    int tx = tid & 15, ty = tid >> 4;
    int base = (c * Hh + h) * CHh;
    float aend = g_acs[base + 255];

    float acc[4][8];
#pragma unroll
    for (int i = 0; i < 4; i++)
#pragma unroll
        for (int j = 0; j < 8; j++) acc[i][j] = 0.f;

    for (int k0 = 0; k0 < 256; k0 += 32) {
        __syncthreads();
        if (tid < 32)
            wv[tid] = g_dt[base + k0 + tid] * expf(aend - g_acs[base + k0 + tid]);
#pragma unroll
        for (int i = 0; i < 8; i++) {            // 32 x 64 x tile
            int e = i * 256 + tid;
            int kk = e >> 6, p = e & 63;
            Xs[kk][p] = g_xbc[(size_t)(c * CHh + k0 + kk) * CONV_DIM + h * 64 + p];
        }
#pragma unroll
        for (int i = 0; i < 16; i++) {           // 32 x 128 B tile
            int e = i * 256 + tid;
            int kk = e >> 7, n = e & 127;
            Bs[kk][n] = g_xbc[(size_t)(c * CHh + k0 + kk) * CONV_DIM + Bcol_OFF + n];
        }
        __syncthreads();
#pragma unroll
        for (int kk = 0; kk < 32; kk++) {
            float w = wv[kk];
            float a[4], b[8];
#pragma unroll
            for (int i = 0; i < 4; i++) a[i] = Xs[kk][ty * 4 + i] * w;
#pragma unroll
            for (int j = 0; j < 8; j++) b[j] = Bs[kk][tx * 8 + j];
#pragma unroll
            for (int i = 0; i < 4; i++)
#pragma unroll
                for (int j = 0; j < 8; j++) acc[i][j] = fmaf(a[i], b[j], acc[i][j]);
        }
    }
    float* out = g_states + (size_t)(c * Hh + h) * Pp * Nn;
#pragma unroll
    for (int i = 0; i < 4; i++)
#pragma unroll
        for (int j = 0; j < 8; j++)
            out[(ty * 4 + i) * Nn + tx * 8 + j] = acc[i][j];
}

// ---------------- inter-chunk state scan ----------------
__global__ void scan_kernel() {
    int idx = blockIdx.x * 256 + threadIdx.x;    // < 64*64*128
    int h = idx >> 13;
    int rem = idx & 8191;
    float st = 0.f;
    for (int c = 0; c < NC; c++) {
        g_stin[(size_t)(c * Hh + h) * 8192 + rem] = st;
        float cend = g_acs[(c * Hh + h) * CHh + 255];
        st = st * expf(cend) + g_states[(size_t)(c * Hh + h) * 8192 + rem];
    }
}

// ---------------- fused Y kernel: Y_diag + Y_off + x*D ----------------
// block = (ltile 0..3, chunk 0..15, head 0..63); 256 threads; dynamic smem.
#define YPAD 68
extern __shared__ __align__(16) float ysm[];
__global__ void y_kernel(const float* __restrict__ Dv) {
    float* CT   = ysm;                   // [128][68]  CT[n][l]
    float* BT   = CT + 128 * YPAD;       // [128][68]  BT[n][s] (also Sin[n][p])
    float* XT   = BT + 128 * YPAD;       // [64][68]   XT[s][p]
    float* GS   = XT + 64 * YPAD;        // [64][68]   GS[s][l]
    float* ACSL = GS + 64 * YPAD;        // [64]
    float* ACSS = ACSL + 64;             // [64]

    int lt = blockIdx.x, c = blockIdx.y, h = blockIdx.z;
    int tid = threadIdx.x;
    int tx = tid & 15, ty = tid >> 4;
    int base = (c * Hh + h) * CHh;
    int Lrow0 = c * CHh + lt * 64;

    // load C tile (transposed) and incoming state (transposed)
    for (int e = tid; e < 64 * 128; e += 256) {
        int l = e >> 7, n = e & 127;
        CT[n * YPAD + l] = g_xbc[(size_t)(Lrow0 + l) * CONV_DIM + Ccol_OFF + n];
    }
    const float* stin = g_stin + (size_t)(c * Hh + h) * (Pp * Nn);
    for (int e = tid; e < 64 * 128; e += 256) {
        int p = e >> 7, n = e & 127;
        BT[n * YPAD + p] = stin[p * Nn + n];
    }
    if (tid < 64) ACSL[tid] = g_acs[base + lt * 64 + tid];
    __syncthreads();

    float yacc[4][4];
    {   // Y_off = exp(Acs[l]) * (C . stin^T)
        float a4[4][4];
#pragma unroll
        for (int i = 0; i < 4; i++)
#pragma unroll
            for (int j = 0; j < 4; j++) a4[i][j] = 0.f;
        for (int n = 0; n < 128; n++) {
            float4 a = *(const float4*)&CT[n * YPAD + ty * 4];
            float4 b = *(const float4*)&BT[n * YPAD + tx * 4];
            float aa[4] = {a.x, a.y, a.z, a.w};
            float bb[4] = {b.x, b.y, b.z, b.w};
#pragma unroll
            for (int i = 0; i < 4; i++)
#pragma unroll
                for (int j = 0; j < 4; j++) a4[i][j] = fmaf(aa[i], bb[j], a4[i][j]);
        }
#pragma unroll
        for (int i = 0; i < 4; i++) {
            float el = expf(ACSL[ty * 4 + i]);
#pragma unroll
            for (int j = 0; j < 4; j++) yacc[i][j] = a4[i][j] * el;
        }
    }

    for (int st = 0; st <= lt; st++) {
        int Srow0 = c * CHh + st * 64;
        __syncthreads();
        for (int e = tid; e < 64 * 128; e += 256) {
            int s = e >> 7, n = e & 127;
            BT[n * YPAD + s] = g_xbc[(size_t)(Srow0 + s) * CONV_DIM + Bcol_OFF + n];
        }
        for (int e = tid; e < 64 * 64; e += 256) {
            int s = e >> 6, p = e & 63;
            XT[s * YPAD + p] = g_xbc[(size_t)(Srow0 + s) * CONV_DIM + h * 64 + p]
                             * g_dt[base + st * 64 + s];
        }
        if (tid < 64) ACSS[tid] = g_acs[base + st * 64 + tid];
        __syncthreads();

        // Phase A: G = C . B^T with decay/mask, stored transposed GS[s][l]
        float gacc[4][4];
#pragma unroll
        for (int i = 0; i < 4; i++)
#pragma unroll
            for (int j = 0; j < 4; j++) gacc[i][j] = 0.f;
        for (int n = 0; n < 128; n++) {
            float4 a = *(const float4*)&CT[n * YPAD + ty * 4];
            float4 b = *(const float4*)&BT[n * YPAD + tx * 4];
            float aa[4] = {a.x, a.y, a.z, a.w};
            float bb[4] = {b.x, b.y, b.z, b.w};
#pragma unroll
            for (int i = 0; i < 4; i++)
#pragma unroll
                for (int j = 0; j < 4; j++) gacc[i][j] = fmaf(aa[i], bb[j], gacc[i][j]);
        }
#pragma unroll
        for (int i = 0; i < 4; i++) {
#pragma unroll
            for (int j = 0; j < 4; j++) {
                int lg = lt * 64 + ty * 4 + i;
                int sg = st * 64 + tx * 4 + j;
                float v = (sg <= lg) ? gacc[i][j] * expf(ACSL[ty * 4 + i] - ACSS[tx * 4 + j]) : 0.f;
                GS[(tx * 4 + j) * YPAD + ty * 4 + i] = v;
            }
        }
        __syncthreads();

        // Phase B: yacc += GS^T . XT
        for (int s = 0; s < 64; s++) {
            float4 a = *(const float4*)&GS[s * YPAD + ty * 4];
            float4 b = *(const float4*)&XT[s * YPAD + tx * 4];
            float aa[4] = {a.x, a.y, a.z, a.w};
            float bb[4] = {b.x, b.y, b.z, b.w};
#pragma unroll
            for (int i = 0; i < 4; i++)
#pragma unroll
                for (int j = 0; j < 4; j++) yacc[i][j] = fmaf(aa[i], bb[j], yacc[i][j]);
        }
    }

    float dh = Dv[h];
#pragma unroll
    for (int i = 0; i < 4; i++) {
        int Lg = Lrow0 + ty * 4 + i;
#pragma unroll
        for (int j = 0; j < 4; j++) {
            int p = tx * 4 + j;
            float xv = g_xbc[(size_t)Lg * CONV_DIM + h * 64 + p];
            g_y[(size_t)Lg * INTER + h * 64 + p] = yacc[i][j] + xv * dh;
        }
    }
}

// ---------------- gated RMSNorm (in-place on g_y) ----------------
__global__ void rmsnorm_kernel(const float* __restrict__ nw) {
    int l = blockIdx.x;
    int tid = threadIdx.x;
    float v[16];
    float ss = 0.f;
#pragma unroll
    for (int i = 0; i < 16; i++) {
        int col = tid + i * 256;
        float y = g_y[(size_t)l * INTER + col];
        float z = g_zx[(size_t)l * OUT_IN + col];
        float yf = y * (z / (1.f + expf(-z)));
        v[i] = yf;
        ss = fmaf(yf, yf, ss);
    }
    __shared__ float red[256];
    red[tid] = ss;
    __syncthreads();
    for (int o = 128; o > 0; o >>= 1) {
        if (tid < o) red[tid] += red[tid + o];
        __syncthreads();
    }
    float scale = rsqrtf(red[0] / (float)INTER + 1e-5f);
#pragma unroll
    for (int i = 0; i < 16; i++) {
        int col = tid + i * 256;
        g_y[(size_t)l * INTER + col] = v[i] * scale * nw[col];
    }
}

// ---------------- launch ----------------
extern "C" void kernel_launch(void* const* d_in, const int* in_sizes, int n_in,
                              void* d_out, int out_size) {
    const float* hs      = (const float*)d_in[0];
    const float* W_in    = (const float*)d_in[1];
    const float* conv_w  = (const float*)d_in[2];
    const float* conv_b  = (const float*)d_in[3];
    const float* dt_bias = (const float*)d_in[4];
    const float* A_log   = (const float*)d_in[5];
    const float* Dv      = (const float*)d_in[6];
    const float* norm_w  = (const float*)d_in[7];
    const float* W_out   = (const float*)d_in[8];
    float* out = (float*)d_out;

    void *p_zx = nullptr, *p_y = nullptr;
    cudaGetSymbolAddress(&p_zx, g_zx);
    cudaGetSymbolAddress(&p_y, g_y);

    const int YSMEM = (2 * 128 * YPAD + 2 * 64 * YPAD + 128) * (int)sizeof(float); // 104960 B
    cudaFuncSetAttribute(y_kernel, cudaFuncAttributeMaxDynamicSharedMemorySize, YSMEM);

    // 1) zxbcdt = hs @ W_in   [4096, 8512]
    gemm_f32<<<dim3((OUT_IN + 127) / 128, L_ / 128), 256>>>(hs, W_in, (float*)p_zx, L_, OUT_IN, HIDD);
    // 2) conv + silu
    conv_silu_kernel<<<dim3(CONV_DIM / 256, L_), 256>>>(conv_w, conv_b);
    // 3) dt + per-chunk cumsum
    dtcs_kernel<<<dim3(NC, Hh), 256>>>(dt_bias, A_log);
    // 4) per-chunk states
    states_kernel<<<dim3(NC, Hh), 256>>>();
    // 5) inter-chunk scan
    scan_kernel<<<(Hh * Pp * Nn) / 256, 256>>>();
    // 6) Y = Y_diag + Y_off + x*D
    y_kernel<<<dim3(4, NC, Hh), 256, YSMEM>>>(Dv);
    // 7) gated RMSNorm (in place)
    rmsnorm_kernel<<<L_, 256>>>(norm_w);
    // 8) out = yn @ W_out  [4096, 2048]
    gemm_f32<<<dim3(HIDD / 128, L_ / 128), 256>>>((const float*)p_y, W_out, out, L_, HIDD, INTER);
}

// round 3
// speedup vs baseline: 2.1681x; 2.1681x over previous
#include <cuda_runtime.h>
#include <cuda_bf16.h>
#include <math.h>
#include <cstdint>

// ---------------- problem constants ----------------
#define L_       4096
#define HIDD     2048
#define Hh       64
#define Pp       64
#define Nn       128
#define CHh      256
#define NC       16
#define INTER    4096
#define CONV_DIM 4352            // INTER + 2N
#define OUT_IN   8512            // 2*(INTER+N) + H
#define OUT_IN_PAD 8576          // 67 * 128
#define XBC_OFF  INTER
#define DTRAW_OFF (2*INTER + 2*Nn)
#define Bcol_OFF INTER
#define Ccol_OFF (INTER + Nn)

// ---------------- device scratch (static; no runtime alloc) ----------------
__device__ float g_zx[L_ * OUT_IN];
__device__ float g_xbc[L_ * CONV_DIM];
__device__ float g_dt[NC * Hh * CHh];
__device__ float g_acs[NC * Hh * CHh];
__device__ float g_states[NC * Hh * Pp * Nn];
__device__ float g_stin[NC * Hh * Pp * Nn];
__device__ float g_y[L_ * INTER];

// bf16 hi/lo staging for tensor-core GEMMs
__device__ __nv_bfloat16 gA1h[L_ * HIDD];
__device__ __nv_bfloat16 gA1l[L_ * HIDD];
__device__ __nv_bfloat16 gB1h[OUT_IN_PAD * HIDD];     // W_in^T, padded
__device__ __nv_bfloat16 gB1l[OUT_IN_PAD * HIDD];
__device__ __nv_bfloat16 gA2h[L_ * INTER];
__device__ __nv_bfloat16 gA2l[L_ * INTER];
__device__ __nv_bfloat16 gB2h[HIDD * INTER];          // W_out^T
__device__ __nv_bfloat16 gB2l[HIDD * INTER];

// ================= low-level helpers (family-portable) =================
__device__ __forceinline__ uint32_t smem_u32(const void* p) {
    uint32_t a;
    asm("{ .reg .u64 t; cvta.to.shared.u64 t, %1; cvt.u32.u64 %0, t; }" : "=r"(a) : "l"(p));
    return a;
}
#define CP16(sm, gm) \
    asm volatile("cp.async.cg.shared.global [%0], [%1], 16;" :: "r"(sm), "l"(gm) : "memory")
#define CP_COMMIT() asm volatile("cp.async.commit_group;" ::: "memory")
#define CP_WAIT(n)  asm volatile("cp.async.wait_group %0;" :: "n"(n) : "memory")

__device__ __forceinline__ void ldsm_x4(uint32_t& r0, uint32_t& r1, uint32_t& r2, uint32_t& r3,
                                        uint32_t addr) {
    asm volatile("ldmatrix.sync.aligned.m8n8.x4.shared.b16 {%0,%1,%2,%3}, [%4];"
                 : "=r"(r0), "=r"(r1), "=r"(r2), "=r"(r3) : "r"(addr));
}
__device__ __forceinline__ void mma16816(float* d, const uint32_t* a, uint32_t b0, uint32_t b1) {
    asm volatile("mma.sync.aligned.m16n8k16.row.col.f32.bf16.bf16.f32 "
                 "{%0,%1,%2,%3}, {%4,%5,%6,%7}, {%8,%9}, {%0,%1,%2,%3};"
                 : "+f"(d[0]), "+f"(d[1]), "+f"(d[2]), "+f"(d[3])
                 : "r"(a[0]), "r"(a[1]), "r"(a[2]), "r"(a[3]), "r"(b0), "r"(b1));
}

// ================= split / transpose conversion kernels =================
__device__ __forceinline__ void split2(float x, __nv_bfloat16& h, __nv_bfloat16& l) {
    h = __float2bfloat16(x);
    l = __float2bfloat16(x - __bfloat162float(h));
}

__global__ void split_kernel(const float* __restrict__ in, __nv_bfloat16* __restrict__ hi,
                             __nv_bfloat16* __restrict__ lo, int n4) {
    int i = blockIdx.x * 256 + threadIdx.x;
    if (i >= n4) return;
    float4 v = ((const float4*)in)[i];
    __nv_bfloat16 h0, h1, h2, h3, l0, l1, l2, l3;
    split2(v.x, h0, l0); split2(v.y, h1, l1); split2(v.z, h2, l2); split2(v.w, h3, l3);
    __nv_bfloat162* H = (__nv_bfloat162*)hi;
    __nv_bfloat162* L = (__nv_bfloat162*)lo;
    H[i * 2]     = __nv_bfloat162{h0, h1};
    H[i * 2 + 1] = __nv_bfloat162{h2, h3};
    L[i * 2]     = __nv_bfloat162{l0, l1};
    L[i * 2 + 1] = __nv_bfloat162{l2, l3};
}

// W[K,N] fp32 -> out[Npad,K] bf16 hi/lo (transposed, zero-padded rows)
__global__ void transpose_split_kernel(const float* __restrict__ W,
                                       __nv_bfloat16* __restrict__ outH,
                                       __nv_bfloat16* __restrict__ outL,
                                       int K, int N) {
    __shared__ float tile[32][33];
    int n0 = blockIdx.x * 32, k0 = blockIdx.y * 32;
    int tx = threadIdx.x, ty = threadIdx.y;
#pragma unroll
    for (int i = 0; i < 4; i++) {
        int k = k0 + ty + i * 8;
        int n = n0 + tx;
        tile[ty + i * 8][tx] = (n < N) ? W[(size_t)k * N + n] : 0.f;
    }
    __syncthreads();
#pragma unroll
    for (int i = 0; i < 4; i++) {
        int nrow = n0 + ty + i * 8;
        int kcol = k0 + tx;
        float x = tile[tx][ty + i * 8];
        __nv_bfloat16 h, l;
        split2(x, h, l);
        outH[(size_t)nrow * K + kcol] = h;
        outL[(size_t)nrow * K + kcol] = l;
    }
}

// ================= HMMA split-bf16 GEMM =================
// C[Mtot, Nreal] = (Ah+Al)[Mtot,K] @ (Bh+Bl)[Npad,K]^T   (3-product split)
// 128x128 CTA tile, 512 threads (16 warps 4x4, warp tile 32x32), K-tile 32,
// cp.async double-buffered smem, ldmatrix operand loads. Row pitch 40 bf16 (80B).
#define KT    32
#define PITCH 40
#define ARR_B   (128 * PITCH * 2)          // bytes per array (10240)
#define STAGE_B (4 * ARR_B)                // bytes per stage (40960)

extern __shared__ __align__(16) char gsm_raw[];

__global__ void __launch_bounds__(512, 1)
gemm_hmma(const __nv_bfloat16* __restrict__ Ah, const __nv_bfloat16* __restrict__ Al,
          const __nv_bfloat16* __restrict__ Bh, const __nv_bfloat16* __restrict__ Bl,
          float* __restrict__ C, int Nreal, int K) {
    const int tid = threadIdx.x;
    const int lane = tid & 31, wid = tid >> 5;
    const int wm = wid >> 2, wn = wid & 3;       // 4x4 warp grid
    const int row0 = blockIdx.y * 128, col0 = blockIdx.x * 128;
    const uint32_t sb = smem_u32(gsm_raw);

    // per-thread cp.async slot: 512 threads = 128 rows x 4 16B-segments
    const int lrow = tid >> 2, lseg = tid & 3;
    const __nv_bfloat16* pAh = Ah + (size_t)(row0 + lrow) * K + lseg * 8;
    const __nv_bfloat16* pAl = Al + (size_t)(row0 + lrow) * K + lseg * 8;
    const __nv_bfloat16* pBh = Bh + (size_t)(col0 + lrow) * K + lseg * 8;
    const __nv_bfloat16* pBl = Bl + (size_t)(col0 + lrow) * K + lseg * 8;
    const uint32_t dst_off = (lrow * PITCH + lseg * 8) * 2;

    float acc[2][4][4];
#pragma unroll
    for (int m = 0; m < 2; m++)
#pragma unroll
        for (int n = 0; n < 4; n++)
#pragma unroll
            for (int v = 0; v < 4; v++) acc[m][n][v] = 0.f;

    const int T = K / KT;

    // prologue: stage 0
    {
        uint32_t s0 = sb + dst_off;
        CP16(s0 + 0 * ARR_B, pAh);
        CP16(s0 + 1 * ARR_B, pAl);
        CP16(s0 + 2 * ARR_B, pBh);
        CP16(s0 + 3 * ARR_B, pBl);
        CP_COMMIT();
    }

    // precomputed fragment smem offsets (within an array)
    const uint32_t a_frag_base = ((wm * 32 + (lane & 15)) * PITCH + (lane >> 4) * 8) * 2;
    const uint32_t b_frag_base = ((wn * 32 + (lane & 7) + (lane >> 4) * 8) * PITCH
                                  + ((lane >> 3) & 1) * 8) * 2;

    for (int t = 0; t < T; t++) {
        if (t + 1 < T) {
            uint32_t s1 = sb + ((t + 1) & 1) * STAGE_B + dst_off;
            int ko = (t + 1) * KT;
            CP16(s1 + 0 * ARR_B, pAh + ko);
            CP16(s1 + 1 * ARR_B, pAl + ko);
            CP16(s1 + 2 * ARR_B, pBh + ko);
            CP16(s1 + 3 * ARR_B, pBl + ko);
            CP_COMMIT();
            CP_WAIT(1);
        } else {
            CP_WAIT(0);
        }
        __syncthreads();

        const uint32_t st = sb + (t & 1) * STAGE_B;
#pragma unroll
        for (int kk = 0; kk < 2; kk++) {
            const uint32_t kb = kk * 32;   // 16 bf16 = 32 bytes
            uint32_t ah[2][4], al[2][4], bh[2][4], bl[2][4];
#pragma unroll
            for (int mt = 0; mt < 2; mt++) {
                uint32_t ao = st + a_frag_base + mt * (16 * PITCH * 2) + kb;
                ldsm_x4(ah[mt][0], ah[mt][1], ah[mt][2], ah[mt][3], ao);
                ldsm_x4(al[mt][0], al[mt][1], al[mt][2], al[mt][3], ao + ARR_B);
            }
#pragma unroll
            for (int np = 0; np < 2; np++) {
                uint32_t bo = st + 2 * ARR_B + b_frag_base + np * (16 * PITCH * 2) + kb;
                ldsm_x4(bh[np][0], bh[np][1], bh[np][2], bh[np][3], bo);
                ldsm_x4(bl[np][0], bl[np][1], bl[np][2], bl[np][3], bo + ARR_B);
            }
#pragma unroll
            for (int mt = 0; mt < 2; mt++) {
#pragma unroll
                for (int nt = 0; nt < 4; nt++) {
                    int np = nt >> 1, hv = (nt & 1) * 2;
                    mma16816(acc[mt][nt], ah[mt], bh[np][hv], bh[np][hv + 1]);
                    mma16816(acc[mt][nt], ah[mt], bl[np][hv], bl[np][hv + 1]);
                    mma16816(acc[mt][nt], al[mt], bh[np][hv], bh[np][hv + 1]);
                }
            }
        }
        __syncthreads();
    }

    // epilogue: d-fragment -> C
#pragma unroll
    for (int mt = 0; mt < 2; mt++) {
        int r = row0 + wm * 32 + mt * 16 + (lane >> 2);
#pragma unroll
        for (int nt = 0; nt < 4; nt++) {
            int c = col0 + wn * 32 + nt * 8 + (lane & 3) * 2;
            if (c < Nreal) {
                *(float2*)&C[(size_t)r * Nreal + c]       = make_float2(acc[mt][nt][0], acc[mt][nt][1]);
                *(float2*)&C[(size_t)(r + 8) * Nreal + c] = make_float2(acc[mt][nt][2], acc[mt][nt][3]);
            }
        }
    }
}

// ---------------- causal depthwise conv (K=4) + bias + silu ----------------
__global__ void conv_silu_kernel(const float* __restrict__ cw, const float* __restrict__ cb) {
    int c = blockIdx.x * 256 + threadIdx.x;
    int l = blockIdx.y;
    float acc = cb[c];
#pragma unroll
    for (int k = 0; k < 4; k++) {
        int ll = l + k - 3;
        if (ll >= 0) acc = fmaf(g_zx[(size_t)ll * OUT_IN + XBC_OFF + c], cw[k * CONV_DIM + c], acc);
    }
    float s = acc / (1.f + expf(-acc));
    g_xbc[(size_t)l * CONV_DIM + c] = s;
}

// ---------------- dt (softplus+clip) and per-chunk cumsum of dt*A ----------------
__global__ void dtcs_kernel(const float* __restrict__ dt_bias, const float* __restrict__ A_log) {
    int c = blockIdx.x, h = blockIdx.y;
    int t = threadIdx.x;
    int Lg = c * CHh + t;
    float raw = g_zx[(size_t)Lg * OUT_IN + DTRAW_OFF + h] + dt_bias[h];
    float sp = (raw > 20.f) ? raw : log1pf(expf(raw));
    float dt = fminf(fmaxf(sp, 0.f), 100.f);
    float A = -expf(A_log[h]);
    __shared__ float s[256];
    s[t] = dt * A;
    __syncthreads();
    for (int off = 1; off < 256; off <<= 1) {
        float v = (t >= off) ? s[t - off] : 0.f;
        __syncthreads();
        s[t] += v;
        __syncthreads();
    }
    int base = (c * Hh + h) * CHh;
    g_dt[base + t] = dt;
    g_acs[base + t] = s[t];
}

// ---------------- per-(chunk,head) states ----------------
__global__ void states_kernel() {
    __shared__ float Xs[32][68];
    __shared__ float Bs[32][132];
    __shared__ float wv[32];
    int c = blockIdx.x, h = blockIdx.y;
    int tid = threadIdx.x;
    int tx = tid & 15, ty = tid >> 4;
    int base = (c * Hh + h) * CHh;
    float aend = g_acs[base + 255];

    float acc[4][8];
#pragma unroll
    for (int i = 0; i < 4; i++)
#pragma unroll
        for (int j = 0; j < 8; j++) acc[i][j] = 0.f;

    for (int k0 = 0; k0 < 256; k0 += 32) {
        __syncthreads();
        if (tid < 32)
            wv[tid] = g_dt[base + k0 + tid] * expf(aend - g_acs[base + k0 + tid]);
#pragma unroll
        for (int i = 0; i < 8; i++) {
            int e = i * 256 + tid;
            int kk = e >> 6, p = e & 63;
            Xs[kk][p] = g_xbc[(size_t)(c * CHh + k0 + kk) * CONV_DIM + h * 64 + p];
        }
#pragma unroll
        for (int i = 0; i < 16; i++) {
            int e = i * 256 + tid;
            int kk = e >> 7, n = e & 127;
            Bs[kk][n] = g_xbc[(size_t)(c * CHh + k0 + kk) * CONV_DIM + Bcol_OFF + n];
        }
        __syncthreads();
#pragma unroll
        for (int kk = 0; kk < 32; kk++) {
            float w = wv[kk];
            float a[4], b[8];
#pragma unroll
            for (int i = 0; i < 4; i++) a[i] = Xs[kk][ty * 4 + i] * w;
#pragma unroll
            for (int j = 0; j < 8; j++) b[j] = Bs[kk][tx * 8 + j];
#pragma unroll
            for (int i = 0; i < 4; i++)
#pragma unroll
                for (int j = 0; j < 8; j++) acc[i][j] = fmaf(a[i], b[j], acc[i][j]);
        }
    }
    float* out = g_states + (size_t)(c * Hh + h) * Pp * Nn;
#pragma unroll
    for (int i = 0; i < 4; i++)
#pragma unroll
        for (int j = 0; j < 8; j++)
            out[(ty * 4 + i) * Nn + tx * 8 + j] = acc[i][j];
}

// ---------------- inter-chunk state scan ----------------
__global__ void scan_kernel() {
    int idx = blockIdx.x * 256 + threadIdx.x;
    int h = idx >> 13;
    int rem = idx & 8191;
    float st = 0.f;
    for (int c = 0; c < NC; c++) {
        g_stin[(size_t)(c * Hh + h) * 8192 + rem] = st;
        float cend = g_acs[(c * Hh + h) * CHh + 255];
        st = st * expf(cend) + g_states[(size_t)(c * Hh + h) * 8192 + rem];
    }
}

// ---------------- fused Y kernel ----------------
#define YPAD 68
extern __shared__ __align__(16) float ysm[];
__global__ void y_kernel(const float* __restrict__ Dv) {
    float* CT   = ysm;
    float* BT   = CT + 128 * YPAD;
    float* XT   = BT + 128 * YPAD;
    float* GS   = XT + 64 * YPAD;
    float* ACSL = GS + 64 * YPAD;
    float* ACSS = ACSL + 64;

    int lt = blockIdx.x, c = blockIdx.y, h = blockIdx.z;
    int tid = threadIdx.x;
    int tx = tid & 15, ty = tid >> 4;
    int base = (c * Hh + h) * CHh;
    int Lrow0 = c * CHh + lt * 64;

    for (int e = tid; e < 64 * 128; e += 256) {
        int l = e >> 7, n = e & 127;
        CT[n * YPAD + l] = g_xbc[(size_t)(Lrow0 + l) * CONV_DIM + Ccol_OFF + n];
    }
    const float* stin = g_stin + (size_t)(c * Hh + h) * (Pp * Nn);
    for (int e = tid; e < 64 * 128; e += 256) {
        int p = e >> 7, n = e & 127;
        BT[n * YPAD + p] = stin[p * Nn + n];
    }
    if (tid < 64) ACSL[tid] = g_acs[base + lt * 64 + tid];
    __syncthreads();

    float yacc[4][4];
    {
        float a4[4][4];
#pragma unroll
        for (int i = 0; i < 4; i++)
#pragma unroll
            for (int j = 0; j < 4; j++) a4[i][j] = 0.f;
        for (int n = 0; n < 128; n++) {
            float4 a = *(const float4*)&CT[n * YPAD + ty * 4];
            float4 b = *(const float4*)&BT[n * YPAD + tx * 4];
            float aa[4] = {a.x, a.y, a.z, a.w};
            float bb[4] = {b.x, b.y, b.z, b.w};
#pragma unroll
            for (int i = 0; i < 4; i++)
#pragma unroll
                for (int j = 0; j < 4; j++) a4[i][j] = fmaf(aa[i], bb[j], a4[i][j]);
        }
#pragma unroll
        for (int i = 0; i < 4; i++) {
            float el = expf(ACSL[ty * 4 + i]);
#pragma unroll
            for (int j = 0; j < 4; j++) yacc[i][j] = a4[i][j] * el;
        }
    }

    for (int st = 0; st <= lt; st++) {
        int Srow0 = c * CHh + st * 64;
        __syncthreads();
        for (int e = tid; e < 64 * 128; e += 256) {
            int s = e >> 7, n = e & 127;
            BT[n * YPAD + s] = g_xbc[(size_t)(Srow0 + s) * CONV_DIM + Bcol_OFF + n];
        }
        for (int e = tid; e < 64 * 64; e += 256) {
            int s = e >> 6, p = e & 63;
            XT[s * YPAD + p] = g_xbc[(size_t)(Srow0 + s) * CONV_DIM + h * 64 + p]
                             * g_dt[base + st * 64 + s];
        }
        if (tid < 64) ACSS[tid] = g_acs[base + st * 64 + tid];
        __syncthreads();

        float gacc[4][4];
#pragma unroll
        for (int i = 0; i < 4; i++)
#pragma unroll
            for (int j = 0; j < 4; j++) gacc[i][j] = 0.f;
        for (int n = 0; n < 128; n++) {
            float4 a = *(const float4*)&CT[n * YPAD + ty * 4];
            float4 b = *(const float4*)&BT[n * YPAD + tx * 4];
            float aa[4] = {a.x, a.y, a.z, a.w};
            float bb[4] = {b.x, b.y, b.z, b.w};
#pragma unroll
            for (int i = 0; i < 4; i++)
#pragma unroll
                for (int j = 0; j < 4; j++) gacc[i][j] = fmaf(aa[i], bb[j], gacc[i][j]);
        }
#pragma unroll
        for (int i = 0; i < 4; i++) {
#pragma unroll
            for (int j = 0; j < 4; j++) {
                int lg = lt * 64 + ty * 4 + i;
                int sg = st * 64 + tx * 4 + j;
                float v = (sg <= lg) ? gacc[i][j] * expf(ACSL[ty * 4 + i] - ACSS[tx * 4 + j]) : 0.f;
                GS[(tx * 4 + j) * YPAD + ty * 4 + i] = v;
            }
        }
        __syncthreads();

        for (int s = 0; s < 64; s++) {
            float4 a = *(const float4*)&GS[s * YPAD + ty * 4];
            float4 b = *(const float4*)&XT[s * YPAD + tx * 4];
            float aa[4] = {a.x, a.y, a.z, a.w};
            float bb[4] = {b.x, b.y, b.z, b.w};
#pragma unroll
            for (int i = 0; i < 4; i++)
#pragma unroll
                for (int j = 0; j < 4; j++) yacc[i][j] = fmaf(aa[i], bb[j], yacc[i][j]);
        }
    }

    float dh = Dv[h];
#pragma unroll
    for (int i = 0; i < 4; i++) {
        int Lg = Lrow0 + ty * 4 + i;
#pragma unroll
        for (int j = 0; j < 4; j++) {
            int p = tx * 4 + j;
            float xv = g_xbc[(size_t)Lg * CONV_DIM + h * 64 + p];
            g_y[(size_t)Lg * INTER + h * 64 + p] = yacc[i][j] + xv * dh;
        }
    }
}

// ---------------- gated RMSNorm (in-place on g_y) ----------------
__global__ void rmsnorm_kernel(const float* __restrict__ nw) {
    int l = blockIdx.x;
    int tid = threadIdx.x;
    float v[16];
    float ss = 0.f;
#pragma unroll
    for (int i = 0; i < 16; i++) {
        int col = tid + i * 256;
        float y = g_y[(size_t)l * INTER + col];
        float z = g_zx[(size_t)l * OUT_IN + col];
        float yf = y * (z / (1.f + expf(-z)));
        v[i] = yf;
        ss = fmaf(yf, yf, ss);
    }
    __shared__ float red[256];
    red[tid] = ss;
    __syncthreads();
    for (int o = 128; o > 0; o >>= 1) {
        if (tid < o) red[tid] += red[tid + o];
        __syncthreads();
    }
    float scale = rsqrtf(red[0] / (float)INTER + 1e-5f);
#pragma unroll
    for (int i = 0; i < 16; i++) {
        int col = tid + i * 256;
        g_y[(size_t)l * INTER + col] = v[i] * scale * nw[col];
    }
}

// ---------------- launch ----------------
extern "C" void kernel_launch(void* const* d_in, const int* in_sizes, int n_in,
                              void* d_out, int out_size) {
    const float* hs      = (const float*)d_in[0];
    const float* W_in    = (const float*)d_in[1];
    const float* conv_w  = (const float*)d_in[2];
    const float* conv_b  = (const float*)d_in[3];
    const float* dt_bias = (const float*)d_in[4];
    const float* A_log   = (const float*)d_in[5];
    const float* Dv      = (const float*)d_in[6];
    const float* norm_w  = (const float*)d_in[7];
    const float* W_out   = (const float*)d_in[8];
    float* out = (float*)d_out;

    void *p_zx, *p_y;
    void *pA1h, *pA1l, *pB1h, *pB1l, *pA2h, *pA2l, *pB2h, *pB2l;
    cudaGetSymbolAddress(&p_zx, g_zx);
    cudaGetSymbolAddress(&p_y, g_y);
    cudaGetSymbolAddress(&pA1h, gA1h); cudaGetSymbolAddress(&pA1l, gA1l);
    cudaGetSymbolAddress(&pB1h, gB1h); cudaGetSymbolAddress(&pB1l, gB1l);
    cudaGetSymbolAddress(&pA2h, gA2h); cudaGetSymbolAddress(&pA2l, gA2l);
    cudaGetSymbolAddress(&pB2h, gB2h); cudaGetSymbolAddress(&pB2l, gB2l);

    const int YSMEM = (2 * 128 * YPAD + 2 * 64 * YPAD + 128) * (int)sizeof(float);
    cudaFuncSetAttribute(y_kernel, cudaFuncAttributeMaxDynamicSharedMemorySize, YSMEM);
    const int GSMEM = 2 * STAGE_B;   // 81920 B
    cudaFuncSetAttribute(gemm_hmma, cudaFuncAttributeMaxDynamicSharedMemorySize, GSMEM);

    // 0a) split hs -> A1 (bf16 hi/lo)
    split_kernel<<<(L_ * HIDD / 4 + 255) / 256, 256>>>(hs, (__nv_bfloat16*)pA1h, (__nv_bfloat16*)pA1l, L_ * HIDD / 4);
    // 0b) transpose+split W_in -> B1 [8576, 2048]
    transpose_split_kernel<<<dim3(OUT_IN_PAD / 32, HIDD / 32), dim3(32, 8)>>>(
        W_in, (__nv_bfloat16*)pB1h, (__nv_bfloat16*)pB1l, HIDD, OUT_IN);
    // 1) zxbcdt = hs @ W_in (HMMA split-bf16)
    gemm_hmma<<<dim3(OUT_IN_PAD / 128, L_ / 128), 512, GSMEM>>>(
        (const __nv_bfloat16*)pA1h, (const __nv_bfloat16*)pA1l,
        (const __nv_bfloat16*)pB1h, (const __nv_bfloat16*)pB1l,
        (float*)p_zx, OUT_IN, HIDD);
    // 2) conv + silu
    conv_silu_kernel<<<dim3(CONV_DIM / 256, L_), 256>>>(conv_w, conv_b);
    // 3) dt + per-chunk cumsum
    dtcs_kernel<<<dim3(NC, Hh), 256>>>(dt_bias, A_log);
    // 4) per-chunk states
    states_kernel<<<dim3(NC, Hh), 256>>>();
    // 5) inter-chunk scan
    scan_kernel<<<(Hh * Pp * Nn) / 256, 256>>>();
    // 6) Y = Y_diag + Y_off + x*D
    y_kernel<<<dim3(4, NC, Hh), 256, YSMEM>>>(Dv);
    // 7) gated RMSNorm
    rmsnorm_kernel<<<L_, 256>>>(norm_w);
    // 8a) split y -> A2
    split_kernel<<<(L_ * INTER / 4 + 255) / 256, 256>>>((const float*)p_y, (__nv_bfloat16*)pA2h, (__nv_bfloat16*)pA2l, L_ * INTER / 4);
    // 8b) transpose+split W_out -> B2 [2048, 4096]
    transpose_split_kernel<<<dim3(HIDD / 32, INTER / 32), dim3(32, 8)>>>(
        W_out, (__nv_bfloat16*)pB2h, (__nv_bfloat16*)pB2l, INTER, HIDD);
    // 8c) out = yn @ W_out (HMMA)
    gemm_hmma<<<dim3(HIDD / 128, L_ / 128), 512, GSMEM>>>(
        (const __nv_bfloat16*)pA2h, (const __nv_bfloat16*)pA2l,
        (const __nv_bfloat16*)pB2h, (const __nv_bfloat16*)pB2l,
        out, HIDD, INTER);
}

// round 4
// speedup vs baseline: 2.5430x; 1.1729x over previous
#include <cuda_runtime.h>
#include <cuda_bf16.h>
#include <math.h>
#include <cstdint>

// ---------------- problem constants ----------------
#define L_       4096
#define HIDD     2048
#define Hh       64
#define Pp       64
#define Nn       128
#define CHh      256
#define NC       16
#define INTER    4096
#define CONV_DIM 4352            // INTER + 2N
#define OUT_IN   8512            // 2*(INTER+N) + H
#define OUT_IN_PAD 8576          // 67 * 128
#define XBC_OFF  INTER
#define DTRAW_OFF (2*INTER + 2*Nn)

// ---------------- device scratch (static; no runtime alloc) ----------------
__device__ float g_zx[L_ * OUT_IN];
__device__ float g_xbc[L_ * CONV_DIM];
__device__ float g_dt[NC * Hh * CHh];
__device__ float g_acs[NC * Hh * CHh];
__device__ float g_states[NC * Hh * Pp * Nn];
__device__ float g_y[L_ * INTER];

// bf16 hi/lo staging for tensor-core GEMMs
__device__ __nv_bfloat16 gA1h[L_ * HIDD];
__device__ __nv_bfloat16 gA1l[L_ * HIDD];
__device__ __nv_bfloat16 gB1h[OUT_IN_PAD * HIDD];
__device__ __nv_bfloat16 gB1l[OUT_IN_PAD * HIDD];
__device__ __nv_bfloat16 gA2h[L_ * INTER];
__device__ __nv_bfloat16 gA2l[L_ * INTER];
__device__ __nv_bfloat16 gB2h[HIDD * INTER];
__device__ __nv_bfloat16 gB2l[HIDD * INTER];

// bf16 hi/lo for SSM tensor-core path
__device__ __nv_bfloat16 g_xdth[L_ * INTER];   // x * dt
__device__ __nv_bfloat16 g_xdtl[L_ * INTER];
__device__ __nv_bfloat16 g_bch[L_ * 256];      // [B(128) | C(128)]
__device__ __nv_bfloat16 g_bcl[L_ * 256];
__device__ __nv_bfloat16 g_stinh[NC * Hh * Pp * Nn];
__device__ __nv_bfloat16 g_stinl[NC * Hh * Pp * Nn];

// ================= low-level helpers =================
__device__ __forceinline__ uint32_t smem_u32(const void* p) {
    uint32_t a;
    asm("{ .reg .u64 t; cvta.to.shared.u64 t, %1; cvt.u32.u64 %0, t; }" : "=r"(a) : "l"(p));
    return a;
}
#define CP16(sm, gm) \
    asm volatile("cp.async.cg.shared.global [%0], [%1], 16;" :: "r"(sm), "l"(gm) : "memory")
#define CP_COMMIT() asm volatile("cp.async.commit_group;" ::: "memory")
#define CP_WAIT(n)  asm volatile("cp.async.wait_group %0;" :: "n"(n) : "memory")

__device__ __forceinline__ void ldsm_x4(uint32_t& r0, uint32_t& r1, uint32_t& r2, uint32_t& r3,
                                        uint32_t addr) {
    asm volatile("ldmatrix.sync.aligned.m8n8.x4.shared.b16 {%0,%1,%2,%3}, [%4];"
                 : "=r"(r0), "=r"(r1), "=r"(r2), "=r"(r3) : "r"(addr));
}
__device__ __forceinline__ void ldsm_x4_t(uint32_t& r0, uint32_t& r1, uint32_t& r2, uint32_t& r3,
                                          uint32_t addr) {
    asm volatile("ldmatrix.sync.aligned.m8n8.x4.trans.shared.b16 {%0,%1,%2,%3}, [%4];"
                 : "=r"(r0), "=r"(r1), "=r"(r2), "=r"(r3) : "r"(addr));
}
__device__ __forceinline__ void mma16816(float* d, const uint32_t* a, uint32_t b0, uint32_t b1) {
    asm volatile("mma.sync.aligned.m16n8k16.row.col.f32.bf16.bf16.f32 "
                 "{%0,%1,%2,%3}, {%4,%5,%6,%7}, {%8,%9}, {%0,%1,%2,%3};"
                 : "+f"(d[0]), "+f"(d[1]), "+f"(d[2]), "+f"(d[3])
                 : "r"(a[0]), "r"(a[1]), "r"(a[2]), "r"(a[3]), "r"(b0), "r"(b1));
}
__device__ __forceinline__ uint32_t pk(__nv_bfloat16 a, __nv_bfloat16 b) {
    __nv_bfloat162 t; t.x = a; t.y = b;
    return *reinterpret_cast<uint32_t*>(&t);
}
__device__ __forceinline__ void split2(float x, __nv_bfloat16& h, __nv_bfloat16& l) {
    h = __float2bfloat16(x);
    l = __float2bfloat16(x - __bfloat162float(h));
}

// ================= split / transpose conversion kernels =================
__global__ void split_kernel(const float* __restrict__ in, __nv_bfloat16* __restrict__ hi,
                             __nv_bfloat16* __restrict__ lo, int n4) {
    int i = blockIdx.x * 256 + threadIdx.x;
    if (i >= n4) return;
    float4 v = ((const float4*)in)[i];
    __nv_bfloat16 h0, h1, h2, h3, l0, l1, l2, l3;
    split2(v.x, h0, l0); split2(v.y, h1, l1); split2(v.z, h2, l2); split2(v.w, h3, l3);
    ((uint2*)hi)[i] = make_uint2(pk(h0, h1), pk(h2, h3));
    ((uint2*)lo)[i] = make_uint2(pk(l0, l1), pk(l2, l3));
}

__global__ void transpose_split_kernel(const float* __restrict__ W,
                                       __nv_bfloat16* __restrict__ outH,
                                       __nv_bfloat16* __restrict__ outL,
                                       int K, int N) {
    __shared__ float tile[32][33];
    int n0 = blockIdx.x * 32, k0 = blockIdx.y * 32;
    int tx = threadIdx.x, ty = threadIdx.y;
#pragma unroll
    for (int i = 0; i < 4; i++) {
        int k = k0 + ty + i * 8;
        int n = n0 + tx;
        tile[ty + i * 8][tx] = (n < N) ? W[(size_t)k * N + n] : 0.f;
    }
    __syncthreads();
#pragma unroll
    for (int i = 0; i < 4; i++) {
        int nrow = n0 + ty + i * 8;
        int kcol = k0 + tx;
        float x = tile[tx][ty + i * 8];
        __nv_bfloat16 h, l;
        split2(x, h, l);
        outH[(size_t)nrow * K + kcol] = h;
        outL[(size_t)nrow * K + kcol] = l;
    }
}

// ================= HMMA split-bf16 GEMM (unchanged from R3) =================
#define KT    32
#define PITCH 40
#define ARR_B   (128 * PITCH * 2)
#define STAGE_B (4 * ARR_B)

extern __shared__ __align__(128) char gsm_raw[];

__global__ void __launch_bounds__(512, 1)
gemm_hmma(const __nv_bfloat16* __restrict__ Ah, const __nv_bfloat16* __restrict__ Al,
          const __nv_bfloat16* __restrict__ Bh, const __nv_bfloat16* __restrict__ Bl,
          float* __restrict__ C, int Nreal, int K) {
    const int tid = threadIdx.x;
    const int lane = tid & 31, wid = tid >> 5;
    const int wm = wid >> 2, wn = wid & 3;
    const int row0 = blockIdx.y * 128, col0 = blockIdx.x * 128;
    const uint32_t sb = smem_u32(gsm_raw);

    const int lrow = tid >> 2, lseg = tid & 3;
    const __nv_bfloat16* pAh = Ah + (size_t)(row0 + lrow) * K + lseg * 8;
    const __nv_bfloat16* pAl = Al + (size_t)(row0 + lrow) * K + lseg * 8;
    const __nv_bfloat16* pBh = Bh + (size_t)(col0 + lrow) * K + lseg * 8;
    const __nv_bfloat16* pBl = Bl + (size_t)(col0 + lrow) * K + lseg * 8;
    const uint32_t dst_off = (lrow * PITCH + lseg * 8) * 2;

    float acc[2][4][4];
#pragma unroll
    for (int m = 0; m < 2; m++)
#pragma unroll
        for (int n = 0; n < 4; n++)
#pragma unroll
            for (int v = 0; v < 4; v++) acc[m][n][v] = 0.f;

    const int T = K / KT;
    {
        uint32_t s0 = sb + dst_off;
        CP16(s0 + 0 * ARR_B, pAh);
        CP16(s0 + 1 * ARR_B, pAl);
        CP16(s0 + 2 * ARR_B, pBh);
        CP16(s0 + 3 * ARR_B, pBl);
        CP_COMMIT();
    }

    const uint32_t a_frag_base = ((wm * 32 + (lane & 15)) * PITCH + (lane >> 4) * 8) * 2;
    const uint32_t b_frag_base = ((wn * 32 + (lane & 7) + (lane >> 4) * 8) * PITCH
                                  + ((lane >> 3) & 1) * 8) * 2;

    for (int t = 0; t < T; t++) {
        if (t + 1 < T) {
            uint32_t s1 = sb + ((t + 1) & 1) * STAGE_B + dst_off;
            int ko = (t + 1) * KT;
            CP16(s1 + 0 * ARR_B, pAh + ko);
            CP16(s1 + 1 * ARR_B, pAl + ko);
            CP16(s1 + 2 * ARR_B, pBh + ko);
            CP16(s1 + 3 * ARR_B, pBl + ko);
            CP_COMMIT();
            CP_WAIT(1);
        } else {
            CP_WAIT(0);
        }
        __syncthreads();

        const uint32_t st = sb + (t & 1) * STAGE_B;
#pragma unroll
        for (int kk = 0; kk < 2; kk++) {
            const uint32_t kb = kk * 32;
            uint32_t ah[2][4], al[2][4], bh[2][4], bl[2][4];
#pragma unroll
            for (int mt = 0; mt < 2; mt++) {
                uint32_t ao = st + a_frag_base + mt * (16 * PITCH * 2) + kb;
                ldsm_x4(ah[mt][0], ah[mt][1], ah[mt][2], ah[mt][3], ao);
                ldsm_x4(al[mt][0], al[mt][1], al[mt][2], al[mt][3], ao + ARR_B);
            }
#pragma unroll
            for (int np = 0; np < 2; np++) {
                uint32_t bo = st + 2 * ARR_B + b_frag_base + np * (16 * PITCH * 2) + kb;
                ldsm_x4(bh[np][0], bh[np][1], bh[np][2], bh[np][3], bo);
                ldsm_x4(bl[np][0], bl[np][1], bl[np][2], bl[np][3], bo + ARR_B);
            }
#pragma unroll
            for (int mt = 0; mt < 2; mt++) {
#pragma unroll
                for (int nt = 0; nt < 4; nt++) {
                    int np = nt >> 1, hv = (nt & 1) * 2;
                    mma16816(acc[mt][nt], ah[mt], bh[np][hv], bh[np][hv + 1]);
                    mma16816(acc[mt][nt], ah[mt], bl[np][hv], bl[np][hv + 1]);
                    mma16816(acc[mt][nt], al[mt], bh[np][hv], bh[np][hv + 1]);
                }
            }
        }
        __syncthreads();
    }

#pragma unroll
    for (int mt = 0; mt < 2; mt++) {
        int r = row0 + wm * 32 + mt * 16 + (lane >> 2);
#pragma unroll
        for (int nt = 0; nt < 4; nt++) {
            int c = col0 + wn * 32 + nt * 8 + (lane & 3) * 2;
            if (c < Nreal) {
                *(float2*)&C[(size_t)r * Nreal + c]       = make_float2(acc[mt][nt][0], acc[mt][nt][1]);
                *(float2*)&C[(size_t)(r + 8) * Nreal + c] = make_float2(acc[mt][nt][2], acc[mt][nt][3]);
            }
        }
    }
}

// ---------------- causal depthwise conv (K=4) + bias + silu ----------------
__global__ void conv_silu_kernel(const float* __restrict__ cw, const float* __restrict__ cb) {
    int c = blockIdx.x * 256 + threadIdx.x;
    int l = blockIdx.y;
    float acc = cb[c];
#pragma unroll
    for (int k = 0; k < 4; k++) {
        int ll = l + k - 3;
        if (ll >= 0) acc = fmaf(g_zx[(size_t)ll * OUT_IN + XBC_OFF + c], cw[k * CONV_DIM + c], acc);
    }
    float s = acc / (1.f + expf(-acc));
    g_xbc[(size_t)l * CONV_DIM + c] = s;
}

// ---------------- dt (softplus+clip) and per-chunk cumsum of dt*A ----------------
__global__ void dtcs_kernel(const float* __restrict__ dt_bias, const float* __restrict__ A_log) {
    int c = blockIdx.x, h = blockIdx.y;
    int t = threadIdx.x;
    int Lg = c * CHh + t;
    float raw = g_zx[(size_t)Lg * OUT_IN + DTRAW_OFF + h] + dt_bias[h];
    float sp = (raw > 20.f) ? raw : log1pf(expf(raw));
    float dt = fminf(fmaxf(sp, 0.f), 100.f);
    float A = -expf(A_log[h]);
    __shared__ float s[256];
    s[t] = dt * A;
    __syncthreads();
    for (int off = 1; off < 256; off <<= 1) {
        float v = (t >= off) ? s[t - off] : 0.f;
        __syncthreads();
        s[t] += v;
        __syncthreads();
    }
    int base = (c * Hh + h) * CHh;
    g_dt[base + t] = dt;
    g_acs[base + t] = s[t];
}

// ---------------- prep: split xdt and B/C into bf16 hi/lo ----------------
__global__ void prep_xdt_kernel() {
    int idx = blockIdx.x * 256 + threadIdx.x;       // < L*INTER/4
    int l = idx >> 10;
    int c4 = (idx & 1023) << 2;
    int h = c4 >> 6;
    float dtv = g_dt[((l >> 8) * Hh + h) * CHh + (l & 255)];
    float4 x = *(const float4*)&g_xbc[(size_t)l * CONV_DIM + c4];
    __nv_bfloat16 h0, h1, h2, h3, l0, l1, l2, l3;
    split2(x.x * dtv, h0, l0); split2(x.y * dtv, h1, l1);
    split2(x.z * dtv, h2, l2); split2(x.w * dtv, h3, l3);
    *(uint2*)&g_xdth[(size_t)l * INTER + c4] = make_uint2(pk(h0, h1), pk(h2, h3));
    *(uint2*)&g_xdtl[(size_t)l * INTER + c4] = make_uint2(pk(l0, l1), pk(l2, l3));
}

__global__ void prep_bc_kernel() {
    int idx = blockIdx.x * 256 + threadIdx.x;       // < L*256/4
    int l = idx >> 6;
    int c4 = (idx & 63) << 2;
    float4 x = *(const float4*)&g_xbc[(size_t)l * CONV_DIM + INTER + c4];
    __nv_bfloat16 h0, h1, h2, h3, l0, l1, l2, l3;
    split2(x.x, h0, l0); split2(x.y, h1, l1); split2(x.z, h2, l2); split2(x.w, h3, l3);
    *(uint2*)&g_bch[(size_t)l * 256 + c4] = make_uint2(pk(h0, h1), pk(h2, h3));
    *(uint2*)&g_bcl[(size_t)l * 256 + c4] = make_uint2(pk(l0, l1), pk(l2, l3));
}

// ---------------- HMMA states: S[p][n] = sum_l (decay*xdt)[l,p] * B[l,n] ----------------
// smem: Xh 0 (9216), Xl 9216, Bh 18432 (17408), Bl 35840, wbuf 53248 (1KB) = 54272
extern __shared__ __align__(128) char ssm2[];
__global__ void __launch_bounds__(128, 2)
states_hmma() {
    const uint32_t sb = smem_u32(ssm2);
    const int tid = threadIdx.x, lane = tid & 31, w = tid >> 5;
    const int c = blockIdx.x, h = blockIdx.y;
    const int base = (c * Hh + h) * CHh;
    const float aend = g_acs[base + 255];
    float* wb = (float*)(ssm2 + 53248);
    for (int t = tid; t < 256; t += 128) wb[t] = expf(aend - g_acs[base + t]);

    float sacc[16][4];
#pragma unroll
    for (int j = 0; j < 16; j++)
#pragma unroll
        for (int v = 0; v < 4; v++) sacc[j][v] = 0.f;

    const uint32_t axb = sb + ((lane & 7) + (lane >> 4) * 8) * 144 + 32 * w + ((lane >> 3) & 1) * 16;
    const uint32_t bxb = sb + 18432 + ((lane & 7) + ((lane >> 3) & 1) * 8) * 272 + (lane >> 4) * 16;

    for (int kt = 0; kt < 4; kt++) {
        __syncthreads();
        int l0 = kt * 64;
        // stage X' = decay * xdt (reconstruct fp32, scale, re-split)
        for (int e = tid; e < 2048; e += 128) {
            int row = e >> 5, seg = e & 31;
            int lg = c * CHh + l0 + row;
            __nv_bfloat162 xh2 = *(const __nv_bfloat162*)&g_xdth[(size_t)lg * INTER + h * 64 + seg * 2];
            __nv_bfloat162 xl2 = *(const __nv_bfloat162*)&g_xdtl[(size_t)lg * INTER + h * 64 + seg * 2];
            float wv = wb[l0 + row];
            float v0 = (__bfloat162float(xh2.x) + __bfloat162float(xl2.x)) * wv;
            float v1 = (__bfloat162float(xh2.y) + __bfloat162float(xl2.y)) * wv;
            __nv_bfloat16 a0, a1, b0, b1;
            split2(v0, a0, b0); split2(v1, a1, b1);
            *(uint32_t*)(ssm2 + row * 144 + seg * 4) = pk(a0, a1);
            *(uint32_t*)(ssm2 + 9216 + row * 144 + seg * 4) = pk(b0, b1);
        }
        // stage B (direct split copy)
        for (int e = tid; e < 2048; e += 128) {
            int row = e >> 5, seg = e & 31;
            int lg = c * CHh + l0 + row;
            *(uint2*)(ssm2 + 18432 + row * 272 + seg * 8) = *(const uint2*)&g_bch[(size_t)lg * 256 + seg * 4];
            *(uint2*)(ssm2 + 35840 + row * 272 + seg * 8) = *(const uint2*)&g_bcl[(size_t)lg * 256 + seg * 4];
        }
        __syncthreads();

#pragma unroll
        for (int t = 0; t < 4; t++) {
            uint32_t ah[4], al[4];
            ldsm_x4_t(ah[0], ah[1], ah[2], ah[3], axb + t * 2304);
            ldsm_x4_t(al[0], al[1], al[2], al[3], axb + 9216 + t * 2304);
#pragma unroll
            for (int np = 0; np < 8; np++) {
                uint32_t bh[4], bl[4];
                ldsm_x4_t(bh[0], bh[1], bh[2], bh[3], bxb + t * 4352 + np * 32);
                ldsm_x4_t(bl[0], bl[1], bl[2], bl[3], bxb + 17408 + t * 4352 + np * 32);
                mma16816(sacc[2 * np],     ah, bh[0], bh[1]);
                mma16816(sacc[2 * np + 1], ah, bh[2], bh[3]);
                mma16816(sacc[2 * np],     ah, bl[0], bl[1]);
                mma16816(sacc[2 * np + 1], ah, bl[2], bl[3]);
                mma16816(sacc[2 * np],     al, bh[0], bh[1]);
                mma16816(sacc[2 * np + 1], al, bh[2], bh[3]);
            }
        }
    }

    float* out = g_states + (size_t)(c * Hh + h) * 8192;
    int p0 = 16 * w + (lane >> 2);
#pragma unroll
    for (int j = 0; j < 16; j++) {
        int n = 8 * j + 2 * (lane & 3);
        *(float2*)&out[p0 * 128 + n]       = make_float2(sacc[j][0], sacc[j][1]);
        *(float2*)&out[(p0 + 8) * 128 + n] = make_float2(sacc[j][2], sacc[j][3]);
    }
}

// ---------------- inter-chunk state scan (emits split stin) ----------------
__global__ void scan_kernel() {
    int idx = blockIdx.x * 256 + threadIdx.x;
    int h = idx >> 13;
    int rem = idx & 8191;
    float st = 0.f;
    for (int c = 0; c < NC; c++) {
        size_t o = (size_t)(c * Hh + h) * 8192 + rem;
        __nv_bfloat16 hi, lo;
        split2(st, hi, lo);
        g_stinh[o] = hi;
        g_stinl[o] = lo;
        float cend = g_acs[(c * Hh + h) * CHh + 255];
        st = st * expf(cend) + g_states[o];
    }
}

// ---------------- HMMA fused Y kernel ----------------
// smem: Ch 0 (17408), Cl 17408, Uh 34816 (Sin then B), Ul 52224,
//       Xh 69632 (9216), Xl 78848, ACSL 88064, ACSS 88320 -> 88576 bytes
#define OFF_CL  17408
#define OFF_UH  34816
#define OFF_UL  52224
#define OFF_XH  69632
#define OFF_XL  78848
#define OFF_AL  88064
#define OFF_AS  88320
extern __shared__ __align__(128) char ysm2[];
__global__ void __launch_bounds__(128, 2)
y_hmma(const float* __restrict__ Dv) {
    const uint32_t sb = smem_u32(ysm2);
    const int tid = threadIdx.x, lane = tid & 31, w = tid >> 5;
    const int lt = blockIdx.x, c = blockIdx.y, h = blockIdx.z;
    const int base = (c * Hh + h) * CHh;
    const int Lrow0 = c * CHh + lt * 64;
    float* acsl = (float*)(ysm2 + OFF_AL);
    float* acss = (float*)(ysm2 + OFF_AS);

    // stage C (hi/lo) and Sin (hi/lo)
    {
        const size_t sinb = (size_t)(c * Hh + h) * 8192;
        for (int e = tid; e < 2048; e += 128) {
            int row = e >> 5, seg = e & 31;
            *(uint2*)(ysm2 + row * 272 + seg * 8) =
                *(const uint2*)&g_bch[(size_t)(Lrow0 + row) * 256 + 128 + seg * 4];
            *(uint2*)(ysm2 + OFF_CL + row * 272 + seg * 8) =
                *(const uint2*)&g_bcl[(size_t)(Lrow0 + row) * 256 + 128 + seg * 4];
            *(uint2*)(ysm2 + OFF_UH + row * 272 + seg * 8) =
                *(const uint2*)&g_stinh[sinb + row * 128 + seg * 4];
            *(uint2*)(ysm2 + OFF_UL + row * 272 + seg * 8) =
                *(const uint2*)&g_stinl[sinb + row * 128 + seg * 4];
        }
        if (tid < 64) acsl[tid] = g_acs[base + lt * 64 + tid];
    }
    __syncthreads();

    const uint32_t a_base = sb + (16 * w + (lane & 15)) * 272 + (lane >> 4) * 16;
    const uint32_t b_base = sb + OFF_UH + ((lane & 7) + (lane >> 4) * 8) * 272 + ((lane >> 3) & 1) * 16;
    const uint32_t x_base = sb + OFF_XH + ((lane & 7) + ((lane >> 3) & 1) * 8) * 144 + (lane >> 4) * 16;

    float yacc[8][4];
#pragma unroll
    for (int j = 0; j < 8; j++)
#pragma unroll
        for (int v = 0; v < 4; v++) yacc[j][v] = 0.f;

    // Y_off = C . Sin^T
#pragma unroll
    for (int kk = 0; kk < 8; kk++) {
        uint32_t ah[4], al[4];
        ldsm_x4(ah[0], ah[1], ah[2], ah[3], a_base + kk * 32);
        ldsm_x4(al[0], al[1], al[2], al[3], a_base + OFF_CL + kk * 32);
#pragma unroll
        for (int np = 0; np < 4; np++) {
            uint32_t bh[4], bl[4];
            ldsm_x4(bh[0], bh[1], bh[2], bh[3], b_base + np * 4352 + kk * 32);
            ldsm_x4(bl[0], bl[1], bl[2], bl[3], b_base + 17408 + np * 4352 + kk * 32);
            mma16816(yacc[2 * np],     ah, bh[0], bh[1]);
            mma16816(yacc[2 * np + 1], ah, bh[2], bh[3]);
            mma16816(yacc[2 * np],     ah, bl[0], bl[1]);
            mma16816(yacc[2 * np + 1], ah, bl[2], bl[3]);
            mma16816(yacc[2 * np],     al, bh[0], bh[1]);
            mma16816(yacc[2 * np + 1], al, bh[2], bh[3]);
        }
    }
    {
        float e0 = expf(acsl[16 * w + (lane >> 2)]);
        float e1 = expf(acsl[16 * w + (lane >> 2) + 8]);
#pragma unroll
        for (int j = 0; j < 8; j++) {
            yacc[j][0] *= e0; yacc[j][1] *= e0;
            yacc[j][2] *= e1; yacc[j][3] *= e1;
        }
    }

    for (int st = 0; st <= lt; st++) {
        const int Srow0 = c * CHh + st * 64;
        __syncthreads();
        for (int e = tid; e < 2048; e += 128) {
            int row = e >> 5, seg = e & 31;
            *(uint2*)(ysm2 + OFF_UH + row * 272 + seg * 8) =
                *(const uint2*)&g_bch[(size_t)(Srow0 + row) * 256 + seg * 4];
            *(uint2*)(ysm2 + OFF_UL + row * 272 + seg * 8) =
                *(const uint2*)&g_bcl[(size_t)(Srow0 + row) * 256 + seg * 4];
        }
        for (int e = tid; e < 1024; e += 128) {
            int row = e >> 4, seg = e & 15;
            *(uint2*)(ysm2 + OFF_XH + row * 144 + seg * 8) =
                *(const uint2*)&g_xdth[(size_t)(Srow0 + row) * INTER + h * 64 + seg * 4];
            *(uint2*)(ysm2 + OFF_XL + row * 144 + seg * 8) =
                *(const uint2*)&g_xdtl[(size_t)(Srow0 + row) * INTER + h * 64 + seg * 4];
        }
        if (tid < 64) acss[tid] = g_acs[base + st * 64 + tid];
        __syncthreads();

        // phase A: G = C . B^T
        float gacc[8][4];
#pragma unroll
        for (int j = 0; j < 8; j++)
#pragma unroll
            for (int v = 0; v < 4; v++) gacc[j][v] = 0.f;
#pragma unroll
        for (int kk = 0; kk < 8; kk++) {
            uint32_t ah[4], al[4];
            ldsm_x4(ah[0], ah[1], ah[2], ah[3], a_base + kk * 32);
            ldsm_x4(al[0], al[1], al[2], al[3], a_base + OFF_CL + kk * 32);
#pragma unroll
            for (int np = 0; np < 4; np++) {
                uint32_t bh[4], bl[4];
                ldsm_x4(bh[0], bh[1], bh[2], bh[3], b_base + np * 4352 + kk * 32);
                ldsm_x4(bl[0], bl[1], bl[2], bl[3], b_base + 17408 + np * 4352 + kk * 32);
                mma16816(gacc[2 * np],     ah, bh[0], bh[1]);
                mma16816(gacc[2 * np + 1], ah, bh[2], bh[3]);
                mma16816(gacc[2 * np],     ah, bl[0], bl[1]);
                mma16816(gacc[2 * np + 1], ah, bl[2], bl[3]);
                mma16816(gacc[2 * np],     al, bh[0], bh[1]);
                mma16816(gacc[2 * np + 1], al, bh[2], bh[3]);
            }
        }

        // decay + causal mask on fragments
        {
            float rA = acsl[16 * w + (lane >> 2)];
            float rB = acsl[16 * w + (lane >> 2) + 8];
            bool diag = (st == lt);
            int l0 = 16 * w + (lane >> 2);
#pragma unroll
            for (int j = 0; j < 8; j++) {
                int s0 = 8 * j + 2 * (lane & 3);
                float c0 = acss[s0], c1 = acss[s0 + 1];
                float e00 = expf(rA - c0), e01 = expf(rA - c1);
                float e10 = expf(rB - c0), e11 = expf(rB - c1);
                if (diag) {
                    if (s0 > l0)         e00 = 0.f;
                    if (s0 + 1 > l0)     e01 = 0.f;
                    if (s0 > l0 + 8)     e10 = 0.f;
                    if (s0 + 1 > l0 + 8) e11 = 0.f;
                }
                gacc[j][0] *= e00; gacc[j][1] *= e01;
                gacc[j][2] *= e10; gacc[j][3] *= e11;
            }
        }

        // phase B: yacc += G . X  (G split hi/lo in registers)
#pragma unroll
        for (int t = 0; t < 4; t++) {
            uint32_t gah[4], gal[4];
            {
                __nv_bfloat16 h0, h1, h2, h3, l0b, l1b, l2b, l3b;
                split2(gacc[2 * t][0], h0, l0b); split2(gacc[2 * t][1], h1, l1b);
                split2(gacc[2 * t][2], h2, l2b); split2(gacc[2 * t][3], h3, l3b);
                gah[0] = pk(h0, h1); gah[1] = pk(h2, h3);
                gal[0] = pk(l0b, l1b); gal[1] = pk(l2b, l3b);
                split2(gacc[2 * t + 1][0], h0, l0b); split2(gacc[2 * t + 1][1], h1, l1b);
                split2(gacc[2 * t + 1][2], h2, l2b); split2(gacc[2 * t + 1][3], h3, l3b);
                gah[2] = pk(h0, h1); gah[3] = pk(h2, h3);
                gal[2] = pk(l0b, l1b); gal[3] = pk(l2b, l3b);
            }
#pragma unroll
            for (int np = 0; np < 4; np++) {
                uint32_t xh[4], xl[4];
                ldsm_x4_t(xh[0], xh[1], xh[2], xh[3], x_base + t * 2304 + np * 32);
                ldsm_x4_t(xl[0], xl[1], xl[2], xl[3], x_base + 9216 + t * 2304 + np * 32);
                mma16816(yacc[2 * np],     gah, xh[0], xh[1]);
                mma16816(yacc[2 * np + 1], gah, xh[2], xh[3]);
                mma16816(yacc[2 * np],     gah, xl[0], xl[1]);
                mma16816(yacc[2 * np + 1], gah, xl[2], xl[3]);
                mma16816(yacc[2 * np],     gal, xh[0], xh[1]);
                mma16816(yacc[2 * np + 1], gal, xh[2], xh[3]);
            }
        }
    }

    // epilogue: + x*D, write g_y
    float dh = Dv[h];
    int r0 = Lrow0 + 16 * w + (lane >> 2);
#pragma unroll
    for (int j = 0; j < 8; j++) {
        int p = h * 64 + 8 * j + 2 * (lane & 3);
        float2 x0 = *(const float2*)&g_xbc[(size_t)r0 * CONV_DIM + p];
        float2 x1 = *(const float2*)&g_xbc[(size_t)(r0 + 8) * CONV_DIM + p];
        *(float2*)&g_y[(size_t)r0 * INTER + p] =
            make_float2(yacc[j][0] + x0.x * dh, yacc[j][1] + x0.y * dh);
        *(float2*)&g_y[(size_t)(r0 + 8) * INTER + p] =
            make_float2(yacc[j][2] + x1.x * dh, yacc[j][3] + x1.y * dh);
    }
}

// ---------------- gated RMSNorm (in-place on g_y) ----------------
__global__ void rmsnorm_kernel(const float* __restrict__ nw) {
    int l = blockIdx.x;
    int tid = threadIdx.x;
    float v[16];
    float ss = 0.f;
#pragma unroll
    for (int i = 0; i < 16; i++) {
        int col = tid + i * 256;
        float y = g_y[(size_t)l * INTER + col];
        float z = g_zx[(size_t)l * OUT_IN + col];
        float yf = y * (z / (1.f + expf(-z)));
        v[i] = yf;
        ss = fmaf(yf, yf, ss);
    }
    __shared__ float red[256];
    red[tid] = ss;
    __syncthreads();
    for (int o = 128; o > 0; o >>= 1) {
        if (tid < o) red[tid] += red[tid + o];
        __syncthreads();
    }
    float scale = rsqrtf(red[0] / (float)INTER + 1e-5f);
#pragma unroll
    for (int i = 0; i < 16; i++) {
        int col = tid + i * 256;
        g_y[(size_t)l * INTER + col] = v[i] * scale * nw[col];
    }
}

// ---------------- launch ----------------
extern "C" void kernel_launch(void* const* d_in, const int* in_sizes, int n_in,
                              void* d_out, int out_size) {
    const float* hs      = (const float*)d_in[0];
    const float* W_in    = (const float*)d_in[1];
    const float* conv_w  = (const float*)d_in[2];
    const float* conv_b  = (const float*)d_in[3];
    const float* dt_bias = (const float*)d_in[4];
    const float* A_log   = (const float*)d_in[5];
    const float* Dv      = (const float*)d_in[6];
    const float* norm_w  = (const float*)d_in[7];
    const float* W_out   = (const float*)d_in[8];
    float* out = (float*)d_out;

    void *p_zx, *p_y;
    void *pA1h, *pA1l, *pB1h, *pB1l, *pA2h, *pA2l, *pB2h, *pB2l;
    cudaGetSymbolAddress(&p_zx, g_zx);
    cudaGetSymbolAddress(&p_y, g_y);
    cudaGetSymbolAddress(&pA1h, gA1h); cudaGetSymbolAddress(&pA1l, gA1l);
    cudaGetSymbolAddress(&pB1h, gB1h); cudaGetSymbolAddress(&pB1l, gB1l);
    cudaGetSymbolAddress(&pA2h, gA2h); cudaGetSymbolAddress(&pA2l, gA2l);
    cudaGetSymbolAddress(&pB2h, gB2h); cudaGetSymbolAddress(&pB2l, gB2l);

    const int GSMEM = 2 * STAGE_B;   // 81920
    cudaFuncSetAttribute(gemm_hmma, cudaFuncAttributeMaxDynamicSharedMemorySize, GSMEM);
    cudaFuncSetAttribute(y_hmma, cudaFuncAttributeMaxDynamicSharedMemorySize, 88576);
    cudaFuncSetAttribute(states_hmma, cudaFuncAttributeMaxDynamicSharedMemorySize, 54272);

    // 0) splits for GEMM1
    split_kernel<<<(L_ * HIDD / 4 + 255) / 256, 256>>>(hs, (__nv_bfloat16*)pA1h, (__nv_bfloat16*)pA1l, L_ * HIDD / 4);
    transpose_split_kernel<<<dim3(OUT_IN_PAD / 32, HIDD / 32), dim3(32, 8)>>>(
        W_in, (__nv_bfloat16*)pB1h, (__nv_bfloat16*)pB1l, HIDD, OUT_IN);
    // 1) zxbcdt = hs @ W_in
    gemm_hmma<<<dim3(OUT_IN_PAD / 128, L_ / 128), 512, GSMEM>>>(
        (const __nv_bfloat16*)pA1h, (const __nv_bfloat16*)pA1l,
        (const __nv_bfloat16*)pB1h, (const __nv_bfloat16*)pB1l,
        (float*)p_zx, OUT_IN, HIDD);
    // 2) conv + silu
    conv_silu_kernel<<<dim3(CONV_DIM / 256, L_), 256>>>(conv_w, conv_b);
    // 3) dt + per-chunk cumsum
    dtcs_kernel<<<dim3(NC, Hh), 256>>>(dt_bias, A_log);
    // 4) prep splits for SSM
    prep_xdt_kernel<<<L_ * INTER / 4 / 256, 256>>>();
    prep_bc_kernel<<<L_ * 256 / 4 / 256, 256>>>();
    // 5) per-chunk states (HMMA)
    states_hmma<<<dim3(NC, Hh), 128, 54272>>>();
    // 6) inter-chunk scan (emits split stin)
    scan_kernel<<<(Hh * Pp * Nn) / 256, 256>>>();
    // 7) Y = Y_diag + Y_off + x*D (HMMA)
    y_hmma<<<dim3(4, NC, Hh), 128, 88576>>>(Dv);
    // 8) gated RMSNorm
    rmsnorm_kernel<<<L_, 256>>>(norm_w);
    // 9) splits + GEMM2
    split_kernel<<<(L_ * INTER / 4 + 255) / 256, 256>>>((const float*)p_y, (__nv_bfloat16*)pA2h, (__nv_bfloat16*)pA2l, L_ * INTER / 4);
    transpose_split_kernel<<<dim3(HIDD / 32, INTER / 32), dim3(32, 8)>>>(
        W_out, (__nv_bfloat16*)pB2h, (__nv_bfloat16*)pB2l, INTER, HIDD);
    gemm_hmma<<<dim3(HIDD / 128, L_ / 128), 512, GSMEM>>>(
        (const __nv_bfloat16*)pA2h, (const __nv_bfloat16*)pA2l,
        (const __nv_bfloat16*)pB2h, (const __nv_bfloat16*)pB2l,
        out, HIDD, INTER);
}

// round 5
// speedup vs baseline: 2.6446x; 1.0399x over previous
#include <cuda_runtime.h>
#include <cuda_bf16.h>
#include <math.h>
#include <cstdint>

// ---------------- problem constants ----------------
#define L_       4096
#define HIDD     2048
#define Hh       64
#define Pp       64
#define Nn       128
#define CHh      256
#define NC       16
#define INTER    4096
#define CONV_DIM 4352            // INTER + 2N
#define OUT_IN   8512            // 2*(INTER+N) + H
#define OUT_IN_PAD 8576          // 67 * 128
#define XBC_OFF  INTER
#define DTRAW_OFF (2*INTER + 2*Nn)

// ---------------- device scratch (static; no runtime alloc) ----------------
__device__ float g_zx[L_ * OUT_IN];
__device__ float g_x[L_ * INTER];              // silu(conv) x part (fp32, for D-term)
__device__ float g_dt[NC * Hh * CHh];
__device__ float g_acs[NC * Hh * CHh];
__device__ float g_states[NC * Hh * Pp * Nn];
__device__ float g_y[L_ * INTER];

// bf16 hi/lo staging for tensor-core GEMMs
__device__ __nv_bfloat16 gA1h[L_ * HIDD];
__device__ __nv_bfloat16 gA1l[L_ * HIDD];
__device__ __nv_bfloat16 gB1h[OUT_IN_PAD * HIDD];
__device__ __nv_bfloat16 gB1l[OUT_IN_PAD * HIDD];
__device__ __nv_bfloat16 gA2h[L_ * INTER];
__device__ __nv_bfloat16 gA2l[L_ * INTER];
__device__ __nv_bfloat16 gB2h[HIDD * INTER];
__device__ __nv_bfloat16 gB2l[HIDD * INTER];

// bf16 hi/lo for SSM tensor-core path
__device__ __nv_bfloat16 g_xdth[L_ * INTER];   // x * dt
__device__ __nv_bfloat16 g_xdtl[L_ * INTER];
__device__ __nv_bfloat16 g_bch[L_ * 256];      // [B(128) | C(128)]
__device__ __nv_bfloat16 g_bcl[L_ * 256];
__device__ __nv_bfloat16 g_stinh[NC * Hh * Pp * Nn];
__device__ __nv_bfloat16 g_stinl[NC * Hh * Pp * Nn];

// ================= low-level helpers =================
__device__ __forceinline__ uint32_t smem_u32(const void* p) {
    uint32_t a;
    asm("{ .reg .u64 t; cvta.to.shared.u64 t, %1; cvt.u32.u64 %0, t; }" : "=r"(a) : "l"(p));
    return a;
}
#define CP16(sm, gm) \
    asm volatile("cp.async.cg.shared.global [%0], [%1], 16;" :: "r"(sm), "l"(gm) : "memory")
#define CP_COMMIT() asm volatile("cp.async.commit_group;" ::: "memory")
#define CP_WAIT(n)  asm volatile("cp.async.wait_group %0;" :: "n"(n) : "memory")

__device__ __forceinline__ void ldsm_x4(uint32_t& r0, uint32_t& r1, uint32_t& r2, uint32_t& r3,
                                        uint32_t addr) {
    asm volatile("ldmatrix.sync.aligned.m8n8.x4.shared.b16 {%0,%1,%2,%3}, [%4];"
                 : "=r"(r0), "=r"(r1), "=r"(r2), "=r"(r3) : "r"(addr));
}
__device__ __forceinline__ void ldsm_x4_t(uint32_t& r0, uint32_t& r1, uint32_t& r2, uint32_t& r3,
                                          uint32_t addr) {
    asm volatile("ldmatrix.sync.aligned.m8n8.x4.trans.shared.b16 {%0,%1,%2,%3}, [%4];"
                 : "=r"(r0), "=r"(r1), "=r"(r2), "=r"(r3) : "r"(addr));
}
__device__ __forceinline__ void mma16816(float* d, const uint32_t* a, uint32_t b0, uint32_t b1) {
    asm volatile("mma.sync.aligned.m16n8k16.row.col.f32.bf16.bf16.f32 "
                 "{%0,%1,%2,%3}, {%4,%5,%6,%7}, {%8,%9}, {%0,%1,%2,%3};"
                 : "+f"(d[0]), "+f"(d[1]), "+f"(d[2]), "+f"(d[3])
                 : "r"(a[0]), "r"(a[1]), "r"(a[2]), "r"(a[3]), "r"(b0), "r"(b1));
}
__device__ __forceinline__ uint32_t pk(__nv_bfloat16 a, __nv_bfloat16 b) {
    __nv_bfloat162 t; t.x = a; t.y = b;
    return *reinterpret_cast<uint32_t*>(&t);
}
__device__ __forceinline__ void split2(float x, __nv_bfloat16& h, __nv_bfloat16& l) {
    h = __float2bfloat16(x);
    l = __float2bfloat16(x - __bfloat162float(h));
}

// ================= split / transpose conversion kernels =================
__global__ void split_kernel(const float* __restrict__ in, __nv_bfloat16* __restrict__ hi,
                             __nv_bfloat16* __restrict__ lo, int n4) {
    int i = blockIdx.x * 256 + threadIdx.x;
    if (i >= n4) return;
    float4 v = ((const float4*)in)[i];
    __nv_bfloat16 h0, h1, h2, h3, l0, l1, l2, l3;
    split2(v.x, h0, l0); split2(v.y, h1, l1); split2(v.z, h2, l2); split2(v.w, h3, l3);
    ((uint2*)hi)[i] = make_uint2(pk(h0, h1), pk(h2, h3));
    ((uint2*)lo)[i] = make_uint2(pk(l0, l1), pk(l2, l3));
}

__global__ void transpose_split_kernel(const float* __restrict__ W,
                                       __nv_bfloat16* __restrict__ outH,
                                       __nv_bfloat16* __restrict__ outL,
                                       int K, int N) {
    __shared__ float tile[32][33];
    int n0 = blockIdx.x * 32, k0 = blockIdx.y * 32;
    int tx = threadIdx.x, ty = threadIdx.y;
#pragma unroll
    for (int i = 0; i < 4; i++) {
        int k = k0 + ty + i * 8;
        int n = n0 + tx;
        tile[ty + i * 8][tx] = (n < N) ? W[(size_t)k * N + n] : 0.f;
    }
    __syncthreads();
#pragma unroll
    for (int i = 0; i < 4; i++) {
        int nrow = n0 + ty + i * 8;
        int kcol = k0 + tx;
        float x = tile[tx][ty + i * 8];
        __nv_bfloat16 h, l;
        split2(x, h, l);
        outH[(size_t)nrow * K + kcol] = h;
        outL[(size_t)nrow * K + kcol] = l;
    }
}

// ================= HMMA split-bf16 GEMM: 3-stage cp.async pipeline =================
#define KT    32
#define PITCH 40
#define ARR_B   (128 * PITCH * 2)
#define STAGE_B (4 * ARR_B)                 // 40960
#define NSTAGE  3

extern __shared__ __align__(128) char gsm_raw[];

__global__ void __launch_bounds__(512, 1)
gemm_hmma(const __nv_bfloat16* __restrict__ Ah, const __nv_bfloat16* __restrict__ Al,
          const __nv_bfloat16* __restrict__ Bh, const __nv_bfloat16* __restrict__ Bl,
          float* __restrict__ C, int Nreal, int K) {
    const int tid = threadIdx.x;
    const int lane = tid & 31, wid = tid >> 5;
    const int wm = wid >> 2, wn = wid & 3;
    const int row0 = blockIdx.y * 128, col0 = blockIdx.x * 128;
    const uint32_t sb = smem_u32(gsm_raw);

    const int lrow = tid >> 2, lseg = tid & 3;
    const __nv_bfloat16* pAh = Ah + (size_t)(row0 + lrow) * K + lseg * 8;
    const __nv_bfloat16* pAl = Al + (size_t)(row0 + lrow) * K + lseg * 8;
    const __nv_bfloat16* pBh = Bh + (size_t)(col0 + lrow) * K + lseg * 8;
    const __nv_bfloat16* pBl = Bl + (size_t)(col0 + lrow) * K + lseg * 8;
    const uint32_t dst_off = (lrow * PITCH + lseg * 8) * 2;

    float acc[2][4][4];
#pragma unroll
    for (int m = 0; m < 2; m++)
#pragma unroll
        for (int n = 0; n < 4; n++)
#pragma unroll
            for (int v = 0; v < 4; v++) acc[m][n][v] = 0.f;

    const int T = K / KT;
    // prologue: stages 0 and 1
#pragma unroll
    for (int t = 0; t < 2; t++) {
        uint32_t s = sb + t * STAGE_B + dst_off;
        int ko = t * KT;
        CP16(s + 0 * ARR_B, pAh + ko);
        CP16(s + 1 * ARR_B, pAl + ko);
        CP16(s + 2 * ARR_B, pBh + ko);
        CP16(s + 3 * ARR_B, pBl + ko);
        CP_COMMIT();
    }

    const uint32_t a_frag_base = ((wm * 32 + (lane & 15)) * PITCH + (lane >> 4) * 8) * 2;
    const uint32_t b_frag_base = ((wn * 32 + (lane & 7) + (lane >> 4) * 8) * PITCH
                                  + ((lane >> 3) & 1) * 8) * 2;

    int sidx = 0;                 // t % 3
    int sfill = 2;                // (t+2) % 3
    for (int t = 0; t < T; t++) {
        if (t + 1 < T) { CP_WAIT(1); } else { CP_WAIT(0); }
        __syncthreads();
        if (t + 2 < T) {
            uint32_t s = sb + sfill * STAGE_B + dst_off;
            int ko = (t + 2) * KT;
            CP16(s + 0 * ARR_B, pAh + ko);
            CP16(s + 1 * ARR_B, pAl + ko);
            CP16(s + 2 * ARR_B, pBh + ko);
            CP16(s + 3 * ARR_B, pBl + ko);
            CP_COMMIT();
        }

        const uint32_t st = sb + sidx * STAGE_B;
#pragma unroll
        for (int kk = 0; kk < 2; kk++) {
            const uint32_t kb = kk * 32;
            uint32_t ah[2][4], al[2][4], bh[2][4], bl[2][4];
#pragma unroll
            for (int mt = 0; mt < 2; mt++) {
                uint32_t ao = st + a_frag_base + mt * (16 * PITCH * 2) + kb;
                ldsm_x4(ah[mt][0], ah[mt][1], ah[mt][2], ah[mt][3], ao);
                ldsm_x4(al[mt][0], al[mt][1], al[mt][2], al[mt][3], ao + ARR_B);
            }
#pragma unroll
            for (int np = 0; np < 2; np++) {
                uint32_t bo = st + 2 * ARR_B + b_frag_base + np * (16 * PITCH * 2) + kb;
                ldsm_x4(bh[np][0], bh[np][1], bh[np][2], bh[np][3], bo);
                ldsm_x4(bl[np][0], bl[np][1], bl[np][2], bl[np][3], bo + ARR_B);
            }
#pragma unroll
            for (int mt = 0; mt < 2; mt++) {
#pragma unroll
                for (int nt = 0; nt < 4; nt++) {
                    int np = nt >> 1, hv = (nt & 1) * 2;
                    mma16816(acc[mt][nt], ah[mt], bh[np][hv], bh[np][hv + 1]);
                    mma16816(acc[mt][nt], ah[mt], bl[np][hv], bl[np][hv + 1]);
                    mma16816(acc[mt][nt], al[mt], bh[np][hv], bh[np][hv + 1]);
                }
            }
        }
        sidx = (sidx + 1 == NSTAGE) ? 0 : sidx + 1;
        sfill = (sfill + 1 == NSTAGE) ? 0 : sfill + 1;
    }

#pragma unroll
    for (int mt = 0; mt < 2; mt++) {
        int r = row0 + wm * 32 + mt * 16 + (lane >> 2);
#pragma unroll
        for (int nt = 0; nt < 4; nt++) {
            int c = col0 + wn * 32 + nt * 8 + (lane & 3) * 2;
            if (c < Nreal) {
                *(float2*)&C[(size_t)r * Nreal + c]       = make_float2(acc[mt][nt][0], acc[mt][nt][1]);
                *(float2*)&C[(size_t)(r + 8) * Nreal + c] = make_float2(acc[mt][nt][2], acc[mt][nt][3]);
            }
        }
    }
}

// ---------------- dt (softplus+clip) and per-chunk cumsum of dt*A ----------------
__global__ void dtcs_kernel(const float* __restrict__ dt_bias, const float* __restrict__ A_log) {
    int c = blockIdx.x, h = blockIdx.y;
    int t = threadIdx.x;
    int Lg = c * CHh + t;
    float raw = g_zx[(size_t)Lg * OUT_IN + DTRAW_OFF + h] + dt_bias[h];
    float sp = (raw > 20.f) ? raw : log1pf(expf(raw));
    float dt = fminf(fmaxf(sp, 0.f), 100.f);
    float A = -expf(A_log[h]);
    __shared__ float s[256];
    s[t] = dt * A;
    __syncthreads();
    for (int off = 1; off < 256; off <<= 1) {
        float v = (t >= off) ? s[t - off] : 0.f;
        __syncthreads();
        s[t] += v;
        __syncthreads();
    }
    int base = (c * Hh + h) * CHh;
    g_dt[base + t] = dt;
    g_acs[base + t] = s[t];
}

// ---------------- fused: causal conv + silu + xdt/BC bf16 split ----------------
__global__ void conv_fused_kernel(const float* __restrict__ cw, const float* __restrict__ cb) {
    int c = blockIdx.x * 256 + threadIdx.x;   // 0..4351
    int l = blockIdx.y;
    float acc = cb[c];
#pragma unroll
    for (int k = 0; k < 4; k++) {
        int ll = l + k - 3;
        if (ll >= 0) acc = fmaf(g_zx[(size_t)ll * OUT_IN + XBC_OFF + c], cw[k * CONV_DIM + c], acc);
    }
    float s = acc / (1.f + expf(-acc));
    if (c < INTER) {
        int h = c >> 6;
        float dtv = g_dt[((l >> 8) * Hh + h) * CHh + (l & 255)];
        g_x[(size_t)l * INTER + c] = s;
        __nv_bfloat16 hh, ll2;
        split2(s * dtv, hh, ll2);
        g_xdth[(size_t)l * INTER + c] = hh;
        g_xdtl[(size_t)l * INTER + c] = ll2;
    } else {
        int cc = c - INTER;
        __nv_bfloat16 hh, ll2;
        split2(s, hh, ll2);
        g_bch[(size_t)l * 256 + cc] = hh;
        g_bcl[(size_t)l * 256 + cc] = ll2;
    }
}

// ---------------- HMMA states ----------------
extern __shared__ __align__(128) char ssm2[];
__global__ void __launch_bounds__(128, 2)
states_hmma() {
    const uint32_t sb = smem_u32(ssm2);
    const int tid = threadIdx.x, lane = tid & 31, w = tid >> 5;
    const int c = blockIdx.x, h = blockIdx.y;
    const int base = (c * Hh + h) * CHh;
    const float aend = g_acs[base + 255];
    float* wb = (float*)(ssm2 + 53248);
    for (int t = tid; t < 256; t += 128) wb[t] = expf(aend - g_acs[base + t]);

    float sacc[16][4];
#pragma unroll
    for (int j = 0; j < 16; j++)
#pragma unroll
        for (int v = 0; v < 4; v++) sacc[j][v] = 0.f;

    const uint32_t axb = sb + ((lane & 7) + (lane >> 4) * 8) * 144 + 32 * w + ((lane >> 3) & 1) * 16;
    const uint32_t bxb = sb + 18432 + ((lane & 7) + ((lane >> 3) & 1) * 8) * 272 + (lane >> 4) * 16;

    for (int kt = 0; kt < 4; kt++) {
        __syncthreads();
        int l0 = kt * 64;
        for (int e = tid; e < 2048; e += 128) {
            int row = e >> 5, seg = e & 31;
            int lg = c * CHh + l0 + row;
            __nv_bfloat162 xh2 = *(const __nv_bfloat162*)&g_xdth[(size_t)lg * INTER + h * 64 + seg * 2];
            __nv_bfloat162 xl2 = *(const __nv_bfloat162*)&g_xdtl[(size_t)lg * INTER + h * 64 + seg * 2];
            float wv = wb[l0 + row];
            float v0 = (__bfloat162float(xh2.x) + __bfloat162float(xl2.x)) * wv;
            float v1 = (__bfloat162float(xh2.y) + __bfloat162float(xl2.y)) * wv;
            __nv_bfloat16 a0, a1, b0, b1;
            split2(v0, a0, b0); split2(v1, a1, b1);
            *(uint32_t*)(ssm2 + row * 144 + seg * 4) = pk(a0, a1);
            *(uint32_t*)(ssm2 + 9216 + row * 144 + seg * 4) = pk(b0, b1);
        }
        for (int e = tid; e < 2048; e += 128) {
            int row = e >> 5, seg = e & 31;
            int lg = c * CHh + l0 + row;
            *(uint2*)(ssm2 + 18432 + row * 272 + seg * 8) = *(const uint2*)&g_bch[(size_t)lg * 256 + seg * 4];
            *(uint2*)(ssm2 + 35840 + row * 272 + seg * 8) = *(const uint2*)&g_bcl[(size_t)lg * 256 + seg * 4];
        }
        __syncthreads();

#pragma unroll
        for (int t = 0; t < 4; t++) {
            uint32_t ah[4], al[4];
            ldsm_x4_t(ah[0], ah[1], ah[2], ah[3], axb + t * 2304);
            ldsm_x4_t(al[0], al[1], al[2], al[3], axb + 9216 + t * 2304);
#pragma unroll
            for (int np = 0; np < 8; np++) {
                uint32_t bh[4], bl[4];
                ldsm_x4_t(bh[0], bh[1], bh[2], bh[3], bxb + t * 4352 + np * 32);
                ldsm_x4_t(bl[0], bl[1], bl[2], bl[3], bxb + 17408 + t * 4352 + np * 32);
                mma16816(sacc[2 * np],     ah, bh[0], bh[1]);
                mma16816(sacc[2 * np + 1], ah, bh[2], bh[3]);
                mma16816(sacc[2 * np],     ah, bl[0], bl[1]);
                mma16816(sacc[2 * np + 1], ah, bl[2], bl[3]);
                mma16816(sacc[2 * np],     al, bh[0], bh[1]);
                mma16816(sacc[2 * np + 1], al, bh[2], bh[3]);
            }
        }
    }

    float* out = g_states + (size_t)(c * Hh + h) * 8192;
    int p0 = 16 * w + (lane >> 2);
#pragma unroll
    for (int j = 0; j < 16; j++) {
        int n = 8 * j + 2 * (lane & 3);
        *(float2*)&out[p0 * 128 + n]       = make_float2(sacc[j][0], sacc[j][1]);
        *(float2*)&out[(p0 + 8) * 128 + n] = make_float2(sacc[j][2], sacc[j][3]);
    }
}

// ---------------- inter-chunk state scan (emits split stin) ----------------
__global__ void scan_kernel() {
    int idx = blockIdx.x * 256 + threadIdx.x;
    int h = idx >> 13;
    int rem = idx & 8191;
    float st = 0.f;
    for (int c = 0; c < NC; c++) {
        size_t o = (size_t)(c * Hh + h) * 8192 + rem;
        __nv_bfloat16 hi, lo;
        split2(st, hi, lo);
        g_stinh[o] = hi;
        g_stinl[o] = lo;
        float cend = g_acs[(c * Hh + h) * CHh + 255];
        st = st * expf(cend) + g_states[o];
    }
}

// ---------------- HMMA fused Y kernel ----------------
#define OFF_CL  17408
#define OFF_UH  34816
#define OFF_UL  52224
#define OFF_XH  69632
#define OFF_XL  78848
#define OFF_AL  88064
#define OFF_AS  88320
extern __shared__ __align__(128) char ysm2[];
__global__ void __launch_bounds__(128, 2)
y_hmma(const float* __restrict__ Dv) {
    const uint32_t sb = smem_u32(ysm2);
    const int tid = threadIdx.x, lane = tid & 31, w = tid >> 5;
    const int lt = blockIdx.x, c = blockIdx.y, h = blockIdx.z;
    const int base = (c * Hh + h) * CHh;
    const int Lrow0 = c * CHh + lt * 64;
    float* acsl = (float*)(ysm2 + OFF_AL);
    float* acss = (float*)(ysm2 + OFF_AS);

    {
        const size_t sinb = (size_t)(c * Hh + h) * 8192;
        for (int e = tid; e < 2048; e += 128) {
            int row = e >> 5, seg = e & 31;
            *(uint2*)(ysm2 + row * 272 + seg * 8) =
                *(const uint2*)&g_bch[(size_t)(Lrow0 + row) * 256 + 128 + seg * 4];
            *(uint2*)(ysm2 + OFF_CL + row * 272 + seg * 8) =
                *(const uint2*)&g_bcl[(size_t)(Lrow0 + row) * 256 + 128 + seg * 4];
            *(uint2*)(ysm2 + OFF_UH + row * 272 + seg * 8) =
                *(const uint2*)&g_stinh[sinb + row * 128 + seg * 4];
            *(uint2*)(ysm2 + OFF_UL + row * 272 + seg * 8) =
                *(const uint2*)&g_stinl[sinb + row * 128 + seg * 4];
        }
        if (tid < 64) acsl[tid] = g_acs[base + lt * 64 + tid];
    }
    __syncthreads();

    const uint32_t a_base = sb + (16 * w + (lane & 15)) * 272 + (lane >> 4) * 16;
    const uint32_t b_base = sb + OFF_UH + ((lane & 7) + (lane >> 4) * 8) * 272 + ((lane >> 3) & 1) * 16;
    const uint32_t x_base = sb + OFF_XH + ((lane & 7) + ((lane >> 3) & 1) * 8) * 144 + (lane >> 4) * 16;

    float yacc[8][4];
#pragma unroll
    for (int j = 0; j < 8; j++)
#pragma unroll
        for (int v = 0; v < 4; v++) yacc[j][v] = 0.f;

    // Y_off = C . Sin^T
#pragma unroll
    for (int kk = 0; kk < 8; kk++) {
        uint32_t ah[4], al[4];
        ldsm_x4(ah[0], ah[1], ah[2], ah[3], a_base + kk * 32);
        ldsm_x4(al[0], al[1], al[2], al[3], a_base + OFF_CL + kk * 32);
#pragma unroll
        for (int np = 0; np < 4; np++) {
            uint32_t bh[4], bl[4];
            ldsm_x4(bh[0], bh[1], bh[2], bh[3], b_base + np * 4352 + kk * 32);
            ldsm_x4(bl[0], bl[1], bl[2], bl[3], b_base + 17408 + np * 4352 + kk * 32);
            mma16816(yacc[2 * np],     ah, bh[0], bh[1]);
            mma16816(yacc[2 * np + 1], ah, bh[2], bh[3]);
            mma16816(yacc[2 * np],     ah, bl[0], bl[1]);
            mma16816(yacc[2 * np + 1], ah, bl[2], bl[3]);
            mma16816(yacc[2 * np],     al, bh[0], bh[1]);
            mma16816(yacc[2 * np + 1], al, bh[2], bh[3]);
        }
    }
    {
        float e0 = expf(acsl[16 * w + (lane >> 2)]);
        float e1 = expf(acsl[16 * w + (lane >> 2) + 8]);
#pragma unroll
        for (int j = 0; j < 8; j++) {
            yacc[j][0] *= e0; yacc[j][1] *= e0;
            yacc[j][2] *= e1; yacc[j][3] *= e1;
        }
    }

    for (int st = 0; st <= lt; st++) {
        const int Srow0 = c * CHh + st * 64;
        __syncthreads();
        for (int e = tid; e < 2048; e += 128) {
            int row = e >> 5, seg = e & 31;
            *(uint2*)(ysm2 + OFF_UH + row * 272 + seg * 8) =
                *(const uint2*)&g_bch[(size_t)(Srow0 + row) * 256 + seg * 4];
            *(uint2*)(ysm2 + OFF_UL + row * 272 + seg * 8) =
                *(const uint2*)&g_bcl[(size_t)(Srow0 + row) * 256 + seg * 4];
        }
        for (int e = tid; e < 1024; e += 128) {
            int row = e >> 4, seg = e & 15;
            *(uint2*)(ysm2 + OFF_XH + row * 144 + seg * 8) =
                *(const uint2*)&g_xdth[(size_t)(Srow0 + row) * INTER + h * 64 + seg * 4];
            *(uint2*)(ysm2 + OFF_XL + row * 144 + seg * 8) =
                *(const uint2*)&g_xdtl[(size_t)(Srow0 + row) * INTER + h * 64 + seg * 4];
        }
        if (tid < 64) acss[tid] = g_acs[base + st * 64 + tid];
        __syncthreads();

        float gacc[8][4];
#pragma unroll
        for (int j = 0; j < 8; j++)
#pragma unroll
            for (int v = 0; v < 4; v++) gacc[j][v] = 0.f;
#pragma unroll
        for (int kk = 0; kk < 8; kk++) {
            uint32_t ah[4], al[4];
            ldsm_x4(ah[0], ah[1], ah[2], ah[3], a_base + kk * 32);
            ldsm_x4(al[0], al[1], al[2], al[3], a_base + OFF_CL + kk * 32);
#pragma unroll
            for (int np = 0; np < 4; np++) {
                uint32_t bh[4], bl[4];
                ldsm_x4(bh[0], bh[1], bh[2], bh[3], b_base + np * 4352 + kk * 32);
                ldsm_x4(bl[0], bl[1], bl[2], bl[3], b_base + 17408 + np * 4352 + kk * 32);
                mma16816(gacc[2 * np],     ah, bh[0], bh[1]);
                mma16816(gacc[2 * np + 1], ah, bh[2], bh[3]);
                mma16816(gacc[2 * np],     ah, bl[0], bl[1]);
                mma16816(gacc[2 * np + 1], ah, bl[2], bl[3]);
                mma16816(gacc[2 * np],     al, bh[0], bh[1]);
                mma16816(gacc[2 * np + 1], al, bh[2], bh[3]);
            }
        }

        {
            float rA = acsl[16 * w + (lane >> 2)];
            float rB = acsl[16 * w + (lane >> 2) + 8];
            bool diag = (st == lt);
            int l0 = 16 * w + (lane >> 2);
#pragma unroll
            for (int j = 0; j < 8; j++) {
                int s0 = 8 * j + 2 * (lane & 3);
                float c0 = acss[s0], c1 = acss[s0 + 1];
                float e00 = expf(rA - c0), e01 = expf(rA - c1);
                float e10 = expf(rB - c0), e11 = expf(rB - c1);
                if (diag) {
                    if (s0 > l0)         e00 = 0.f;
                    if (s0 + 1 > l0)     e01 = 0.f;
                    if (s0 > l0 + 8)     e10 = 0.f;
                    if (s0 + 1 > l0 + 8) e11 = 0.f;
                }
                gacc[j][0] *= e00; gacc[j][1] *= e01;
                gacc[j][2] *= e10; gacc[j][3] *= e11;
            }
        }

#pragma unroll
        for (int t = 0; t < 4; t++) {
            uint32_t gah[4], gal[4];
            {
                __nv_bfloat16 h0, h1, h2, h3, l0b, l1b, l2b, l3b;
                split2(gacc[2 * t][0], h0, l0b); split2(gacc[2 * t][1], h1, l1b);
                split2(gacc[2 * t][2], h2, l2b); split2(gacc[2 * t][3], h3, l3b);
                gah[0] = pk(h0, h1); gah[1] = pk(h2, h3);
                gal[0] = pk(l0b, l1b); gal[1] = pk(l2b, l3b);
                split2(gacc[2 * t + 1][0], h0, l0b); split2(gacc[2 * t + 1][1], h1, l1b);
                split2(gacc[2 * t + 1][2], h2, l2b); split2(gacc[2 * t + 1][3], h3, l3b);
                gah[2] = pk(h0, h1); gah[3] = pk(h2, h3);
                gal[2] = pk(l0b, l1b); gal[3] = pk(l2b, l3b);
            }
#pragma unroll
            for (int np = 0; np < 4; np++) {
                uint32_t xh[4], xl[4];
                ldsm_x4_t(xh[0], xh[1], xh[2], xh[3], x_base + t * 2304 + np * 32);
                ldsm_x4_t(xl[0], xl[1], xl[2], xl[3], x_base + 9216 + t * 2304 + np * 32);
                mma16816(yacc[2 * np],     gah, xh[0], xh[1]);
                mma16816(yacc[2 * np + 1], gah, xh[2], xh[3]);
                mma16816(yacc[2 * np],     gah, xl[0], xl[1]);
                mma16816(yacc[2 * np + 1], gah, xl[2], xl[3]);
                mma16816(yacc[2 * np],     gal, xh[0], xh[1]);
                mma16816(yacc[2 * np + 1], gal, xh[2], xh[3]);
            }
        }
    }

    // epilogue: + x*D, write g_y
    float dh = Dv[h];
    int r0 = Lrow0 + 16 * w + (lane >> 2);
#pragma unroll
    for (int j = 0; j < 8; j++) {
        int p = h * 64 + 8 * j + 2 * (lane & 3);
        float2 x0 = *(const float2*)&g_x[(size_t)r0 * INTER + p];
        float2 x1 = *(const float2*)&g_x[(size_t)(r0 + 8) * INTER + p];
        *(float2*)&g_y[(size_t)r0 * INTER + p] =
            make_float2(yacc[j][0] + x0.x * dh, yacc[j][1] + x0.y * dh);
        *(float2*)&g_y[(size_t)(r0 + 8) * INTER + p] =
            make_float2(yacc[j][2] + x1.x * dh, yacc[j][3] + x1.y * dh);
    }
}

// ---------------- gated RMSNorm fused with bf16 hi/lo split ----------------
__global__ void rmsnorm_split_kernel(const float* __restrict__ nw) {
    int l = blockIdx.x;
    int tid = threadIdx.x;
    float v[16];
    float ss = 0.f;
#pragma unroll
    for (int i = 0; i < 16; i++) {
        int col = tid + i * 256;
        float y = g_y[(size_t)l * INTER + col];
        float z = g_zx[(size_t)l * OUT_IN + col];
        float yf = y * (z / (1.f + expf(-z)));
        v[i] = yf;
        ss = fmaf(yf, yf, ss);
    }
    __shared__ float red[256];
    red[tid] = ss;
    __syncthreads();
    for (int o = 128; o > 0; o >>= 1) {
        if (tid < o) red[tid] += red[tid + o];
        __syncthreads();
    }
    float scale = rsqrtf(red[0] / (float)INTER + 1e-5f);
#pragma unroll
    for (int i = 0; i < 16; i++) {
        int col = tid + i * 256;
        float yn = v[i] * scale * nw[col];
        __nv_bfloat16 h, lo;
        split2(yn, h, lo);
        gA2h[(size_t)l * INTER + col] = h;
        gA2l[(size_t)l * INTER + col] = lo;
    }
}

// ---------------- launch ----------------
extern "C" void kernel_launch(void* const* d_in, const int* in_sizes, int n_in,
                              void* d_out, int out_size) {
    const float* hs      = (const float*)d_in[0];
    const float* W_in    = (const float*)d_in[1];
    const float* conv_w  = (const float*)d_in[2];
    const float* conv_b  = (const float*)d_in[3];
    const float* dt_bias = (const float*)d_in[4];
    const float* A_log   = (const float*)d_in[5];
    const float* Dv      = (const float*)d_in[6];
    const float* norm_w  = (const float*)d_in[7];
    const float* W_out   = (const float*)d_in[8];
    float* out = (float*)d_out;

    void *p_zx;
    void *pA1h, *pA1l, *pB1h, *pB1l, *pA2h, *pA2l, *pB2h, *pB2l;
    cudaGetSymbolAddress(&p_zx, g_zx);
    cudaGetSymbolAddress(&pA1h, gA1h); cudaGetSymbolAddress(&pA1l, gA1l);
    cudaGetSymbolAddress(&pB1h, gB1h); cudaGetSymbolAddress(&pB1l, gB1l);
    cudaGetSymbolAddress(&pA2h, gA2h); cudaGetSymbolAddress(&pA2l, gA2l);
    cudaGetSymbolAddress(&pB2h, gB2h); cudaGetSymbolAddress(&pB2l, gB2l);

    const int GSMEM = NSTAGE * STAGE_B;   // 122880
    cudaFuncSetAttribute(gemm_hmma, cudaFuncAttributeMaxDynamicSharedMemorySize, GSMEM);
    cudaFuncSetAttribute(y_hmma, cudaFuncAttributeMaxDynamicSharedMemorySize, 88576);
    cudaFuncSetAttribute(states_hmma, cudaFuncAttributeMaxDynamicSharedMemorySize, 54272);

    // 1) split hs -> A1
    split_kernel<<<(L_ * HIDD / 4 + 255) / 256, 256>>>(hs, (__nv_bfloat16*)pA1h, (__nv_bfloat16*)pA1l, L_ * HIDD / 4);
    // 2) transpose+split W_in -> B1
    transpose_split_kernel<<<dim3(OUT_IN_PAD / 32, HIDD / 32), dim3(32, 8)>>>(
        W_in, (__nv_bfloat16*)pB1h, (__nv_bfloat16*)pB1l, HIDD, OUT_IN);
    // 3) transpose+split W_out -> B2 (input-only; hoisted so gemm1 is the 4th launch for ncu)
    transpose_split_kernel<<<dim3(HIDD / 32, INTER / 32), dim3(32, 8)>>>(
        W_out, (__nv_bfloat16*)pB2h, (__nv_bfloat16*)pB2l, INTER, HIDD);
    // 4) zxbcdt = hs @ W_in   <-- profiled launch
    gemm_hmma<<<dim3(OUT_IN_PAD / 128, L_ / 128), 512, GSMEM>>>(
        (const __nv_bfloat16*)pA1h, (const __nv_bfloat16*)pA1l,
        (const __nv_bfloat16*)pB1h, (const __nv_bfloat16*)pB1l,
        (float*)p_zx, OUT_IN, HIDD);
    // 5) dt + per-chunk cumsum (only needs g_zx)
    dtcs_kernel<<<dim3(NC, Hh), 256>>>(dt_bias, A_log);
    // 6) fused conv + silu + xdt/BC splits
    conv_fused_kernel<<<dim3(CONV_DIM / 256, L_), 256>>>(conv_w, conv_b);
    // 7) per-chunk states (HMMA)
    states_hmma<<<dim3(NC, Hh), 128, 54272>>>();
    // 8) inter-chunk scan
    scan_kernel<<<(Hh * Pp * Nn) / 256, 256>>>();
    // 9) Y (HMMA)
    y_hmma<<<dim3(4, NC, Hh), 128, 88576>>>(Dv);
    // 10) gated RMSNorm + split A2
    rmsnorm_split_kernel<<<L_, 256>>>(norm_w);
    // 11) out = yn @ W_out
    gemm_hmma<<<dim3(HIDD / 128, L_ / 128), 512, GSMEM>>>(
        (const __nv_bfloat16*)pA2h, (const __nv_bfloat16*)pA2l,
        (const __nv_bfloat16*)pB2h, (const __nv_bfloat16*)pB2l,
        out, HIDD, INTER);
}

// round 6
// speedup vs baseline: 2.6984x; 1.0203x over previous
#include <cuda_runtime.h>
#include <cuda_bf16.h>
#include <math.h>
#include <cstdint>

// ---------------- problem constants ----------------
#define L_       4096
#define HIDD     2048
#define Hh       64
#define Pp       64
#define Nn       128
#define CHh      256
#define NC       16
#define INTER    4096
#define CONV_DIM 4352            // INTER + 2N
#define OUT_IN   8512            // 2*(INTER+N) + H
#define OUT_IN_PAD 8576          // 67 * 128
#define XBC_OFF  INTER
#define DTRAW_OFF (2*INTER + 2*Nn)

// ---------------- device scratch (static; no runtime alloc) ----------------
__device__ float g_zx[L_ * OUT_IN];
__device__ float g_x[L_ * INTER];              // silu(conv) x part (fp32, for D-term)
__device__ float g_dt[NC * Hh * CHh];
__device__ float g_acs[NC * Hh * CHh];
__device__ float g_states[NC * Hh * Pp * Nn];
__device__ float g_y[L_ * INTER];

// bf16 hi/lo staging for tensor-core GEMMs
__device__ __nv_bfloat16 gA1h[L_ * HIDD];
__device__ __nv_bfloat16 gA1l[L_ * HIDD];
__device__ __nv_bfloat16 gB1h[OUT_IN_PAD * HIDD];
__device__ __nv_bfloat16 gB1l[OUT_IN_PAD * HIDD];
__device__ __nv_bfloat16 gA2h[L_ * INTER];
__device__ __nv_bfloat16 gA2l[L_ * INTER];
__device__ __nv_bfloat16 gB2h[HIDD * INTER];
__device__ __nv_bfloat16 gB2l[HIDD * INTER];

// bf16 hi/lo for SSM tensor-core path
__device__ __nv_bfloat16 g_xdth[L_ * INTER];   // x * dt
__device__ __nv_bfloat16 g_xdtl[L_ * INTER];
__device__ __nv_bfloat16 g_bch[L_ * 256];      // [B(128) | C(128)]
__device__ __nv_bfloat16 g_bcl[L_ * 256];
__device__ __nv_bfloat16 g_stinh[NC * Hh * Pp * Nn];
__device__ __nv_bfloat16 g_stinl[NC * Hh * Pp * Nn];

// ================= low-level helpers =================
__device__ __forceinline__ uint32_t smem_u32(const void* p) {
    uint32_t a;
    asm("{ .reg .u64 t; cvta.to.shared.u64 t, %1; cvt.u32.u64 %0, t; }" : "=r"(a) : "l"(p));
    return a;
}
#define CP16(sm, gm) \
    asm volatile("cp.async.cg.shared.global [%0], [%1], 16;" :: "r"(sm), "l"(gm) : "memory")
#define CP_COMMIT() asm volatile("cp.async.commit_group;" ::: "memory")
#define CP_WAIT(n)  asm volatile("cp.async.wait_group %0;" :: "n"(n) : "memory")

__device__ __forceinline__ void ldsm_x4(uint32_t& r0, uint32_t& r1, uint32_t& r2, uint32_t& r3,
                                        uint32_t addr) {
    asm volatile("ldmatrix.sync.aligned.m8n8.x4.shared.b16 {%0,%1,%2,%3}, [%4];"
                 : "=r"(r0), "=r"(r1), "=r"(r2), "=r"(r3) : "r"(addr));
}
__device__ __forceinline__ void ldsm_x4_t(uint32_t& r0, uint32_t& r1, uint32_t& r2, uint32_t& r3,
                                          uint32_t addr) {
    asm volatile("ldmatrix.sync.aligned.m8n8.x4.trans.shared.b16 {%0,%1,%2,%3}, [%4];"
                 : "=r"(r0), "=r"(r1), "=r"(r2), "=r"(r3) : "r"(addr));
}
__device__ __forceinline__ void mma16816(float* d, const uint32_t* a, uint32_t b0, uint32_t b1) {
    asm volatile("mma.sync.aligned.m16n8k16.row.col.f32.bf16.bf16.f32 "
                 "{%0,%1,%2,%3}, {%4,%5,%6,%7}, {%8,%9}, {%0,%1,%2,%3};"
                 : "+f"(d[0]), "+f"(d[1]), "+f"(d[2]), "+f"(d[3])
                 : "r"(a[0]), "r"(a[1]), "r"(a[2]), "r"(a[3]), "r"(b0), "r"(b1));
}
__device__ __forceinline__ uint32_t pk(__nv_bfloat16 a, __nv_bfloat16 b) {
    __nv_bfloat162 t; t.x = a; t.y = b;
    return *reinterpret_cast<uint32_t*>(&t);
}
__device__ __forceinline__ void split2(float x, __nv_bfloat16& h, __nv_bfloat16& l) {
    h = __float2bfloat16(x);
    l = __float2bfloat16(x - __bfloat162float(h));
}

// ================= split / transpose conversion kernels =================
__global__ void split_kernel(const float* __restrict__ in, __nv_bfloat16* __restrict__ hi,
                             __nv_bfloat16* __restrict__ lo, int n4) {
    int i = blockIdx.x * 256 + threadIdx.x;
    if (i >= n4) return;
    float4 v = ((const float4*)in)[i];
    __nv_bfloat16 h0, h1, h2, h3, l0, l1, l2, l3;
    split2(v.x, h0, l0); split2(v.y, h1, l1); split2(v.z, h2, l2); split2(v.w, h3, l3);
    ((uint2*)hi)[i] = make_uint2(pk(h0, h1), pk(h2, h3));
    ((uint2*)lo)[i] = make_uint2(pk(l0, l1), pk(l2, l3));
}

__global__ void transpose_split_kernel(const float* __restrict__ W,
                                       __nv_bfloat16* __restrict__ outH,
                                       __nv_bfloat16* __restrict__ outL,
                                       int K, int N) {
    __shared__ float tile[32][33];
    int n0 = blockIdx.x * 32, k0 = blockIdx.y * 32;
    int tx = threadIdx.x, ty = threadIdx.y;
#pragma unroll
    for (int i = 0; i < 4; i++) {
        int k = k0 + ty + i * 8;
        int n = n0 + tx;
        tile[ty + i * 8][tx] = (n < N) ? W[(size_t)k * N + n] : 0.f;
    }
    __syncthreads();
#pragma unroll
    for (int i = 0; i < 4; i++) {
        int nrow = n0 + ty + i * 8;
        int kcol = k0 + tx;
        float x = tile[tx][ty + i * 8];
        __nv_bfloat16 h, l;
        split2(x, h, l);
        outH[(size_t)nrow * K + kcol] = h;
        outL[(size_t)nrow * K + kcol] = l;
    }
}

// ================= HMMA split-bf16 GEMM: 256 thr, 2 CTA/SM, warp tile 64x32 =================
#define KT    32
#define PITCH 40
#define ARR_B   (128 * PITCH * 2)          // 10240
#define STAGE_B (4 * ARR_B)                // 40960; 2 stages = 80 KB/CTA

extern __shared__ __align__(128) char gsm_raw[];

__global__ void __launch_bounds__(256, 2)
gemm_hmma(const __nv_bfloat16* __restrict__ Ah, const __nv_bfloat16* __restrict__ Al,
          const __nv_bfloat16* __restrict__ Bh, const __nv_bfloat16* __restrict__ Bl,
          float* __restrict__ C, int Nreal, int K) {
    const int tid = threadIdx.x;
    const int lane = tid & 31, wid = tid >> 5;
    const int wm = wid & 1, wn = wid >> 1;     // 2x4 warp grid; warp tile 64x32
    const int row0 = blockIdx.y * 128, col0 = blockIdx.x * 128;
    const uint32_t sb = smem_u32(gsm_raw);

    // cp.async mapping: 256 threads, 2 threads per row, 2x16B per thread per array
    const int lrow = tid >> 1;
    const int lelem = (tid & 1) * 16;          // element offset (bf16)
    const __nv_bfloat16* pAh = Ah + (size_t)(row0 + lrow) * K + lelem;
    const __nv_bfloat16* pAl = Al + (size_t)(row0 + lrow) * K + lelem;
    const __nv_bfloat16* pBh = Bh + (size_t)(col0 + lrow) * K + lelem;
    const __nv_bfloat16* pBl = Bl + (size_t)(col0 + lrow) * K + lelem;
    const uint32_t dst_off = (lrow * PITCH + lelem) * 2;

    float acc[4][4][4];
#pragma unroll
    for (int m = 0; m < 4; m++)
#pragma unroll
        for (int n = 0; n < 4; n++)
#pragma unroll
            for (int v = 0; v < 4; v++) acc[m][n][v] = 0.f;

    const int T = K / KT;

#define GFILL(sidx, ko) do { \
        uint32_t _s = sb + (sidx) * STAGE_B + dst_off; \
        CP16(_s + 0 * ARR_B,      pAh + (ko));      CP16(_s + 0 * ARR_B + 16, pAh + (ko) + 8); \
        CP16(_s + 1 * ARR_B,      pAl + (ko));      CP16(_s + 1 * ARR_B + 16, pAl + (ko) + 8); \
        CP16(_s + 2 * ARR_B,      pBh + (ko));      CP16(_s + 2 * ARR_B + 16, pBh + (ko) + 8); \
        CP16(_s + 3 * ARR_B,      pBl + (ko));      CP16(_s + 3 * ARR_B + 16, pBl + (ko) + 8); \
        CP_COMMIT(); \
    } while (0)

    GFILL(0, 0);

    const uint32_t a_frag_base = ((wm * 64 + (lane & 15)) * PITCH + (lane >> 4) * 8) * 2;
    const uint32_t b_frag_base = ((wn * 32 + (lane & 7) + (lane >> 4) * 8) * PITCH
                                  + ((lane >> 3) & 1) * 8) * 2;

    for (int t = 0; t < T; t++) {
        if (t + 1 < T) {
            GFILL((t + 1) & 1, (t + 1) * KT);
            CP_WAIT(1);
        } else {
            CP_WAIT(0);
        }
        __syncthreads();

        const uint32_t st = sb + (t & 1) * STAGE_B;
#pragma unroll
        for (int kk = 0; kk < 2; kk++) {
            const uint32_t kb = kk * 32;
            uint32_t bh[2][4], bl[2][4];
#pragma unroll
            for (int np = 0; np < 2; np++) {
                uint32_t bo = st + 2 * ARR_B + b_frag_base + np * (16 * PITCH * 2) + kb;
                ldsm_x4(bh[np][0], bh[np][1], bh[np][2], bh[np][3], bo);
                ldsm_x4(bl[np][0], bl[np][1], bl[np][2], bl[np][3], bo + ARR_B);
            }
#pragma unroll
            for (int mt = 0; mt < 4; mt++) {
                uint32_t ah[4], al[4];
                uint32_t ao = st + a_frag_base + mt * (16 * PITCH * 2) + kb;
                ldsm_x4(ah[0], ah[1], ah[2], ah[3], ao);
                ldsm_x4(al[0], al[1], al[2], al[3], ao + ARR_B);
#pragma unroll
                for (int nt = 0; nt < 4; nt++) {
                    int np = nt >> 1, hv = (nt & 1) * 2;
                    mma16816(acc[mt][nt], ah, bh[np][hv], bh[np][hv + 1]);
                    mma16816(acc[mt][nt], ah, bl[np][hv], bl[np][hv + 1]);
                    mma16816(acc[mt][nt], al, bh[np][hv], bh[np][hv + 1]);
                }
            }
        }
        __syncthreads();
    }

#pragma unroll
    for (int mt = 0; mt < 4; mt++) {
        int r = row0 + wm * 64 + mt * 16 + (lane >> 2);
#pragma unroll
        for (int nt = 0; nt < 4; nt++) {
            int c = col0 + wn * 32 + nt * 8 + (lane & 3) * 2;
            if (c < Nreal) {
                *(float2*)&C[(size_t)r * Nreal + c]       = make_float2(acc[mt][nt][0], acc[mt][nt][1]);
                *(float2*)&C[(size_t)(r + 8) * Nreal + c] = make_float2(acc[mt][nt][2], acc[mt][nt][3]);
            }
        }
    }
#undef GFILL
}

// ---------------- dt (softplus+clip) and per-chunk cumsum of dt*A ----------------
__global__ void dtcs_kernel(const float* __restrict__ dt_bias, const float* __restrict__ A_log) {
    int c = blockIdx.x, h = blockIdx.y;
    int t = threadIdx.x;
    int Lg = c * CHh + t;
    float raw = g_zx[(size_t)Lg * OUT_IN + DTRAW_OFF + h] + dt_bias[h];
    float sp = (raw > 20.f) ? raw : log1pf(expf(raw));
    float dt = fminf(fmaxf(sp, 0.f), 100.f);
    float A = -expf(A_log[h]);
    __shared__ float s[256];
    s[t] = dt * A;
    __syncthreads();
    for (int off = 1; off < 256; off <<= 1) {
        float v = (t >= off) ? s[t - off] : 0.f;
        __syncthreads();
        s[t] += v;
        __syncthreads();
    }
    int base = (c * Hh + h) * CHh;
    g_dt[base + t] = dt;
    g_acs[base + t] = s[t];
}

// ---------------- fused: causal conv + silu + xdt/BC bf16 split ----------------
__global__ void conv_fused_kernel(const float* __restrict__ cw, const float* __restrict__ cb) {
    int c = blockIdx.x * 256 + threadIdx.x;   // 0..4351
    int l = blockIdx.y;
    float acc = cb[c];
#pragma unroll
    for (int k = 0; k < 4; k++) {
        int ll = l + k - 3;
        if (ll >= 0) acc = fmaf(g_zx[(size_t)ll * OUT_IN + XBC_OFF + c], cw[k * CONV_DIM + c], acc);
    }
    float s = acc / (1.f + expf(-acc));
    if (c < INTER) {
        int h = c >> 6;
        float dtv = g_dt[((l >> 8) * Hh + h) * CHh + (l & 255)];
        g_x[(size_t)l * INTER + c] = s;
        __nv_bfloat16 hh, ll2;
        split2(s * dtv, hh, ll2);
        g_xdth[(size_t)l * INTER + c] = hh;
        g_xdtl[(size_t)l * INTER + c] = ll2;
    } else {
        int cc = c - INTER;
        __nv_bfloat16 hh, ll2;
        split2(s, hh, ll2);
        g_bch[(size_t)l * 256 + cc] = hh;
        g_bcl[(size_t)l * 256 + cc] = ll2;
    }
}

// ---------------- HMMA states ----------------
extern __shared__ __align__(128) char ssm2[];
__global__ void __launch_bounds__(128, 2)
states_hmma() {
    const uint32_t sb = smem_u32(ssm2);
    const int tid = threadIdx.x, lane = tid & 31, w = tid >> 5;
    const int c = blockIdx.x, h = blockIdx.y;
    const int base = (c * Hh + h) * CHh;
    const float aend = g_acs[base + 255];
    float* wb = (float*)(ssm2 + 53248);
    for (int t = tid; t < 256; t += 128) wb[t] = expf(aend - g_acs[base + t]);

    float sacc[16][4];
#pragma unroll
    for (int j = 0; j < 16; j++)
#pragma unroll
        for (int v = 0; v < 4; v++) sacc[j][v] = 0.f;

    const uint32_t axb = sb + ((lane & 7) + (lane >> 4) * 8) * 144 + 32 * w + ((lane >> 3) & 1) * 16;
    const uint32_t bxb = sb + 18432 + ((lane & 7) + ((lane >> 3) & 1) * 8) * 272 + (lane >> 4) * 16;

    for (int kt = 0; kt < 4; kt++) {
        __syncthreads();
        int l0 = kt * 64;
        for (int e = tid; e < 2048; e += 128) {
            int row = e >> 5, seg = e & 31;
            int lg = c * CHh + l0 + row;
            __nv_bfloat162 xh2 = *(const __nv_bfloat162*)&g_xdth[(size_t)lg * INTER + h * 64 + seg * 2];
            __nv_bfloat162 xl2 = *(const __nv_bfloat162*)&g_xdtl[(size_t)lg * INTER + h * 64 + seg * 2];
            float wv = wb[l0 + row];
            float v0 = (__bfloat162float(xh2.x) + __bfloat162float(xl2.x)) * wv;
            float v1 = (__bfloat162float(xh2.y) + __bfloat162float(xl2.y)) * wv;
            __nv_bfloat16 a0, a1, b0, b1;
            split2(v0, a0, b0); split2(v1, a1, b1);
            *(uint32_t*)(ssm2 + row * 144 + seg * 4) = pk(a0, a1);
            *(uint32_t*)(ssm2 + 9216 + row * 144 + seg * 4) = pk(b0, b1);
        }
        for (int e = tid; e < 2048; e += 128) {
            int row = e >> 5, seg = e & 31;
            int lg = c * CHh + l0 + row;
            *(uint2*)(ssm2 + 18432 + row * 272 + seg * 8) = *(const uint2*)&g_bch[(size_t)lg * 256 + seg * 4];
            *(uint2*)(ssm2 + 35840 + row * 272 + seg * 8) = *(const uint2*)&g_bcl[(size_t)lg * 256 + seg * 4];
        }
        __syncthreads();

#pragma unroll
        for (int t = 0; t < 4; t++) {
            uint32_t ah[4], al[4];
            ldsm_x4_t(ah[0], ah[1], ah[2], ah[3], axb + t * 2304);
            ldsm_x4_t(al[0], al[1], al[2], al[3], axb + 9216 + t * 2304);
#pragma unroll
            for (int np = 0; np < 8; np++) {
                uint32_t bh[4], bl[4];
                ldsm_x4_t(bh[0], bh[1], bh[2], bh[3], bxb + t * 4352 + np * 32);
                ldsm_x4_t(bl[0], bl[1], bl[2], bl[3], bxb + 17408 + t * 4352 + np * 32);
                mma16816(sacc[2 * np],     ah, bh[0], bh[1]);
                mma16816(sacc[2 * np + 1], ah, bh[2], bh[3]);
                mma16816(sacc[2 * np],     ah, bl[0], bl[1]);
                mma16816(sacc[2 * np + 1], ah, bl[2], bl[3]);
                mma16816(sacc[2 * np],     al, bh[0], bh[1]);
                mma16816(sacc[2 * np + 1], al, bh[2], bh[3]);
            }
        }
    }

    float* out = g_states + (size_t)(c * Hh + h) * 8192;
    int p0 = 16 * w + (lane >> 2);
#pragma unroll
    for (int j = 0; j < 16; j++) {
        int n = 8 * j + 2 * (lane & 3);
        *(float2*)&out[p0 * 128 + n]       = make_float2(sacc[j][0], sacc[j][1]);
        *(float2*)&out[(p0 + 8) * 128 + n] = make_float2(sacc[j][2], sacc[j][3]);
    }
}

// ---------------- inter-chunk state scan (emits split stin) ----------------
__global__ void scan_kernel() {
    int idx = blockIdx.x * 256 + threadIdx.x;
    int h = idx >> 13;
    int rem = idx & 8191;
    float st = 0.f;
    for (int c = 0; c < NC; c++) {
        size_t o = (size_t)(c * Hh + h) * 8192 + rem;
        __nv_bfloat16 hi, lo;
        split2(st, hi, lo);
        g_stinh[o] = hi;
        g_stinl[o] = lo;
        float cend = g_acs[(c * Hh + h) * CHh + 255];
        st = st * expf(cend) + g_states[o];
    }
}

// ---------------- HMMA fused Y kernel ----------------
#define OFF_CL  17408
#define OFF_UH  34816
#define OFF_UL  52224
#define OFF_XH  69632
#define OFF_XL  78848
#define OFF_AL  88064
#define OFF_AS  88320
extern __shared__ __align__(128) char ysm2[];
__global__ void __launch_bounds__(128, 2)
y_hmma(const float* __restrict__ Dv) {
    const uint32_t sb = smem_u32(ysm2);
    const int tid = threadIdx.x, lane = tid & 31, w = tid >> 5;
    const int lt = blockIdx.x, c = blockIdx.y, h = blockIdx.z;
    const int base = (c * Hh + h) * CHh;
    const int Lrow0 = c * CHh + lt * 64;
    float* acsl = (float*)(ysm2 + OFF_AL);
    float* acss = (float*)(ysm2 + OFF_AS);

    {
        const size_t sinb = (size_t)(c * Hh + h) * 8192;
        for (int e = tid; e < 2048; e += 128) {
            int row = e >> 5, seg = e & 31;
            *(uint2*)(ysm2 + row * 272 + seg * 8) =
                *(const uint2*)&g_bch[(size_t)(Lrow0 + row) * 256 + 128 + seg * 4];
            *(uint2*)(ysm2 + OFF_CL + row * 272 + seg * 8) =
                *(const uint2*)&g_bcl[(size_t)(Lrow0 + row) * 256 + 128 + seg * 4];
            *(uint2*)(ysm2 + OFF_UH + row * 272 + seg * 8) =
                *(const uint2*)&g_stinh[sinb + row * 128 + seg * 4];
            *(uint2*)(ysm2 + OFF_UL + row * 272 + seg * 8) =
                *(const uint2*)&g_stinl[sinb + row * 128 + seg * 4];
        }
        if (tid < 64) acsl[tid] = g_acs[base + lt * 64 + tid];
    }
    __syncthreads();

    const uint32_t a_base = sb + (16 * w + (lane & 15)) * 272 + (lane >> 4) * 16;
    const uint32_t b_base = sb + OFF_UH + ((lane & 7) + (lane >> 4) * 8) * 272 + ((lane >> 3) & 1) * 16;
    const uint32_t x_base = sb + OFF_XH + ((lane & 7) + ((lane >> 3) & 1) * 8) * 144 + (lane >> 4) * 16;

    float yacc[8][4];
#pragma unroll
    for (int j = 0; j < 8; j++)
#pragma unroll
        for (int v = 0; v < 4; v++) yacc[j][v] = 0.f;

    // Y_off = C . Sin^T
#pragma unroll
    for (int kk = 0; kk < 8; kk++) {
        uint32_t ah[4], al[4];
        ldsm_x4(ah[0], ah[1], ah[2], ah[3], a_base + kk * 32);
        ldsm_x4(al[0], al[1], al[2], al[3], a_base + OFF_CL + kk * 32);
#pragma unroll
        for (int np = 0; np < 4; np++) {
            uint32_t bh[4], bl[4];
            ldsm_x4(bh[0], bh[1], bh[2], bh[3], b_base + np * 4352 + kk * 32);
            ldsm_x4(bl[0], bl[1], bl[2], bl[3], b_base + 17408 + np * 4352 + kk * 32);
            mma16816(yacc[2 * np],     ah, bh[0], bh[1]);
            mma16816(yacc[2 * np + 1], ah, bh[2], bh[3]);
            mma16816(yacc[2 * np],     ah, bl[0], bl[1]);
            mma16816(yacc[2 * np + 1], ah, bl[2], bl[3]);
            mma16816(yacc[2 * np],     al, bh[0], bh[1]);
            mma16816(yacc[2 * np + 1], al, bh[2], bh[3]);
        }
    }
    {
        float e0 = expf(acsl[16 * w + (lane >> 2)]);
        float e1 = expf(acsl[16 * w + (lane >> 2) + 8]);
#pragma unroll
        for (int j = 0; j < 8; j++) {
            yacc[j][0] *= e0; yacc[j][1] *= e0;
            yacc[j][2] *= e1; yacc[j][3] *= e1;
        }
    }

    for (int st = 0; st <= lt; st++) {
        const int Srow0 = c * CHh + st * 64;
        __syncthreads();
        for (int e = tid; e < 2048; e += 128) {
            int row = e >> 5, seg = e & 31;
            *(uint2*)(ysm2 + OFF_UH + row * 272 + seg * 8) =
                *(const uint2*)&g_bch[(size_t)(Srow0 + row) * 256 + seg * 4];
            *(uint2*)(ysm2 + OFF_UL + row * 272 + seg * 8) =
                *(const uint2*)&g_bcl[(size_t)(Srow0 + row) * 256 + seg * 4];
        }
        for (int e = tid; e < 1024; e += 128) {
            int row = e >> 4, seg = e & 15;
            *(uint2*)(ysm2 + OFF_XH + row * 144 + seg * 8) =
                *(const uint2*)&g_xdth[(size_t)(Srow0 + row) * INTER + h * 64 + seg * 4];
            *(uint2*)(ysm2 + OFF_XL + row * 144 + seg * 8) =
                *(const uint2*)&g_xdtl[(size_t)(Srow0 + row) * INTER + h * 64 + seg * 4];
        }
        if (tid < 64) acss[tid] = g_acs[base + st * 64 + tid];
        __syncthreads();

        float gacc[8][4];
#pragma unroll
        for (int j = 0; j < 8; j++)
#pragma unroll
            for (int v = 0; v < 4; v++) gacc[j][v] = 0.f;
#pragma unroll
        for (int kk = 0; kk < 8; kk++) {
            uint32_t ah[4], al[4];
            ldsm_x4(ah[0], ah[1], ah[2], ah[3], a_base + kk * 32);
            ldsm_x4(al[0], al[1], al[2], al[3], a_base + OFF_CL + kk * 32);
#pragma unroll
            for (int np = 0; np < 4; np++) {
                uint32_t bh[4], bl[4];
                ldsm_x4(bh[0], bh[1], bh[2], bh[3], b_base + np * 4352 + kk * 32);
                ldsm_x4(bl[0], bl[1], bl[2], bl[3], b_base + 17408 + np * 4352 + kk * 32);
                mma16816(gacc[2 * np],     ah, bh[0], bh[1]);
                mma16816(gacc[2 * np + 1], ah, bh[2], bh[3]);
                mma16816(gacc[2 * np],     ah, bl[0], bl[1]);
                mma16816(gacc[2 * np + 1], ah, bl[2], bl[3]);
                mma16816(gacc[2 * np],     al, bh[0], bh[1]);
                mma16816(gacc[2 * np + 1], al, bh[2], bh[3]);
            }
        }

        {
            float rA = acsl[16 * w + (lane >> 2)];
            float rB = acsl[16 * w + (lane >> 2) + 8];
            bool diag = (st == lt);
            int l0 = 16 * w + (lane >> 2);
#pragma unroll
            for (int j = 0; j < 8; j++) {
                int s0 = 8 * j + 2 * (lane & 3);
                float c0 = acss[s0], c1 = acss[s0 + 1];
                float e00 = expf(rA - c0), e01 = expf(rA - c1);
                float e10 = expf(rB - c0), e11 = expf(rB - c1);
                if (diag) {
                    if (s0 > l0)         e00 = 0.f;
                    if (s0 + 1 > l0)     e01 = 0.f;
                    if (s0 > l0 + 8)     e10 = 0.f;
                    if (s0 + 1 > l0 + 8) e11 = 0.f;
                }
                gacc[j][0] *= e00; gacc[j][1] *= e01;
                gacc[j][2] *= e10; gacc[j][3] *= e11;
            }
        }

#pragma unroll
        for (int t = 0; t < 4; t++) {
            uint32_t gah[4], gal[4];
            {
                __nv_bfloat16 h0, h1, h2, h3, l0b, l1b, l2b, l3b;
                split2(gacc[2 * t][0], h0, l0b); split2(gacc[2 * t][1], h1, l1b);
                split2(gacc[2 * t][2], h2, l2b); split2(gacc[2 * t][3], h3, l3b);
                gah[0] = pk(h0, h1); gah[1] = pk(h2, h3);
                gal[0] = pk(l0b, l1b); gal[1] = pk(l2b, l3b);
                split2(gacc[2 * t + 1][0], h0, l0b); split2(gacc[2 * t + 1][1], h1, l1b);
                split2(gacc[2 * t + 1][2], h2, l2b); split2(gacc[2 * t + 1][3], h3, l3b);
                gah[2] = pk(h0, h1); gah[3] = pk(h2, h3);
                gal[2] = pk(l0b, l1b); gal[3] = pk(l2b, l3b);
            }
#pragma unroll
            for (int np = 0; np < 4; np++) {
                uint32_t xh[4], xl[4];
                ldsm_x4_t(xh[0], xh[1], xh[2], xh[3], x_base + t * 2304 + np * 32);
                ldsm_x4_t(xl[0], xl[1], xl[2], xl[3], x_base + 9216 + t * 2304 + np * 32);
                mma16816(yacc[2 * np],     gah, xh[0], xh[1]);
                mma16816(yacc[2 * np + 1], gah, xh[2], xh[3]);
                mma16816(yacc[2 * np],     gah, xl[0], xl[1]);
                mma16816(yacc[2 * np + 1], gah, xl[2], xl[3]);
                mma16816(yacc[2 * np],     gal, xh[0], xh[1]);
                mma16816(yacc[2 * np + 1], gal, xh[2], xh[3]);
            }
        }
    }

    // epilogue: + x*D, write g_y
    float dh = Dv[h];
    int r0 = Lrow0 + 16 * w + (lane >> 2);
#pragma unroll
    for (int j = 0; j < 8; j++) {
        int p = h * 64 + 8 * j + 2 * (lane & 3);
        float2 x0 = *(const float2*)&g_x[(size_t)r0 * INTER + p];
        float2 x1 = *(const float2*)&g_x[(size_t)(r0 + 8) * INTER + p];
        *(float2*)&g_y[(size_t)r0 * INTER + p] =
            make_float2(yacc[j][0] + x0.x * dh, yacc[j][1] + x0.y * dh);
        *(float2*)&g_y[(size_t)(r0 + 8) * INTER + p] =
            make_float2(yacc[j][2] + x1.x * dh, yacc[j][3] + x1.y * dh);
    }
}

// ---------------- gated RMSNorm fused with bf16 hi/lo split ----------------
__global__ void rmsnorm_split_kernel(const float* __restrict__ nw) {
    int l = blockIdx.x;
    int tid = threadIdx.x;
    float v[16];
    float ss = 0.f;
#pragma unroll
    for (int i = 0; i < 16; i++) {
        int col = tid + i * 256;
        float y = g_y[(size_t)l * INTER + col];
        float z = g_zx[(size_t)l * OUT_IN + col];
        float yf = y * (z / (1.f + expf(-z)));
        v[i] = yf;
        ss = fmaf(yf, yf, ss);
    }
    __shared__ float red[256];
    red[tid] = ss;
    __syncthreads();
    for (int o = 128; o > 0; o >>= 1) {
        if (tid < o) red[tid] += red[tid + o];
        __syncthreads();
    }
    float scale = rsqrtf(red[0] / (float)INTER + 1e-5f);
#pragma unroll
    for (int i = 0; i < 16; i++) {
        int col = tid + i * 256;
        float yn = v[i] * scale * nw[col];
        __nv_bfloat16 h, lo;
        split2(yn, h, lo);
        gA2h[(size_t)l * INTER + col] = h;
        gA2l[(size_t)l * INTER + col] = lo;
    }
}

// ---------------- launch ----------------
extern "C" void kernel_launch(void* const* d_in, const int* in_sizes, int n_in,
                              void* d_out, int out_size) {
    const float* hs      = (const float*)d_in[0];
    const float* W_in    = (const float*)d_in[1];
    const float* conv_w  = (const float*)d_in[2];
    const float* conv_b  = (const float*)d_in[3];
    const float* dt_bias = (const float*)d_in[4];
    const float* A_log   = (const float*)d_in[5];
    const float* Dv      = (const float*)d_in[6];
    const float* norm_w  = (const float*)d_in[7];
    const float* W_out   = (const float*)d_in[8];
    float* out = (float*)d_out;

    void *p_zx;
    void *pA1h, *pA1l, *pB1h, *pB1l, *pA2h, *pA2l, *pB2h, *pB2l;
    cudaGetSymbolAddress(&p_zx, g_zx);
    cudaGetSymbolAddress(&pA1h, gA1h); cudaGetSymbolAddress(&pA1l, gA1l);
    cudaGetSymbolAddress(&pB1h, gB1h); cudaGetSymbolAddress(&pB1l, gB1l);
    cudaGetSymbolAddress(&pA2h, gA2h); cudaGetSymbolAddress(&pA2l, gA2l);
    cudaGetSymbolAddress(&pB2h, gB2h); cudaGetSymbolAddress(&pB2l, gB2l);

    const int GSMEM = 2 * STAGE_B;   // 81920 -> 2 CTAs/SM
    cudaFuncSetAttribute(gemm_hmma, cudaFuncAttributeMaxDynamicSharedMemorySize, GSMEM);
    cudaFuncSetAttribute(y_hmma, cudaFuncAttributeMaxDynamicSharedMemorySize, 88576);
    cudaFuncSetAttribute(states_hmma, cudaFuncAttributeMaxDynamicSharedMemorySize, 54272);

    // 1) split hs -> A1
    split_kernel<<<(L_ * HIDD / 4 + 255) / 256, 256>>>(hs, (__nv_bfloat16*)pA1h, (__nv_bfloat16*)pA1l, L_ * HIDD / 4);
    // 2) transpose+split W_in -> B1
    transpose_split_kernel<<<dim3(OUT_IN_PAD / 32, HIDD / 32), dim3(32, 8)>>>(
        W_in, (__nv_bfloat16*)pB1h, (__nv_bfloat16*)pB1l, HIDD, OUT_IN);
    // 3) transpose+split W_out -> B2
    transpose_split_kernel<<<dim3(HIDD / 32, INTER / 32), dim3(32, 8)>>>(
        W_out, (__nv_bfloat16*)pB2h, (__nv_bfloat16*)pB2l, INTER, HIDD);
    // 4) zxbcdt = hs @ W_in   <-- profiled launch
    gemm_hmma<<<dim3(OUT_IN_PAD / 128, L_ / 128), 256, GSMEM>>>(
        (const __nv_bfloat16*)pA1h, (const __nv_bfloat16*)pA1l,
        (const __nv_bfloat16*)pB1h, (const __nv_bfloat16*)pB1l,
        (float*)p_zx, OUT_IN, HIDD);
    // 5) dt + per-chunk cumsum
    dtcs_kernel<<<dim3(NC, Hh), 256>>>(dt_bias, A_log);
    // 6) fused conv + silu + xdt/BC splits
    conv_fused_kernel<<<dim3(CONV_DIM / 256, L_), 256>>>(conv_w, conv_b);
    // 7) per-chunk states (HMMA)
    states_hmma<<<dim3(NC, Hh), 128, 54272>>>();
    // 8) inter-chunk scan
    scan_kernel<<<(Hh * Pp * Nn) / 256, 256>>>();
    // 9) Y (HMMA)
    y_hmma<<<dim3(4, NC, Hh), 128, 88576>>>(Dv);
    // 10) gated RMSNorm + split A2
    rmsnorm_split_kernel<<<L_, 256>>>(norm_w);
    // 11) out = yn @ W_out
    gemm_hmma<<<dim3(HIDD / 128, L_ / 128), 256, GSMEM>>>(
        (const __nv_bfloat16*)pA2h, (const __nv_bfloat16*)pA2l,
        (const __nv_bfloat16*)pB2h, (const __nv_bfloat16*)pB2l,
        out, HIDD, INTER);
}

// round 8
// speedup vs baseline: 2.8596x; 1.0598x over previous
#include <cuda_runtime.h>
#include <cuda_bf16.h>
#include <math.h>
#include <cstdint>

// ---------------- problem constants ----------------
#define L_       4096
#define HIDD     2048
#define Hh       64
#define Pp       64
#define Nn       128
#define CHh      256
#define NC       16
#define INTER    4096
#define CONV_DIM 4352            // INTER + 2N
#define OUT_IN   8512            // 2*(INTER+N) + H
#define OUT_IN_PAD 8576          // 67 * 128
#define XBC_OFF  INTER
#define DTRAW_OFF (2*INTER + 2*Nn)

// ---------------- device scratch (static; no runtime alloc) ----------------
__device__ float g_zx[L_ * OUT_IN];
__device__ float g_x[L_ * INTER];
__device__ float g_dt[NC * Hh * CHh];
__device__ float g_acs[NC * Hh * CHh];
__device__ float g_states[NC * Hh * Pp * Nn];
__device__ float g_y[L_ * INTER];

__device__ __nv_bfloat16 gA1h[L_ * HIDD];
__device__ __nv_bfloat16 gA1l[L_ * HIDD];
__device__ __nv_bfloat16 gB1h[OUT_IN_PAD * HIDD];
__device__ __nv_bfloat16 gB1l[OUT_IN_PAD * HIDD];
__device__ __nv_bfloat16 gA2h[L_ * INTER];
__device__ __nv_bfloat16 gA2l[L_ * INTER];
__device__ __nv_bfloat16 gB2h[HIDD * INTER];
__device__ __nv_bfloat16 gB2l[HIDD * INTER];

__device__ __nv_bfloat16 g_xdth[L_ * INTER];
__device__ __nv_bfloat16 g_xdtl[L_ * INTER];
__device__ __nv_bfloat16 g_bch[L_ * 256];
__device__ __nv_bfloat16 g_bcl[L_ * 256];
__device__ __nv_bfloat16 g_stinh[NC * Hh * Pp * Nn];
__device__ __nv_bfloat16 g_stinl[NC * Hh * Pp * Nn];

// ================= low-level helpers =================
__device__ __forceinline__ uint32_t smem_u32(const void* p) {
    uint32_t a;
    asm("{ .reg .u64 t; cvta.to.shared.u64 t, %1; cvt.u32.u64 %0, t; }" : "=r"(a) : "l"(p));
    return a;
}
#define CP16(sm, gm) \
    asm volatile("cp.async.cg.shared.global [%0], [%1], 16;" :: "r"(sm), "l"(gm) : "memory")
#define CP_COMMIT() asm volatile("cp.async.commit_group;" ::: "memory")
#define CP_WAIT(n)  asm volatile("cp.async.wait_group %0;" :: "n"(n) : "memory")

__device__ __forceinline__ void ldsm_x4(uint32_t& r0, uint32_t& r1, uint32_t& r2, uint32_t& r3,
                                        uint32_t addr) {
    asm volatile("ldmatrix.sync.aligned.m8n8.x4.shared.b16 {%0,%1,%2,%3}, [%4];"
                 : "=r"(r0), "=r"(r1), "=r"(r2), "=r"(r3) : "r"(addr));
}
__device__ __forceinline__ void ldsm_x4_t(uint32_t& r0, uint32_t& r1, uint32_t& r2, uint32_t& r3,
                                          uint32_t addr) {
    asm volatile("ldmatrix.sync.aligned.m8n8.x4.trans.shared.b16 {%0,%1,%2,%3}, [%4];"
                 : "=r"(r0), "=r"(r1), "=r"(r2), "=r"(r3) : "r"(addr));
}
__device__ __forceinline__ void mma16816(float* d, const uint32_t* a, uint32_t b0, uint32_t b1) {
    asm volatile("mma.sync.aligned.m16n8k16.row.col.f32.bf16.bf16.f32 "
                 "{%0,%1,%2,%3}, {%4,%5,%6,%7}, {%8,%9}, {%0,%1,%2,%3};"
                 : "+f"(d[0]), "+f"(d[1]), "+f"(d[2]), "+f"(d[3])
                 : "r"(a[0]), "r"(a[1]), "r"(a[2]), "r"(a[3]), "r"(b0), "r"(b1));
}
__device__ __forceinline__ uint32_t pk(__nv_bfloat16 a, __nv_bfloat16 b) {
    __nv_bfloat162 t; t.x = a; t.y = b;
    return *reinterpret_cast<uint32_t*>(&t);
}
__device__ __forceinline__ void split2(float x, __nv_bfloat16& h, __nv_bfloat16& l) {
    h = __float2bfloat16(x);
    l = __float2bfloat16(x - __bfloat162float(h));
}

// ================= split / transpose conversion kernels =================
__global__ void split_kernel(const float* __restrict__ in, __nv_bfloat16* __restrict__ hi,
                             __nv_bfloat16* __restrict__ lo, int n4) {
    int i = blockIdx.x * 256 + threadIdx.x;
    if (i >= n4) return;
    float4 v = ((const float4*)in)[i];
    __nv_bfloat16 h0, h1, h2, h3, l0, l1, l2, l3;
    split2(v.x, h0, l0); split2(v.y, h1, l1); split2(v.z, h2, l2); split2(v.w, h3, l3);
    ((uint2*)hi)[i] = make_uint2(pk(h0, h1), pk(h2, h3));
    ((uint2*)lo)[i] = make_uint2(pk(l0, l1), pk(l2, l3));
}

__global__ void transpose_split_kernel(const float* __restrict__ W,
                                       __nv_bfloat16* __restrict__ outH,
                                       __nv_bfloat16* __restrict__ outL,
                                       int K, int N) {
    __shared__ float tile[32][33];
    int n0 = blockIdx.x * 32, k0 = blockIdx.y * 32;
    int tx = threadIdx.x, ty = threadIdx.y;
#pragma unroll
    for (int i = 0; i < 4; i++) {
        int k = k0 + ty + i * 8;
        int n = n0 + tx;
        tile[ty + i * 8][tx] = (n < N) ? W[(size_t)k * N + n] : 0.f;
    }
    __syncthreads();
#pragma unroll
    for (int i = 0; i < 4; i++) {
        int nrow = n0 + ty + i * 8;
        int kcol = k0 + tx;
        float x = tile[tx][ty + i * 8];
        __nv_bfloat16 h, l;
        split2(x, h, l);
        outH[(size_t)nrow * K + kcol] = h;
        outL[(size_t)nrow * K + kcol] = l;
    }
}

// ================= HMMA split-bf16 GEMM: KT=16, 4 stages, single-sync mainloop =================
// Row pitch 48 BYTES (24 bf16): 16B-aligned rows (fixes R7 misalignment);
// (addr/16) mod 8 over 8 rows = {0,3,6,1,4,7,2,5} -> conflict-free ldmatrix.
#define KT      16
#define PITCHB  48
#define ARR_B   (128 * PITCHB)            // 6144 bytes per array
#define STAGE_B (4 * ARR_B)               // 24576; 4 stages = 96 KB/CTA -> 2 CTA/SM
#define NSTG    4

extern __shared__ __align__(128) char gsm_raw[];

__global__ void __launch_bounds__(256, 2)
gemm_hmma(const __nv_bfloat16* __restrict__ Ah, const __nv_bfloat16* __restrict__ Al,
          const __nv_bfloat16* __restrict__ Bh, const __nv_bfloat16* __restrict__ Bl,
          float* __restrict__ C, int Nreal, int K) {
    const int tid = threadIdx.x;
    const int lane = tid & 31, wid = tid >> 5;
    const int wm = wid & 1, wn = wid >> 1;     // 2x4 warp grid; warp tile 64x32
    const int row0 = blockIdx.y * 128, col0 = blockIdx.x * 128;
    const uint32_t sb = smem_u32(gsm_raw);

    // cp.async mapping: 256 threads = 128 rows x 2 16B-segments, one per array
    const int lrow = tid >> 1;
    const int lelem = (tid & 1) * 8;           // element offset (bf16), 8 elems = 16B
    const __nv_bfloat16* pAh = Ah + (size_t)(row0 + lrow) * K + lelem;
    const __nv_bfloat16* pAl = Al + (size_t)(row0 + lrow) * K + lelem;
    const __nv_bfloat16* pBh = Bh + (size_t)(col0 + lrow) * K + lelem;
    const __nv_bfloat16* pBl = Bl + (size_t)(col0 + lrow) * K + lelem;
    const uint32_t dst_off = lrow * PITCHB + (tid & 1) * 16;   // 48*r + {0,16}: 16B aligned

    float acc[4][4][4];
#pragma unroll
    for (int m = 0; m < 4; m++)
#pragma unroll
        for (int n = 0; n < 4; n++)
#pragma unroll
            for (int v = 0; v < 4; v++) acc[m][n][v] = 0.f;

    const int T = K / KT;

#define GFILL_NC(sidx, ko) do { \
        uint32_t _s = sb + (sidx) * STAGE_B + dst_off; \
        CP16(_s + 0 * ARR_B, pAh + (ko)); \
        CP16(_s + 1 * ARR_B, pAl + (ko)); \
        CP16(_s + 2 * ARR_B, pBh + (ko)); \
        CP16(_s + 3 * ARR_B, pBl + (ko)); \
    } while (0)

    // prologue: fill stages 0..2, one commit group each
#pragma unroll
    for (int t = 0; t < 3; t++) {
        GFILL_NC(t, t * KT);
        CP_COMMIT();
    }

    const uint32_t a_frag_base = (wm * 64 + (lane & 15)) * PITCHB + (lane >> 4) * 16;
    const uint32_t b_frag_base = (wn * 32 + (lane & 7) + (lane >> 4) * 8) * PITCHB
                                 + ((lane >> 3) & 1) * 16;

    for (int t = 0; t < T; t++) {
        // one commit per iter => wait_group 2 makes stage t's group complete
        CP_WAIT(2);
        __syncthreads();
        if (t + 3 < T) GFILL_NC((t + 3) & 3, (t + 3) * KT);
        CP_COMMIT();

        const uint32_t st = sb + (t & 3) * STAGE_B;
        uint32_t bh[2][4], bl[2][4];
#pragma unroll
        for (int np = 0; np < 2; np++) {
            uint32_t bo = st + 2 * ARR_B + b_frag_base + np * (16 * PITCHB);
            ldsm_x4(bh[np][0], bh[np][1], bh[np][2], bh[np][3], bo);
            ldsm_x4(bl[np][0], bl[np][1], bl[np][2], bl[np][3], bo + ARR_B);
        }
#pragma unroll
        for (int mt = 0; mt < 4; mt++) {
            uint32_t ah[4], al[4];
            uint32_t ao = st + a_frag_base + mt * (16 * PITCHB);
            ldsm_x4(ah[0], ah[1], ah[2], ah[3], ao);
            ldsm_x4(al[0], al[1], al[2], al[3], ao + ARR_B);
#pragma unroll
            for (int nt = 0; nt < 4; nt++) {
                int np = nt >> 1, hv = (nt & 1) * 2;
                mma16816(acc[mt][nt], ah, bh[np][hv], bh[np][hv + 1]);
                mma16816(acc[mt][nt], ah, bl[np][hv], bl[np][hv + 1]);
                mma16816(acc[mt][nt], al, bh[np][hv], bh[np][hv + 1]);
            }
        }
    }

#pragma unroll
    for (int mt = 0; mt < 4; mt++) {
        int r = row0 + wm * 64 + mt * 16 + (lane >> 2);
#pragma unroll
        for (int nt = 0; nt < 4; nt++) {
            int c = col0 + wn * 32 + nt * 8 + (lane & 3) * 2;
            if (c < Nreal) {
                *(float2*)&C[(size_t)r * Nreal + c]       = make_float2(acc[mt][nt][0], acc[mt][nt][1]);
                *(float2*)&C[(size_t)(r + 8) * Nreal + c] = make_float2(acc[mt][nt][2], acc[mt][nt][3]);
            }
        }
    }
#undef GFILL_NC
}

// ---------------- dt (softplus+clip) and per-chunk cumsum of dt*A ----------------
__global__ void dtcs_kernel(const float* __restrict__ dt_bias, const float* __restrict__ A_log) {
    int c = blockIdx.x, h = blockIdx.y;
    int t = threadIdx.x;
    int Lg = c * CHh + t;
    float raw = g_zx[(size_t)Lg * OUT_IN + DTRAW_OFF + h] + dt_bias[h];
    float sp = (raw > 20.f) ? raw : log1pf(expf(raw));
    float dt = fminf(fmaxf(sp, 0.f), 100.f);
    float A = -expf(A_log[h]);
    __shared__ float s[256];
    s[t] = dt * A;
    __syncthreads();
    for (int off = 1; off < 256; off <<= 1) {
        float v = (t >= off) ? s[t - off] : 0.f;
        __syncthreads();
        s[t] += v;
        __syncthreads();
    }
    int base = (c * Hh + h) * CHh;
    g_dt[base + t] = dt;
    g_acs[base + t] = s[t];
}

// ---------------- fused: causal conv + silu + xdt/BC bf16 split ----------------
__global__ void conv_fused_kernel(const float* __restrict__ cw, const float* __restrict__ cb) {
    int c = blockIdx.x * 256 + threadIdx.x;
    int l = blockIdx.y;
    float acc = cb[c];
#pragma unroll
    for (int k = 0; k < 4; k++) {
        int ll = l + k - 3;
        if (ll >= 0) acc = fmaf(g_zx[(size_t)ll * OUT_IN + XBC_OFF + c], cw[k * CONV_DIM + c], acc);
    }
    float s = acc / (1.f + expf(-acc));
    if (c < INTER) {
        int h = c >> 6;
        float dtv = g_dt[((l >> 8) * Hh + h) * CHh + (l & 255)];
        g_x[(size_t)l * INTER + c] = s;
        __nv_bfloat16 hh, ll2;
        split2(s * dtv, hh, ll2);
        g_xdth[(size_t)l * INTER + c] = hh;
        g_xdtl[(size_t)l * INTER + c] = ll2;
    } else {
        int cc = c - INTER;
        __nv_bfloat16 hh, ll2;
        split2(s, hh, ll2);
        g_bch[(size_t)l * 256 + cc] = hh;
        g_bcl[(size_t)l * 256 + cc] = ll2;
    }
}

// ---------------- HMMA states ----------------
extern __shared__ __align__(128) char ssm2[];
__global__ void __launch_bounds__(128, 2)
states_hmma() {
    const uint32_t sb = smem_u32(ssm2);
    const int tid = threadIdx.x, lane = tid & 31, w = tid >> 5;
    const int c = blockIdx.x, h = blockIdx.y;
    const int base = (c * Hh + h) * CHh;
    const float aend = g_acs[base + 255];
    float* wb = (float*)(ssm2 + 53248);
    for (int t = tid; t < 256; t += 128) wb[t] = expf(aend - g_acs[base + t]);

    float sacc[16][4];
#pragma unroll
    for (int j = 0; j < 16; j++)
#pragma unroll
        for (int v = 0; v < 4; v++) sacc[j][v] = 0.f;

    const uint32_t axb = sb + ((lane & 7) + (lane >> 4) * 8) * 144 + 32 * w + ((lane >> 3) & 1) * 16;
    const uint32_t bxb = sb + 18432 + ((lane & 7) + ((lane >> 3) & 1) * 8) * 272 + (lane >> 4) * 16;

    for (int kt = 0; kt < 4; kt++) {
        __syncthreads();
        int l0 = kt * 64;
        for (int e = tid; e < 2048; e += 128) {
            int row = e >> 5, seg = e & 31;
            int lg = c * CHh + l0 + row;
            __nv_bfloat162 xh2 = *(const __nv_bfloat162*)&g_xdth[(size_t)lg * INTER + h * 64 + seg * 2];
            __nv_bfloat162 xl2 = *(const __nv_bfloat162*)&g_xdtl[(size_t)lg * INTER + h * 64 + seg * 2];
            float wv = wb[l0 + row];
            float v0 = (__bfloat162float(xh2.x) + __bfloat162float(xl2.x)) * wv;
            float v1 = (__bfloat162float(xh2.y) + __bfloat162float(xl2.y)) * wv;
            __nv_bfloat16 a0, a1, b0, b1;
            split2(v0, a0, b0); split2(v1, a1, b1);
            *(uint32_t*)(ssm2 + row * 144 + seg * 4) = pk(a0, a1);
            *(uint32_t*)(ssm2 + 9216 + row * 144 + seg * 4) = pk(b0, b1);
        }
        for (int e = tid; e < 2048; e += 128) {
            int row = e >> 5, seg = e & 31;
            int lg = c * CHh + l0 + row;
            *(uint2*)(ssm2 + 18432 + row * 272 + seg * 8) = *(const uint2*)&g_bch[(size_t)lg * 256 + seg * 4];
            *(uint2*)(ssm2 + 35840 + row * 272 + seg * 8) = *(const uint2*)&g_bcl[(size_t)lg * 256 + seg * 4];
        }
        __syncthreads();

#pragma unroll
        for (int t = 0; t < 4; t++) {
            uint32_t ah[4], al[4];
            ldsm_x4_t(ah[0], ah[1], ah[2], ah[3], axb + t * 2304);
            ldsm_x4_t(al[0], al[1], al[2], al[3], axb + 9216 + t * 2304);
#pragma unroll
            for (int np = 0; np < 8; np++) {
                uint32_t bh[4], bl[4];
                ldsm_x4_t(bh[0], bh[1], bh[2], bh[3], bxb + t * 4352 + np * 32);
                ldsm_x4_t(bl[0], bl[1], bl[2], bl[3], bxb + 17408 + t * 4352 + np * 32);
                mma16816(sacc[2 * np],     ah, bh[0], bh[1]);
                mma16816(sacc[2 * np + 1], ah, bh[2], bh[3]);
                mma16816(sacc[2 * np],     ah, bl[0], bl[1]);
                mma16816(sacc[2 * np + 1], ah, bl[2], bl[3]);
                mma16816(sacc[2 * np],     al, bh[0], bh[1]);
                mma16816(sacc[2 * np + 1], al, bh[2], bh[3]);
            }
        }
    }

    float* out = g_states + (size_t)(c * Hh + h) * 8192;
    int p0 = 16 * w + (lane >> 2);
#pragma unroll
    for (int j = 0; j < 16; j++) {
        int n = 8 * j + 2 * (lane & 3);
        *(float2*)&out[p0 * 128 + n]       = make_float2(sacc[j][0], sacc[j][1]);
        *(float2*)&out[(p0 + 8) * 128 + n] = make_float2(sacc[j][2], sacc[j][3]);
    }
}

// ---------------- inter-chunk state scan (emits split stin) ----------------
__global__ void scan_kernel() {
    int idx = blockIdx.x * 256 + threadIdx.x;
    int h = idx >> 13;
    int rem = idx & 8191;
    float st = 0.f;
    for (int c = 0; c < NC; c++) {
        size_t o = (size_t)(c * Hh + h) * 8192 + rem;
        __nv_bfloat16 hi, lo;
        split2(st, hi, lo);
        g_stinh[o] = hi;
        g_stinl[o] = lo;
        float cend = g_acs[(c * Hh + h) * CHh + 255];
        st = st * expf(cend) + g_states[o];
    }
}

// ---------------- HMMA fused Y kernel ----------------
#define OFF_CL  17408
#define OFF_UH  34816
#define OFF_UL  52224
#define OFF_XH  69632
#define OFF_XL  78848
#define OFF_AL  88064
#define OFF_AS  88320
extern __shared__ __align__(128) char ysm2[];
__global__ void __launch_bounds__(128, 2)
y_hmma(const float* __restrict__ Dv) {
    const uint32_t sb = smem_u32(ysm2);
    const int tid = threadIdx.x, lane = tid & 31, w = tid >> 5;
    const int lt = blockIdx.x, c = blockIdx.y, h = blockIdx.z;
    const int base = (c * Hh + h) * CHh;
    const int Lrow0 = c * CHh + lt * 64;
    float* acsl = (float*)(ysm2 + OFF_AL);
    float* acss = (float*)(ysm2 + OFF_AS);

    {
        const size_t sinb = (size_t)(c * Hh + h) * 8192;
        for (int e = tid; e < 2048; e += 128) {
            int row = e >> 5, seg = e & 31;
            *(uint2*)(ysm2 + row * 272 + seg * 8) =
                *(const uint2*)&g_bch[(size_t)(Lrow0 + row) * 256 + 128 + seg * 4];
            *(uint2*)(ysm2 + OFF_CL + row * 272 + seg * 8) =
                *(const uint2*)&g_bcl[(size_t)(Lrow0 + row) * 256 + 128 + seg * 4];
            *(uint2*)(ysm2 + OFF_UH + row * 272 + seg * 8) =
                *(const uint2*)&g_stinh[sinb + row * 128 + seg * 4];
            *(uint2*)(ysm2 + OFF_UL + row * 272 + seg * 8) =
                *(const uint2*)&g_stinl[sinb + row * 128 + seg * 4];
        }
        if (tid < 64) acsl[tid] = g_acs[base + lt * 64 + tid];
    }
    __syncthreads();

    const uint32_t a_base = sb + (16 * w + (lane & 15)) * 272 + (lane >> 4) * 16;
    const uint32_t b_base = sb + OFF_UH + ((lane & 7) + (lane >> 4) * 8) * 272 + ((lane >> 3) & 1) * 16;
    const uint32_t x_base = sb + OFF_XH + ((lane & 7) + ((lane >> 3) & 1) * 8) * 144 + (lane >> 4) * 16;

    float yacc[8][4];
#pragma unroll
    for (int j = 0; j < 8; j++)
#pragma unroll
        for (int v = 0; v < 4; v++) yacc[j][v] = 0.f;

    // Y_off = C . Sin^T
#pragma unroll
    for (int kk = 0; kk < 8; kk++) {
        uint32_t ah[4], al[4];
        ldsm_x4(ah[0], ah[1], ah[2], ah[3], a_base + kk * 32);
        ldsm_x4(al[0], al[1], al[2], al[3], a_base + OFF_CL + kk * 32);
#pragma unroll
        for (int np = 0; np < 4; np++) {
            uint32_t bh[4], bl[4];
            ldsm_x4(bh[0], bh[1], bh[2], bh[3], b_base + np * 4352 + kk * 32);
            ldsm_x4(bl[0], bl[1], bl[2], bl[3], b_base + 17408 + np * 4352 + kk * 32);
            mma16816(yacc[2 * np],     ah, bh[0], bh[1]);
            mma16816(yacc[2 * np + 1], ah, bh[2], bh[3]);
            mma16816(yacc[2 * np],     ah, bl[0], bl[1]);
            mma16816(yacc[2 * np + 1], ah, bl[2], bl[3]);
            mma16816(yacc[2 * np],     al, bh[0], bh[1]);
            mma16816(yacc[2 * np + 1], al, bh[2], bh[3]);
        }
    }
    {
        float e0 = expf(acsl[16 * w + (lane >> 2)]);
        float e1 = expf(acsl[16 * w + (lane >> 2) + 8]);
#pragma unroll
        for (int j = 0; j < 8; j++) {
            yacc[j][0] *= e0; yacc[j][1] *= e0;
            yacc[j][2] *= e1; yacc[j][3] *= e1;
        }
    }

    for (int st = 0; st <= lt; st++) {
        const int Srow0 = c * CHh + st * 64;
        __syncthreads();
        for (int e = tid; e < 2048; e += 128) {
            int row = e >> 5, seg = e & 31;
            *(uint2*)(ysm2 + OFF_UH + row * 272 + seg * 8) =
                *(const uint2*)&g_bch[(size_t)(Srow0 + row) * 256 + seg * 4];
            *(uint2*)(ysm2 + OFF_UL + row * 272 + seg * 8) =
                *(const uint2*)&g_bcl[(size_t)(Srow0 + row) * 256 + seg * 4];
        }
        for (int e = tid; e < 1024; e += 128) {
            int row = e >> 4, seg = e & 15;
            *(uint2*)(ysm2 + OFF_XH + row * 144 + seg * 8) =
                *(const uint2*)&g_xdth[(size_t)(Srow0 + row) * INTER + h * 64 + seg * 4];
            *(uint2*)(ysm2 + OFF_XL + row * 144 + seg * 8) =
                *(const uint2*)&g_xdtl[(size_t)(Srow0 + row) * INTER + h * 64 + seg * 4];
        }
        if (tid < 64) acss[tid] = g_acs[base + st * 64 + tid];
        __syncthreads();

        float gacc[8][4];
#pragma unroll
        for (int j = 0; j < 8; j++)
#pragma unroll
            for (int v = 0; v < 4; v++) gacc[j][v] = 0.f;
#pragma unroll
        for (int kk = 0; kk < 8; kk++) {
            uint32_t ah[4], al[4];
            ldsm_x4(ah[0], ah[1], ah[2], ah[3], a_base + kk * 32);
            ldsm_x4(al[0], al[1], al[2], al[3], a_base + OFF_CL + kk * 32);
#pragma unroll
            for (int np = 0; np < 4; np++) {
                uint32_t bh[4], bl[4];
                ldsm_x4(bh[0], bh[1], bh[2], bh[3], b_base + np * 4352 + kk * 32);
                ldsm_x4(bl[0], bl[1], bl[2], bl[3], b_base + 17408 + np * 4352 + kk * 32);
                mma16816(gacc[2 * np],     ah, bh[0], bh[1]);
                mma16816(gacc[2 * np + 1], ah, bh[2], bh[3]);
                mma16816(gacc[2 * np],     ah, bl[0], bl[1]);
                mma16816(gacc[2 * np + 1], ah, bl[2], bl[3]);
                mma16816(gacc[2 * np],     al, bh[0], bh[1]);
                mma16816(gacc[2 * np + 1], al, bh[2], bh[3]);
            }
        }

        {
            float rA = acsl[16 * w + (lane >> 2)];
            float rB = acsl[16 * w + (lane >> 2) + 8];
            bool diag = (st == lt);
            int l0 = 16 * w + (lane >> 2);
#pragma unroll
            for (int j = 0; j < 8; j++) {
                int s0 = 8 * j + 2 * (lane & 3);
                float c0 = acss[s0], c1 = acss[s0 + 1];
                float e00 = expf(rA - c0), e01 = expf(rA - c1);
                float e10 = expf(rB - c0), e11 = expf(rB - c1);
                if (diag) {
                    if (s0 > l0)         e00 = 0.f;
                    if (s0 + 1 > l0)     e01 = 0.f;
                    if (s0 > l0 + 8)     e10 = 0.f;
                    if (s0 + 1 > l0 + 8) e11 = 0.f;
                }
                gacc[j][0] *= e00; gacc[j][1] *= e01;
                gacc[j][2] *= e10; gacc[j][3] *= e11;
            }
        }

#pragma unroll
        for (int t = 0; t < 4; t++) {
            uint32_t gah[4], gal[4];
            {
                __nv_bfloat16 h0, h1, h2, h3, l0b, l1b, l2b, l3b;
                split2(gacc[2 * t][0], h0, l0b); split2(gacc[2 * t][1], h1, l1b);
                split2(gacc[2 * t][2], h2, l2b); split2(gacc[2 * t][3], h3, l3b);
                gah[0] = pk(h0, h1); gah[1] = pk(h2, h3);
                gal[0] = pk(l0b, l1b); gal[1] = pk(l2b, l3b);
                split2(gacc[2 * t + 1][0], h0, l0b); split2(gacc[2 * t + 1][1], h1, l1b);
                split2(gacc[2 * t + 1][2], h2, l2b); split2(gacc[2 * t + 1][3], h3, l3b);
                gah[2] = pk(h0, h1); gah[3] = pk(h2, h3);
                gal[2] = pk(l0b, l1b); gal[3] = pk(l2b, l3b);
            }
#pragma unroll
            for (int np = 0; np < 4; np++) {
                uint32_t xh[4], xl[4];
                ldsm_x4_t(xh[0], xh[1], xh[2], xh[3], x_base + t * 2304 + np * 32);
                ldsm_x4_t(xl[0], xl[1], xl[2], xl[3], x_base + 9216 + t * 2304 + np * 32);
                mma16816(yacc[2 * np],     gah, xh[0], xh[1]);
                mma16816(yacc[2 * np + 1], gah, xh[2], xh[3]);
                mma16816(yacc[2 * np],     gah, xl[0], xl[1]);
                mma16816(yacc[2 * np + 1], gah, xl[2], xl[3]);
                mma16816(yacc[2 * np],     gal, xh[0], xh[1]);
                mma16816(yacc[2 * np + 1], gal, xh[2], xh[3]);
            }
        }
    }

    // epilogue: + x*D, write g_y
    float dh = Dv[h];
    int r0 = Lrow0 + 16 * w + (lane >> 2);
#pragma unroll
    for (int j = 0; j < 8; j++) {
        int p = h * 64 + 8 * j + 2 * (lane & 3);
        float2 x0 = *(const float2*)&g_x[(size_t)r0 * INTER + p];
        float2 x1 = *(const float2*)&g_x[(size_t)(r0 + 8) * INTER + p];
        *(float2*)&g_y[(size_t)r0 * INTER + p] =
            make_float2(yacc[j][0] + x0.x * dh, yacc[j][1] + x0.y * dh);
        *(float2*)&g_y[(size_t)(r0 + 8) * INTER + p] =
            make_float2(yacc[j][2] + x1.x * dh, yacc[j][3] + x1.y * dh);
    }
}

// ---------------- gated RMSNorm fused with bf16 hi/lo split ----------------
__global__ void rmsnorm_split_kernel(const float* __restrict__ nw) {
    int l = blockIdx.x;
    int tid = threadIdx.x;
    float v[16];
    float ss = 0.f;
#pragma unroll
    for (int i = 0; i < 16; i++) {
        int col = tid + i * 256;
        float y = g_y[(size_t)l * INTER + col];
        float z = g_zx[(size_t)l * OUT_IN + col];
        float yf = y * (z / (1.f + expf(-z)));
        v[i] = yf;
        ss = fmaf(yf, yf, ss);
    }
    __shared__ float red[256];
    red[tid] = ss;
    __syncthreads();
    for (int o = 128; o > 0; o >>= 1) {
        if (tid < o) red[tid] += red[tid + o];
        __syncthreads();
    }
    float scale = rsqrtf(red[0] / (float)INTER + 1e-5f);
#pragma unroll
    for (int i = 0; i < 16; i++) {
        int col = tid + i * 256;
        float yn = v[i] * scale * nw[col];
        __nv_bfloat16 h, lo;
        split2(yn, h, lo);
        gA2h[(size_t)l * INTER + col] = h;
        gA2l[(size_t)l * INTER + col] = lo;
    }
}

// ---------------- launch ----------------
extern "C" void kernel_launch(void* const* d_in, const int* in_sizes, int n_in,
                              void* d_out, int out_size) {
    const float* hs      = (const float*)d_in[0];
    const float* W_in    = (const float*)d_in[1];
    const float* conv_w  = (const float*)d_in[2];
    const float* conv_b  = (const float*)d_in[3];
    const float* dt_bias = (const float*)d_in[4];
    const float* A_log   = (const float*)d_in[5];
    const float* Dv      = (const float*)d_in[6];
    const float* norm_w  = (const float*)d_in[7];
    const float* W_out   = (const float*)d_in[8];
    float* out = (float*)d_out;

    void *p_zx;
    void *pA1h, *pA1l, *pB1h, *pB1l, *pA2h, *pA2l, *pB2h, *pB2l;
    cudaGetSymbolAddress(&p_zx, g_zx);
    cudaGetSymbolAddress(&pA1h, gA1h); cudaGetSymbolAddress(&pA1l, gA1l);
    cudaGetSymbolAddress(&pB1h, gB1h); cudaGetSymbolAddress(&pB1l, gB1l);
    cudaGetSymbolAddress(&pA2h, gA2h); cudaGetSymbolAddress(&pA2l, gA2l);
    cudaGetSymbolAddress(&pB2h, gB2h); cudaGetSymbolAddress(&pB2l, gB2l);

    const int GSMEM = NSTG * STAGE_B;   // 98304 -> 2 CTAs/SM (192 KB of 228 KB)
    cudaFuncSetAttribute(gemm_hmma, cudaFuncAttributeMaxDynamicSharedMemorySize, GSMEM);
    cudaFuncSetAttribute(y_hmma, cudaFuncAttributeMaxDynamicSharedMemorySize, 88576);
    cudaFuncSetAttribute(states_hmma, cudaFuncAttributeMaxDynamicSharedMemorySize, 54272);

    // 1) split hs -> A1
    split_kernel<<<(L_ * HIDD / 4 + 255) / 256, 256>>>(hs, (__nv_bfloat16*)pA1h, (__nv_bfloat16*)pA1l, L_ * HIDD / 4);
    // 2) transpose+split W_in -> B1
    transpose_split_kernel<<<dim3(OUT_IN_PAD / 32, HIDD / 32), dim3(32, 8)>>>(
        W_in, (__nv_bfloat16*)pB1h, (__nv_bfloat16*)pB1l, HIDD, OUT_IN);
    // 3) transpose+split W_out -> B2
    transpose_split_kernel<<<dim3(HIDD / 32, INTER / 32), dim3(32, 8)>>>(
        W_out, (__nv_bfloat16*)pB2h, (__nv_bfloat16*)pB2l, INTER, HIDD);
    // 4) zxbcdt = hs @ W_in   <-- profiled launch
    gemm_hmma<<<dim3(OUT_IN_PAD / 128, L_ / 128), 256, GSMEM>>>(
        (const __nv_bfloat16*)pA1h, (const __nv_bfloat16*)pA1l,
        (const __nv_bfloat16*)pB1h, (const __nv_bfloat16*)pB1l,
        (float*)p_zx, OUT_IN, HIDD);
    // 5) dt + per-chunk cumsum
    dtcs_kernel<<<dim3(NC, Hh), 256>>>(dt_bias, A_log);
    // 6) fused conv + silu + xdt/BC splits
    conv_fused_kernel<<<dim3(CONV_DIM / 256, L_), 256>>>(conv_w, conv_b);
    // 7) per-chunk states (HMMA)
    states_hmma<<<dim3(NC, Hh), 128, 54272>>>();
    // 8) inter-chunk scan
    scan_kernel<<<(Hh * Pp * Nn) / 256, 256>>>();
    // 9) Y (HMMA)
    y_hmma<<<dim3(4, NC, Hh), 128, 88576>>>(Dv);
    // 10) gated RMSNorm + split A2
    rmsnorm_split_kernel<<<L_, 256>>>(norm_w);
    // 11) out = yn @ W_out
    gemm_hmma<<<dim3(HIDD / 128, L_ / 128), 256, GSMEM>>>(
        (const __nv_bfloat16*)pA2h, (const __nv_bfloat16*)pA2l,
        (const __nv_bfloat16*)pB2h, (const __nv_bfloat16*)pB2l,
        out, HIDD, INTER);
}

// round 9
// speedup vs baseline: 2.8820x; 1.0078x over previous
#include <cuda_runtime.h>
#include <cuda_bf16.h>
#include <math.h>
#include <cstdint>

// ---------------- problem constants ----------------
#define L_       4096
#define HIDD     2048
#define Hh       64
#define Pp       64
#define Nn       128
#define CHh      256
#define NC       16
#define INTER    4096
#define CONV_DIM 4352            // INTER + 2N
#define OUT_IN   8512            // 2*(INTER+N) + H
#define OUT_IN_PAD 8576          // 67 * 128
#define XBC_OFF  INTER
#define DTRAW_OFF (2*INTER + 2*Nn)

// ---------------- device scratch (static; no runtime alloc) ----------------
__device__ float g_zx[L_ * OUT_IN];
__device__ float g_x[L_ * INTER];
__device__ float g_dt[NC * Hh * CHh];
__device__ float g_acs[NC * Hh * CHh];
__device__ float g_states[NC * Hh * Pp * Nn];
__device__ float g_y[L_ * INTER];

__device__ __nv_bfloat16 gA1h[L_ * HIDD];
__device__ __nv_bfloat16 gA1l[L_ * HIDD];
__device__ __nv_bfloat16 gB1h[OUT_IN_PAD * HIDD];
__device__ __nv_bfloat16 gB1l[OUT_IN_PAD * HIDD];
__device__ __nv_bfloat16 gA2h[L_ * INTER];
__device__ __nv_bfloat16 gA2l[L_ * INTER];
__device__ __nv_bfloat16 gB2h[HIDD * INTER];
__device__ __nv_bfloat16 gB2l[HIDD * INTER];

__device__ __nv_bfloat16 g_xdth[L_ * INTER];
__device__ __nv_bfloat16 g_xdtl[L_ * INTER];
__device__ __nv_bfloat16 g_bch[L_ * 256];
__device__ __nv_bfloat16 g_bcl[L_ * 256];
__device__ __nv_bfloat16 g_stinh[NC * Hh * Pp * Nn];
__device__ __nv_bfloat16 g_stinl[NC * Hh * Pp * Nn];

// ================= low-level helpers =================
__device__ __forceinline__ uint32_t smem_u32(const void* p) {
    uint32_t a;
    asm("{ .reg .u64 t; cvta.to.shared.u64 t, %1; cvt.u32.u64 %0, t; }" : "=r"(a) : "l"(p));
    return a;
}
#define CP16(sm, gm) \
    asm volatile("cp.async.cg.shared.global [%0], [%1], 16;" :: "r"(sm), "l"(gm) : "memory")
#define CP_COMMIT() asm volatile("cp.async.commit_group;" ::: "memory")
#define CP_WAIT(n)  asm volatile("cp.async.wait_group %0;" :: "n"(n) : "memory")

__device__ __forceinline__ void ldsm_x4(uint32_t& r0, uint32_t& r1, uint32_t& r2, uint32_t& r3,
                                        uint32_t addr) {
    asm volatile("ldmatrix.sync.aligned.m8n8.x4.shared.b16 {%0,%1,%2,%3}, [%4];"
                 : "=r"(r0), "=r"(r1), "=r"(r2), "=r"(r3) : "r"(addr));
}
__device__ __forceinline__ void ldsm_x4_t(uint32_t& r0, uint32_t& r1, uint32_t& r2, uint32_t& r3,
                                          uint32_t addr) {
    asm volatile("ldmatrix.sync.aligned.m8n8.x4.trans.shared.b16 {%0,%1,%2,%3}, [%4];"
                 : "=r"(r0), "=r"(r1), "=r"(r2), "=r"(r3) : "r"(addr));
}
__device__ __forceinline__ void mma16816(float* d, const uint32_t* a, uint32_t b0, uint32_t b1) {
    asm volatile("mma.sync.aligned.m16n8k16.row.col.f32.bf16.bf16.f32 "
                 "{%0,%1,%2,%3}, {%4,%5,%6,%7}, {%8,%9}, {%0,%1,%2,%3};"
                 : "+f"(d[0]), "+f"(d[1]), "+f"(d[2]), "+f"(d[3])
                 : "r"(a[0]), "r"(a[1]), "r"(a[2]), "r"(a[3]), "r"(b0), "r"(b1));
}
__device__ __forceinline__ uint32_t pk(__nv_bfloat16 a, __nv_bfloat16 b) {
    __nv_bfloat162 t; t.x = a; t.y = b;
    return *reinterpret_cast<uint32_t*>(&t);
}
__device__ __forceinline__ void split2(float x, __nv_bfloat16& h, __nv_bfloat16& l) {
    h = __float2bfloat16(x);
    l = __float2bfloat16(x - __bfloat162float(h));
}

// ================= split / transpose conversion kernels =================
__global__ void split_kernel(const float* __restrict__ in, __nv_bfloat16* __restrict__ hi,
                             __nv_bfloat16* __restrict__ lo, int n4) {
    int i = blockIdx.x * 256 + threadIdx.x;
    if (i >= n4) return;
    float4 v = ((const float4*)in)[i];
    __nv_bfloat16 h0, h1, h2, h3, l0, l1, l2, l3;
    split2(v.x, h0, l0); split2(v.y, h1, l1); split2(v.z, h2, l2); split2(v.w, h3, l3);
    ((uint2*)hi)[i] = make_uint2(pk(h0, h1), pk(h2, h3));
    ((uint2*)lo)[i] = make_uint2(pk(l0, l1), pk(l2, l3));
}

__global__ void transpose_split_kernel(const float* __restrict__ W,
                                       __nv_bfloat16* __restrict__ outH,
                                       __nv_bfloat16* __restrict__ outL,
                                       int K, int N) {
    __shared__ float tile[32][33];
    int n0 = blockIdx.x * 32, k0 = blockIdx.y * 32;
    int tx = threadIdx.x, ty = threadIdx.y;
#pragma unroll
    for (int i = 0; i < 4; i++) {
        int k = k0 + ty + i * 8;
        int n = n0 + tx;
        tile[ty + i * 8][tx] = (n < N) ? W[(size_t)k * N + n] : 0.f;
    }
    __syncthreads();
#pragma unroll
    for (int i = 0; i < 4; i++) {
        int nrow = n0 + ty + i * 8;
        int kcol = k0 + tx;
        float x = tile[tx][ty + i * 8];
        __nv_bfloat16 h, l;
        split2(x, h, l);
        outH[(size_t)nrow * K + kcol] = h;
        outL[(size_t)nrow * K + kcol] = l;
    }
}

// ================= HMMA split-bf16 GEMM: packed hi/lo rows, 5 stages =================
// Row = [hi 32B | lo 32B | pad 16B], pitch 80B. (addr/16)%8 step 5 -> conflict-free.
// 5 stages x 20480B = 100KB/CTA -> 2 CTA/SM. wait_group(2): stage ready 1 iter early.
#define KT      16
#define PITCHB  80
#define PARR_B  (128 * PITCHB)            // 10240 per packed array (A or B)
#define STAGE_B (2 * PARR_B)              // 20480
#define NSTG    5

extern __shared__ __align__(128) char gsm_raw[];

__global__ void __launch_bounds__(256, 2)
gemm_hmma(const __nv_bfloat16* __restrict__ Ah, const __nv_bfloat16* __restrict__ Al,
          const __nv_bfloat16* __restrict__ Bh, const __nv_bfloat16* __restrict__ Bl,
          float* __restrict__ C, int Nreal, int K) {
    const int tid = threadIdx.x;
    const int lane = tid & 31, wid = tid >> 5;
    const int wm = wid & 1, wn = wid >> 1;     // 2x4 warp grid; warp tile 64x32
    const int row0 = blockIdx.y * 128, col0 = blockIdx.x * 128;
    const uint32_t sb = smem_u32(gsm_raw);

    // cp.async: 256 threads = 128 rows x 2 16B-halves; each thread fills hi+lo of its half
    const int lrow = tid >> 1;
    const int lelem = (tid & 1) * 8;
    const __nv_bfloat16* pAh = Ah + (size_t)(row0 + lrow) * K + lelem;
    const __nv_bfloat16* pAl = Al + (size_t)(row0 + lrow) * K + lelem;
    const __nv_bfloat16* pBh = Bh + (size_t)(col0 + lrow) * K + lelem;
    const __nv_bfloat16* pBl = Bl + (size_t)(col0 + lrow) * K + lelem;
    const uint32_t dstA = lrow * PITCHB + (tid & 1) * 16;      // 16B aligned

    float acc[4][4][4];
#pragma unroll
    for (int m = 0; m < 4; m++)
#pragma unroll
        for (int n = 0; n < 4; n++)
#pragma unroll
            for (int v = 0; v < 4; v++) acc[m][n][v] = 0.f;

    const int T = K / KT;

#define GFILL_NC(sidx, ko) do { \
        uint32_t _s = sb + (sidx) * STAGE_B; \
        CP16(_s + dstA,               pAh + (ko)); \
        CP16(_s + dstA + 32,          pAl + (ko)); \
        CP16(_s + PARR_B + dstA,      pBh + (ko)); \
        CP16(_s + PARR_B + dstA + 32, pBl + (ko)); \
    } while (0)

    // prologue: fill stages 0..3, one commit group each
#pragma unroll
    for (int t = 0; t < 4; t++) {
        GFILL_NC(t, t * KT);
        CP_COMMIT();
    }

    const uint32_t a_frag_base = (wm * 64 + (lane & 15)) * PITCHB + (lane >> 4) * 16;
    const uint32_t b_frag_base = (wn * 32 + (lane & 7) + (lane >> 4) * 8) * PITCHB
                                 + ((lane >> 3) & 1) * 16;

    int sread = 0, sfill = 4;
    for (int t = 0; t < T; t++) {
        // committed = 4+t; wait(2) -> groups <= t+1 complete -> stage t ready with slack
        CP_WAIT(2);
        __syncthreads();
        if (t + 4 < T) GFILL_NC(sfill, (t + 4) * KT);
        CP_COMMIT();

        const uint32_t st = sb + sread * STAGE_B;
        uint32_t bh[2][4], bl[2][4];
#pragma unroll
        for (int np = 0; np < 2; np++) {
            uint32_t bo = st + PARR_B + b_frag_base + np * (16 * PITCHB);
            ldsm_x4(bh[np][0], bh[np][1], bh[np][2], bh[np][3], bo);
            ldsm_x4(bl[np][0], bl[np][1], bl[np][2], bl[np][3], bo + 32);
        }
#pragma unroll
        for (int mt = 0; mt < 4; mt++) {
            uint32_t ah[4], al[4];
            uint32_t ao = st + a_frag_base + mt * (16 * PITCHB);
            ldsm_x4(ah[0], ah[1], ah[2], ah[3], ao);
            ldsm_x4(al[0], al[1], al[2], al[3], ao + 32);
#pragma unroll
            for (int nt = 0; nt < 4; nt++) {
                int np = nt >> 1, hv = (nt & 1) * 2;
                mma16816(acc[mt][nt], ah, bh[np][hv], bh[np][hv + 1]);
                mma16816(acc[mt][nt], ah, bl[np][hv], bl[np][hv + 1]);
                mma16816(acc[mt][nt], al, bh[np][hv], bh[np][hv + 1]);
            }
        }
        sread = (sread + 1 == NSTG) ? 0 : sread + 1;
        sfill = (sfill + 1 == NSTG) ? 0 : sfill + 1;
    }

#pragma unroll
    for (int mt = 0; mt < 4; mt++) {
        int r = row0 + wm * 64 + mt * 16 + (lane >> 2);
#pragma unroll
        for (int nt = 0; nt < 4; nt++) {
            int c = col0 + wn * 32 + nt * 8 + (lane & 3) * 2;
            if (c < Nreal) {
                *(float2*)&C[(size_t)r * Nreal + c]       = make_float2(acc[mt][nt][0], acc[mt][nt][1]);
                *(float2*)&C[(size_t)(r + 8) * Nreal + c] = make_float2(acc[mt][nt][2], acc[mt][nt][3]);
            }
        }
    }
#undef GFILL_NC
}

// ---------------- dt (softplus+clip) and per-chunk cumsum of dt*A ----------------
__global__ void dtcs_kernel(const float* __restrict__ dt_bias, const float* __restrict__ A_log) {
    int c = blockIdx.x, h = blockIdx.y;
    int t = threadIdx.x;
    int Lg = c * CHh + t;
    float raw = g_zx[(size_t)Lg * OUT_IN + DTRAW_OFF + h] + dt_bias[h];
    float sp = (raw > 20.f) ? raw : log1pf(expf(raw));
    float dt = fminf(fmaxf(sp, 0.f), 100.f);
    float A = -expf(A_log[h]);
    __shared__ float s[256];
    s[t] = dt * A;
    __syncthreads();
    for (int off = 1; off < 256; off <<= 1) {
        float v = (t >= off) ? s[t - off] : 0.f;
        __syncthreads();
        s[t] += v;
        __syncthreads();
    }
    int base = (c * Hh + h) * CHh;
    g_dt[base + t] = dt;
    g_acs[base + t] = s[t];
}

// ---------------- fused: causal conv + silu + xdt/BC bf16 split ----------------
__global__ void conv_fused_kernel(const float* __restrict__ cw, const float* __restrict__ cb) {
    int c = blockIdx.x * 256 + threadIdx.x;
    int l = blockIdx.y;
    float acc = cb[c];
#pragma unroll
    for (int k = 0; k < 4; k++) {
        int ll = l + k - 3;
        if (ll >= 0) acc = fmaf(g_zx[(size_t)ll * OUT_IN + XBC_OFF + c], cw[k * CONV_DIM + c], acc);
    }
    float s = acc / (1.f + expf(-acc));
    if (c < INTER) {
        int h = c >> 6;
        float dtv = g_dt[((l >> 8) * Hh + h) * CHh + (l & 255)];
        g_x[(size_t)l * INTER + c] = s;
        __nv_bfloat16 hh, ll2;
        split2(s * dtv, hh, ll2);
        g_xdth[(size_t)l * INTER + c] = hh;
        g_xdtl[(size_t)l * INTER + c] = ll2;
    } else {
        int cc = c - INTER;
        __nv_bfloat16 hh, ll2;
        split2(s, hh, ll2);
        g_bch[(size_t)l * 256 + cc] = hh;
        g_bcl[(size_t)l * 256 + cc] = ll2;
    }
}

// ---------------- HMMA states ----------------
extern __shared__ __align__(128) char ssm2[];
__global__ void __launch_bounds__(128, 2)
states_hmma() {
    const uint32_t sb = smem_u32(ssm2);
    const int tid = threadIdx.x, lane = tid & 31, w = tid >> 5;
    const int c = blockIdx.x, h = blockIdx.y;
    const int base = (c * Hh + h) * CHh;
    const float aend = g_acs[base + 255];
    float* wb = (float*)(ssm2 + 53248);
    for (int t = tid; t < 256; t += 128) wb[t] = expf(aend - g_acs[base + t]);

    float sacc[16][4];
#pragma unroll
    for (int j = 0; j < 16; j++)
#pragma unroll
        for (int v = 0; v < 4; v++) sacc[j][v] = 0.f;

    const uint32_t axb = sb + ((lane & 7) + (lane >> 4) * 8) * 144 + 32 * w + ((lane >> 3) & 1) * 16;
    const uint32_t bxb = sb + 18432 + ((lane & 7) + ((lane >> 3) & 1) * 8) * 272 + (lane >> 4) * 16;

    for (int kt = 0; kt < 4; kt++) {
        __syncthreads();
        int l0 = kt * 64;
        for (int e = tid; e < 2048; e += 128) {
            int row = e >> 5, seg = e & 31;
            int lg = c * CHh + l0 + row;
            __nv_bfloat162 xh2 = *(const __nv_bfloat162*)&g_xdth[(size_t)lg * INTER + h * 64 + seg * 2];
            __nv_bfloat162 xl2 = *(const __nv_bfloat162*)&g_xdtl[(size_t)lg * INTER + h * 64 + seg * 2];
            float wv = wb[l0 + row];
            float v0 = (__bfloat162float(xh2.x) + __bfloat162float(xl2.x)) * wv;
            float v1 = (__bfloat162float(xh2.y) + __bfloat162float(xl2.y)) * wv;
            __nv_bfloat16 a0, a1, b0, b1;
            split2(v0, a0, b0); split2(v1, a1, b1);
            *(uint32_t*)(ssm2 + row * 144 + seg * 4) = pk(a0, a1);
            *(uint32_t*)(ssm2 + 9216 + row * 144 + seg * 4) = pk(b0, b1);
        }
        for (int e = tid; e < 2048; e += 128) {
            int row = e >> 5, seg = e & 31;
            int lg = c * CHh + l0 + row;
            *(uint2*)(ssm2 + 18432 + row * 272 + seg * 8) = *(const uint2*)&g_bch[(size_t)lg * 256 + seg * 4];
            *(uint2*)(ssm2 + 35840 + row * 272 + seg * 8) = *(const uint2*)&g_bcl[(size_t)lg * 256 + seg * 4];
        }
        __syncthreads();

#pragma unroll
        for (int t = 0; t < 4; t++) {
            uint32_t ah[4], al[4];
            ldsm_x4_t(ah[0], ah[1], ah[2], ah[3], axb + t * 2304);
            ldsm_x4_t(al[0], al[1], al[2], al[3], axb + 9216 + t * 2304);
#pragma unroll
            for (int np = 0; np < 8; np++) {
                uint32_t bh[4], bl[4];
                ldsm_x4_t(bh[0], bh[1], bh[2], bh[3], bxb + t * 4352 + np * 32);
                ldsm_x4_t(bl[0], bl[1], bl[2], bl[3], bxb + 17408 + t * 4352 + np * 32);
                mma16816(sacc[2 * np],     ah, bh[0], bh[1]);
                mma16816(sacc[2 * np + 1], ah, bh[2], bh[3]);
                mma16816(sacc[2 * np],     ah, bl[0], bl[1]);
                mma16816(sacc[2 * np + 1], ah, bl[2], bl[3]);
                mma16816(sacc[2 * np],     al, bh[0], bh[1]);
                mma16816(sacc[2 * np + 1], al, bh[2], bh[3]);
            }
        }
    }

    float* out = g_states + (size_t)(c * Hh + h) * 8192;
    int p0 = 16 * w + (lane >> 2);
#pragma unroll
    for (int j = 0; j < 16; j++) {
        int n = 8 * j + 2 * (lane & 3);
        *(float2*)&out[p0 * 128 + n]       = make_float2(sacc[j][0], sacc[j][1]);
        *(float2*)&out[(p0 + 8) * 128 + n] = make_float2(sacc[j][2], sacc[j][3]);
    }
}

// ---------------- inter-chunk state scan (emits split stin) ----------------
__global__ void scan_kernel() {
    int idx = blockIdx.x * 256 + threadIdx.x;
    int h = idx >> 13;
    int rem = idx & 8191;
    float st = 0.f;
    for (int c = 0; c < NC; c++) {
        size_t o = (size_t)(c * Hh + h) * 8192 + rem;
        __nv_bfloat16 hi, lo;
        split2(st, hi, lo);
        g_stinh[o] = hi;
        g_stinl[o] = lo;
        float cend = g_acs[(c * Hh + h) * CHh + 255];
        st = st * expf(cend) + g_states[o];
    }
}

// ---------------- HMMA fused Y kernel ----------------
#define OFF_CL  17408
#define OFF_UH  34816
#define OFF_UL  52224
#define OFF_XH  69632
#define OFF_XL  78848
#define OFF_AL  88064
#define OFF_AS  88320
extern __shared__ __align__(128) char ysm2[];
__global__ void __launch_bounds__(128, 2)
y_hmma(const float* __restrict__ Dv) {
    const uint32_t sb = smem_u32(ysm2);
    const int tid = threadIdx.x, lane = tid & 31, w = tid >> 5;
    const int lt = blockIdx.x, c = blockIdx.y, h = blockIdx.z;
    const int base = (c * Hh + h) * CHh;
    const int Lrow0 = c * CHh + lt * 64;
    float* acsl = (float*)(ysm2 + OFF_AL);
    float* acss = (float*)(ysm2 + OFF_AS);

    {
        const size_t sinb = (size_t)(c * Hh + h) * 8192;
        for (int e = tid; e < 2048; e += 128) {
            int row = e >> 5, seg = e & 31;
            *(uint2*)(ysm2 + row * 272 + seg * 8) =
                *(const uint2*)&g_bch[(size_t)(Lrow0 + row) * 256 + 128 + seg * 4];
            *(uint2*)(ysm2 + OFF_CL + row * 272 + seg * 8) =
                *(const uint2*)&g_bcl[(size_t)(Lrow0 + row) * 256 + 128 + seg * 4];
            *(uint2*)(ysm2 + OFF_UH + row * 272 + seg * 8) =
                *(const uint2*)&g_stinh[sinb + row * 128 + seg * 4];
            *(uint2*)(ysm2 + OFF_UL + row * 272 + seg * 8) =
                *(const uint2*)&g_stinl[sinb + row * 128 + seg * 4];
        }
        if (tid < 64) acsl[tid] = g_acs[base + lt * 64 + tid];
    }
    __syncthreads();

    const uint32_t a_base = sb + (16 * w + (lane & 15)) * 272 + (lane >> 4) * 16;
    const uint32_t b_base = sb + OFF_UH + ((lane & 7) + (lane >> 4) * 8) * 272 + ((lane >> 3) & 1) * 16;
    const uint32_t x_base = sb + OFF_XH + ((lane & 7) + ((lane >> 3) & 1) * 8) * 144 + (lane >> 4) * 16;

    float yacc[8][4];
#pragma unroll
    for (int j = 0; j < 8; j++)
#pragma unroll
        for (int v = 0; v < 4; v++) yacc[j][v] = 0.f;

    // Y_off = C . Sin^T
#pragma unroll
    for (int kk = 0; kk < 8; kk++) {
        uint32_t ah[4], al[4];
        ldsm_x4(ah[0], ah[1], ah[2], ah[3], a_base + kk * 32);
        ldsm_x4(al[0], al[1], al[2], al[3], a_base + OFF_CL + kk * 32);
#pragma unroll
        for (int np = 0; np < 4; np++) {
            uint32_t bh[4], bl[4];
            ldsm_x4(bh[0], bh[1], bh[2], bh[3], b_base + np * 4352 + kk * 32);
            ldsm_x4(bl[0], bl[1], bl[2], bl[3], b_base + 17408 + np * 4352 + kk * 32);
            mma16816(yacc[2 * np],     ah, bh[0], bh[1]);
            mma16816(yacc[2 * np + 1], ah, bh[2], bh[3]);
            mma16816(yacc[2 * np],     ah, bl[0], bl[1]);
            mma16816(yacc[2 * np + 1], ah, bl[2], bl[3]);
            mma16816(yacc[2 * np],     al, bh[0], bh[1]);
            mma16816(yacc[2 * np + 1], al, bh[2], bh[3]);
        }
    }
    {
        float e0 = expf(acsl[16 * w + (lane >> 2)]);
        float e1 = expf(acsl[16 * w + (lane >> 2) + 8]);
#pragma unroll
        for (int j = 0; j < 8; j++) {
            yacc[j][0] *= e0; yacc[j][1] *= e0;
            yacc[j][2] *= e1; yacc[j][3] *= e1;
        }
    }

    for (int st = 0; st <= lt; st++) {
        const int Srow0 = c * CHh + st * 64;
        __syncthreads();
        for (int e = tid; e < 2048; e += 128) {
            int row = e >> 5, seg = e & 31;
            *(uint2*)(ysm2 + OFF_UH + row * 272 + seg * 8) =
                *(const uint2*)&g_bch[(size_t)(Srow0 + row) * 256 + seg * 4];
            *(uint2*)(ysm2 + OFF_UL + row * 272 + seg * 8) =
                *(const uint2*)&g_bcl[(size_t)(Srow0 + row) * 256 + seg * 4];
        }
        for (int e = tid; e < 1024; e += 128) {
            int row = e >> 4, seg = e & 15;
            *(uint2*)(ysm2 + OFF_XH + row * 144 + seg * 8) =
                *(const uint2*)&g_xdth[(size_t)(Srow0 + row) * INTER + h * 64 + seg * 4];
            *(uint2*)(ysm2 + OFF_XL + row * 144 + seg * 8) =
                *(const uint2*)&g_xdtl[(size_t)(Srow0 + row) * INTER + h * 64 + seg * 4];
        }
        if (tid < 64) acss[tid] = g_acs[base + st * 64 + tid];
        __syncthreads();

        float gacc[8][4];
#pragma unroll
        for (int j = 0; j < 8; j++)
#pragma unroll
            for (int v = 0; v < 4; v++) gacc[j][v] = 0.f;
#pragma unroll
        for (int kk = 0; kk < 8; kk++) {
            uint32_t ah[4], al[4];
            ldsm_x4(ah[0], ah[1], ah[2], ah[3], a_base + kk * 32);
            ldsm_x4(al[0], al[1], al[2], al[3], a_base + OFF_CL + kk * 32);
#pragma unroll
            for (int np = 0; np < 4; np++) {
                uint32_t bh[4], bl[4];
                ldsm_x4(bh[0], bh[1], bh[2], bh[3], b_base + np * 4352 + kk * 32);
                ldsm_x4(bl[0], bl[1], bl[2], bl[3], b_base + 17408 + np * 4352 + kk * 32);
                mma16816(gacc[2 * np],     ah, bh[0], bh[1]);
                mma16816(gacc[2 * np + 1], ah, bh[2], bh[3]);
                mma16816(gacc[2 * np],     ah, bl[0], bl[1]);
                mma16816(gacc[2 * np + 1], ah, bl[2], bl[3]);
                mma16816(gacc[2 * np],     al, bh[0], bh[1]);
                mma16816(gacc[2 * np + 1], al, bh[2], bh[3]);
            }
        }

        {
            float rA = acsl[16 * w + (lane >> 2)];
            float rB = acsl[16 * w + (lane >> 2) + 8];
            bool diag = (st == lt);
            int l0 = 16 * w + (lane >> 2);
#pragma unroll
            for (int j = 0; j < 8; j++) {
                int s0 = 8 * j + 2 * (lane & 3);
                float c0 = acss[s0], c1 = acss[s0 + 1];
                float e00 = expf(rA - c0), e01 = expf(rA - c1);
                float e10 = expf(rB - c0), e11 = expf(rB - c1);
                if (diag) {
                    if (s0 > l0)         e00 = 0.f;
                    if (s0 + 1 > l0)     e01 = 0.f;
                    if (s0 > l0 + 8)     e10 = 0.f;
                    if (s0 + 1 > l0 + 8) e11 = 0.f;
                }
                gacc[j][0] *= e00; gacc[j][1] *= e01;
                gacc[j][2] *= e10; gacc[j][3] *= e11;
            }
        }

#pragma unroll
        for (int t = 0; t < 4; t++) {
            uint32_t gah[4], gal[4];
            {
                __nv_bfloat16 h0, h1, h2, h3, l0b, l1b, l2b, l3b;
                split2(gacc[2 * t][0], h0, l0b); split2(gacc[2 * t][1], h1, l1b);
                split2(gacc[2 * t][2], h2, l2b); split2(gacc[2 * t][3], h3, l3b);
                gah[0] = pk(h0, h1); gah[1] = pk(h2, h3);
                gal[0] = pk(l0b, l1b); gal[1] = pk(l2b, l3b);
                split2(gacc[2 * t + 1][0], h0, l0b); split2(gacc[2 * t + 1][1], h1, l1b);
                split2(gacc[2 * t + 1][2], h2, l2b); split2(gacc[2 * t + 1][3], h3, l3b);
                gah[2] = pk(h0, h1); gah[3] = pk(h2, h3);
                gal[2] = pk(l0b, l1b); gal[3] = pk(l2b, l3b);
            }
#pragma unroll
            for (int np = 0; np < 4; np++) {
                uint32_t xh[4], xl[4];
                ldsm_x4_t(xh[0], xh[1], xh[2], xh[3], x_base + t * 2304 + np * 32);
                ldsm_x4_t(xl[0], xl[1], xl[2], xl[3], x_base + 9216 + t * 2304 + np * 32);
                mma16816(yacc[2 * np],     gah, xh[0], xh[1]);
                mma16816(yacc[2 * np + 1], gah, xh[2], xh[3]);
                mma16816(yacc[2 * np],     gah, xl[0], xl[1]);
                mma16816(yacc[2 * np + 1], gah, xl[2], xl[3]);
                mma16816(yacc[2 * np],     gal, xh[0], xh[1]);
                mma16816(yacc[2 * np + 1], gal, xh[2], xh[3]);
            }
        }
    }

    // epilogue: + x*D, write g_y
    float dh = Dv[h];
    int r0 = Lrow0 + 16 * w + (lane >> 2);
#pragma unroll
    for (int j = 0; j < 8; j++) {
        int p = h * 64 + 8 * j + 2 * (lane & 3);
        float2 x0 = *(const float2*)&g_x[(size_t)r0 * INTER + p];
        float2 x1 = *(const float2*)&g_x[(size_t)(r0 + 8) * INTER + p];
        *(float2*)&g_y[(size_t)r0 * INTER + p] =
            make_float2(yacc[j][0] + x0.x * dh, yacc[j][1] + x0.y * dh);
        *(float2*)&g_y[(size_t)(r0 + 8) * INTER + p] =
            make_float2(yacc[j][2] + x1.x * dh, yacc[j][3] + x1.y * dh);
    }
}

// ---------------- gated RMSNorm fused with bf16 hi/lo split ----------------
__global__ void rmsnorm_split_kernel(const float* __restrict__ nw) {
    int l = blockIdx.x;
    int tid = threadIdx.x;
    float v[16];
    float ss = 0.f;
#pragma unroll
    for (int i = 0; i < 16; i++) {
        int col = tid + i * 256;
        float y = g_y[(size_t)l * INTER + col];
        float z = g_zx[(size_t)l * OUT_IN + col];
        float yf = y * (z / (1.f + expf(-z)));
        v[i] = yf;
        ss = fmaf(yf, yf, ss);
    }
    __shared__ float red[256];
    red[tid] = ss;
    __syncthreads();
    for (int o = 128; o > 0; o >>= 1) {
        if (tid < o) red[tid] += red[tid + o];
        __syncthreads();
    }
    float scale = rsqrtf(red[0] / (float)INTER + 1e-5f);
#pragma unroll
    for (int i = 0; i < 16; i++) {
        int col = tid + i * 256;
        float yn = v[i] * scale * nw[col];
        __nv_bfloat16 h, lo;
        split2(yn, h, lo);
        gA2h[(size_t)l * INTER + col] = h;
        gA2l[(size_t)l * INTER + col] = lo;
    }
}

// ---------------- launch ----------------
extern "C" void kernel_launch(void* const* d_in, const int* in_sizes, int n_in,
                              void* d_out, int out_size) {
    const float* hs      = (const float*)d_in[0];
    const float* W_in    = (const float*)d_in[1];
    const float* conv_w  = (const float*)d_in[2];
    const float* conv_b  = (const float*)d_in[3];
    const float* dt_bias = (const float*)d_in[4];
    const float* A_log   = (const float*)d_in[5];
    const float* Dv      = (const float*)d_in[6];
    const float* norm_w  = (const float*)d_in[7];
    const float* W_out   = (const float*)d_in[8];
    float* out = (float*)d_out;

    void *p_zx;
    void *pA1h, *pA1l, *pB1h, *pB1l, *pA2h, *pA2l, *pB2h, *pB2l;
    cudaGetSymbolAddress(&p_zx, g_zx);
    cudaGetSymbolAddress(&pA1h, gA1h); cudaGetSymbolAddress(&pA1l, gA1l);
    cudaGetSymbolAddress(&pB1h, gB1h); cudaGetSymbolAddress(&pB1l, gB1l);
    cudaGetSymbolAddress(&pA2h, gA2h); cudaGetSymbolAddress(&pA2l, gA2l);
    cudaGetSymbolAddress(&pB2h, gB2h); cudaGetSymbolAddress(&pB2l, gB2l);

    const int GSMEM = NSTG * STAGE_B;   // 102400 -> 2 CTAs/SM (200 KB)
    cudaFuncSetAttribute(gemm_hmma, cudaFuncAttributeMaxDynamicSharedMemorySize, GSMEM);
    cudaFuncSetAttribute(y_hmma, cudaFuncAttributeMaxDynamicSharedMemorySize, 88576);
    cudaFuncSetAttribute(states_hmma, cudaFuncAttributeMaxDynamicSharedMemorySize, 54272);

    // 1) split hs -> A1
    split_kernel<<<(L_ * HIDD / 4 + 255) / 256, 256>>>(hs, (__nv_bfloat16*)pA1h, (__nv_bfloat16*)pA1l, L_ * HIDD / 4);
    // 2) transpose+split W_in -> B1
    transpose_split_kernel<<<dim3(OUT_IN_PAD / 32, HIDD / 32), dim3(32, 8)>>>(
        W_in, (__nv_bfloat16*)pB1h, (__nv_bfloat16*)pB1l, HIDD, OUT_IN);
    // 3) transpose+split W_out -> B2
    transpose_split_kernel<<<dim3(HIDD / 32, INTER / 32), dim3(32, 8)>>>(
        W_out, (__nv_bfloat16*)pB2h, (__nv_bfloat16*)pB2l, INTER, HIDD);
    // 4) zxbcdt = hs @ W_in   <-- profiled launch
    gemm_hmma<<<dim3(OUT_IN_PAD / 128, L_ / 128), 256, GSMEM>>>(
        (const __nv_bfloat16*)pA1h, (const __nv_bfloat16*)pA1l,
        (const __nv_bfloat16*)pB1h, (const __nv_bfloat16*)pB1l,
        (float*)p_zx, OUT_IN, HIDD);
    // 5) dt + per-chunk cumsum
    dtcs_kernel<<<dim3(NC, Hh), 256>>>(dt_bias, A_log);
    // 6) fused conv + silu + xdt/BC splits
    conv_fused_kernel<<<dim3(CONV_DIM / 256, L_), 256>>>(conv_w, conv_b);
    // 7) per-chunk states (HMMA)
    states_hmma<<<dim3(NC, Hh), 128, 54272>>>();
    // 8) inter-chunk scan
    scan_kernel<<<(Hh * Pp * Nn) / 256, 256>>>();
    // 9) Y (HMMA)
    y_hmma<<<dim3(4, NC, Hh), 128, 88576>>>(Dv);
    // 10) gated RMSNorm + split A2
    rmsnorm_split_kernel<<<L_, 256>>>(norm_w);
    // 11) out = yn @ W_out
    gemm_hmma<<<dim3(HIDD / 128, L_ / 128), 256, GSMEM>>>(
        (const __nv_bfloat16*)pA2h, (const __nv_bfloat16*)pA2l,
        (const __nv_bfloat16*)pB2h, (const __nv_bfloat16*)pB2l,
        out, HIDD, INTER);
}

// round 11
// speedup vs baseline: 3.0546x; 1.0599x over previous
#include <cuda_runtime.h>
#include <cuda_bf16.h>
#include <math.h>
#include <cstdint>

// ---------------- problem constants ----------------
#define L_       4096
#define HIDD     2048
#define Hh       64
#define Pp       64
#define Nn       128
#define CHh      256
#define NC       16
#define INTER    4096
#define CONV_DIM 4352            // INTER + 2N
#define OUT_IN   8512            // 2*(INTER+N) + H
#define OUT_IN_PAD 8576          // 67 * 128
#define XBC_OFF  INTER
#define DTRAW_OFF (2*INTER + 2*Nn)

// ---------------- device scratch (static; no runtime alloc) ----------------
__device__ float g_zx[L_ * OUT_IN];
__device__ float g_x[L_ * INTER];
__device__ float g_dt[NC * Hh * CHh];
__device__ float g_acs[NC * Hh * CHh];
__device__ float g_states[NC * Hh * Pp * Nn];
__device__ float g_y[L_ * INTER];

__device__ __nv_bfloat16 gA1h[L_ * HIDD];
__device__ __nv_bfloat16 gA1l[L_ * HIDD];
__device__ __nv_bfloat16 gB1h[OUT_IN_PAD * HIDD];
__device__ __nv_bfloat16 gB1l[OUT_IN_PAD * HIDD];
__device__ __nv_bfloat16 gA2h[L_ * INTER];
__device__ __nv_bfloat16 gA2l[L_ * INTER];
__device__ __nv_bfloat16 gB2h[HIDD * INTER];
__device__ __nv_bfloat16 gB2l[HIDD * INTER];

__device__ __nv_bfloat16 g_xdth[L_ * INTER];
__device__ __nv_bfloat16 g_xdtl[L_ * INTER];
__device__ __nv_bfloat16 g_bch[L_ * 256];
__device__ __nv_bfloat16 g_bcl[L_ * 256];
__device__ __nv_bfloat16 g_stinh[NC * Hh * Pp * Nn];
__device__ __nv_bfloat16 g_stinl[NC * Hh * Pp * Nn];

// ================= low-level helpers =================
__device__ __forceinline__ uint32_t smem_u32(const void* p) {
    uint32_t a;
    asm("{ .reg .u64 t; cvta.to.shared.u64 t, %1; cvt.u32.u64 %0, t; }" : "=r"(a) : "l"(p));
    return a;
}
#define CP16(sm, gm) \
    asm volatile("cp.async.cg.shared.global [%0], [%1], 16;" :: "r"(sm), "l"(gm) : "memory")
#define CP_COMMIT() asm volatile("cp.async.commit_group;" ::: "memory")
#define CP_WAIT(n)  asm volatile("cp.async.wait_group %0;" :: "n"(n) : "memory")

__device__ __forceinline__ void ldsm_x4(uint32_t& r0, uint32_t& r1, uint32_t& r2, uint32_t& r3,
                                        uint32_t addr) {
    asm volatile("ldmatrix.sync.aligned.m8n8.x4.shared.b16 {%0,%1,%2,%3}, [%4];"
                 : "=r"(r0), "=r"(r1), "=r"(r2), "=r"(r3) : "r"(addr));
}
__device__ __forceinline__ void ldsm_x4_t(uint32_t& r0, uint32_t& r1, uint32_t& r2, uint32_t& r3,
                                          uint32_t addr) {
    asm volatile("ldmatrix.sync.aligned.m8n8.x4.trans.shared.b16 {%0,%1,%2,%3}, [%4];"
                 : "=r"(r0), "=r"(r1), "=r"(r2), "=r"(r3) : "r"(addr));
}
__device__ __forceinline__ void mma16816(float* d, const uint32_t* a, uint32_t b0, uint32_t b1) {
    asm volatile("mma.sync.aligned.m16n8k16.row.col.f32.bf16.bf16.f32 "
                 "{%0,%1,%2,%3}, {%4,%5,%6,%7}, {%8,%9}, {%0,%1,%2,%3};"
                 : "+f"(d[0]), "+f"(d[1]), "+f"(d[2]), "+f"(d[3])
                 : "r"(a[0]), "r"(a[1]), "r"(a[2]), "r"(a[3]), "r"(b0), "r"(b1));
}
__device__ __forceinline__ uint32_t pk(__nv_bfloat16 a, __nv_bfloat16 b) {
    __nv_bfloat162 t; t.x = a; t.y = b;
    return *reinterpret_cast<uint32_t*>(&t);
}
__device__ __forceinline__ void split2(float x, __nv_bfloat16& h, __nv_bfloat16& l) {
    h = __float2bfloat16(x);
    l = __float2bfloat16(x - __bfloat162float(h));
}

// ================= split / transpose conversion kernels =================
__global__ void split_kernel(const float* __restrict__ in, __nv_bfloat16* __restrict__ hi,
                             __nv_bfloat16* __restrict__ lo, int n4) {
    int i = blockIdx.x * 256 + threadIdx.x;
    if (i >= n4) return;
    float4 v = ((const float4*)in)[i];
    __nv_bfloat16 h0, h1, h2, h3, l0, l1, l2, l3;
    split2(v.x, h0, l0); split2(v.y, h1, l1); split2(v.z, h2, l2); split2(v.w, h3, l3);
    ((uint2*)hi)[i] = make_uint2(pk(h0, h1), pk(h2, h3));
    ((uint2*)lo)[i] = make_uint2(pk(l0, l1), pk(l2, l3));
}

__global__ void transpose_split_kernel(const float* __restrict__ W,
                                       __nv_bfloat16* __restrict__ outH,
                                       __nv_bfloat16* __restrict__ outL,
                                       int K, int N) {
    __shared__ float tile[32][33];
    int n0 = blockIdx.x * 32, k0 = blockIdx.y * 32;
    int tx = threadIdx.x, ty = threadIdx.y;
#pragma unroll
    for (int i = 0; i < 4; i++) {
        int k = k0 + ty + i * 8;
        int n = n0 + tx;
        tile[ty + i * 8][tx] = (n < N) ? W[(size_t)k * N + n] : 0.f;
    }
    __syncthreads();
#pragma unroll
    for (int i = 0; i < 4; i++) {
        int nrow = n0 + ty + i * 8;
        int kcol = k0 + tx;
        float x = tile[tx][ty + i * 8];
        __nv_bfloat16 h, l;
        split2(x, h, l);
        outH[(size_t)nrow * K + kcol] = h;
        outL[(size_t)nrow * K + kcol] = l;
    }
}

// ================= HMMA split-bf16 GEMM: packed hi/lo rows, 5 stages =================
#define KT      16
#define PITCHB  80
#define PARR_B  (128 * PITCHB)            // 10240 per packed array (A or B)
#define STAGE_B (2 * PARR_B)              // 20480
#define NSTG    5

extern __shared__ __align__(128) char gsm_raw[];

__global__ void __launch_bounds__(256, 2)
gemm_hmma(const __nv_bfloat16* __restrict__ Ah, const __nv_bfloat16* __restrict__ Al,
          const __nv_bfloat16* __restrict__ Bh, const __nv_bfloat16* __restrict__ Bl,
          float* __restrict__ C, int Nreal, int K) {
    const int tid = threadIdx.x;
    const int lane = tid & 31, wid = tid >> 5;
    const int wm = wid & 1, wn = wid >> 1;
    const int row0 = blockIdx.y * 128, col0 = blockIdx.x * 128;
    const uint32_t sb = smem_u32(gsm_raw);

    const int lrow = tid >> 1;
    const int lelem = (tid & 1) * 8;
    const __nv_bfloat16* pAh = Ah + (size_t)(row0 + lrow) * K + lelem;
    const __nv_bfloat16* pAl = Al + (size_t)(row0 + lrow) * K + lelem;
    const __nv_bfloat16* pBh = Bh + (size_t)(col0 + lrow) * K + lelem;
    const __nv_bfloat16* pBl = Bl + (size_t)(col0 + lrow) * K + lelem;
    const uint32_t dstA = lrow * PITCHB + (tid & 1) * 16;

    float acc[4][4][4];
#pragma unroll
    for (int m = 0; m < 4; m++)
#pragma unroll
        for (int n = 0; n < 4; n++)
#pragma unroll
            for (int v = 0; v < 4; v++) acc[m][n][v] = 0.f;

    const int T = K / KT;

#define GFILL_NC(sidx, ko) do { \
        uint32_t _s = sb + (sidx) * STAGE_B; \
        CP16(_s + dstA,               pAh + (ko)); \
        CP16(_s + dstA + 32,          pAl + (ko)); \
        CP16(_s + PARR_B + dstA,      pBh + (ko)); \
        CP16(_s + PARR_B + dstA + 32, pBl + (ko)); \
    } while (0)

#pragma unroll
    for (int t = 0; t < 4; t++) {
        GFILL_NC(t, t * KT);
        CP_COMMIT();
    }

    const uint32_t a_frag_base = (wm * 64 + (lane & 15)) * PITCHB + (lane >> 4) * 16;
    const uint32_t b_frag_base = (wn * 32 + (lane & 7) + (lane >> 4) * 8) * PITCHB
                                 + ((lane >> 3) & 1) * 16;

    int sread = 0, sfill = 4;
    for (int t = 0; t < T; t++) {
        CP_WAIT(2);
        __syncthreads();
        if (t + 4 < T) GFILL_NC(sfill, (t + 4) * KT);
        CP_COMMIT();

        const uint32_t st = sb + sread * STAGE_B;
        uint32_t bh[2][4], bl[2][4];
#pragma unroll
        for (int np = 0; np < 2; np++) {
            uint32_t bo = st + PARR_B + b_frag_base + np * (16 * PITCHB);
            ldsm_x4(bh[np][0], bh[np][1], bh[np][2], bh[np][3], bo);
            ldsm_x4(bl[np][0], bl[np][1], bl[np][2], bl[np][3], bo + 32);
        }
#pragma unroll
        for (int mt = 0; mt < 4; mt++) {
            uint32_t ah[4], al[4];
            uint32_t ao = st + a_frag_base + mt * (16 * PITCHB);
            ldsm_x4(ah[0], ah[1], ah[2], ah[3], ao);
            ldsm_x4(al[0], al[1], al[2], al[3], ao + 32);
#pragma unroll
            for (int nt = 0; nt < 4; nt++) {
                int np = nt >> 1, hv = (nt & 1) * 2;
                mma16816(acc[mt][nt], ah, bh[np][hv], bh[np][hv + 1]);
                mma16816(acc[mt][nt], ah, bl[np][hv], bl[np][hv + 1]);
                mma16816(acc[mt][nt], al, bh[np][hv], bh[np][hv + 1]);
            }
        }
        sread = (sread + 1 == NSTG) ? 0 : sread + 1;
        sfill = (sfill + 1 == NSTG) ? 0 : sfill + 1;
    }

#pragma unroll
    for (int mt = 0; mt < 4; mt++) {
        int r = row0 + wm * 64 + mt * 16 + (lane >> 2);
#pragma unroll
        for (int nt = 0; nt < 4; nt++) {
            int c = col0 + wn * 32 + nt * 8 + (lane & 3) * 2;
            if (c < Nreal) {
                *(float2*)&C[(size_t)r * Nreal + c]       = make_float2(acc[mt][nt][0], acc[mt][nt][1]);
                *(float2*)&C[(size_t)(r + 8) * Nreal + c] = make_float2(acc[mt][nt][2], acc[mt][nt][3]);
            }
        }
    }
#undef GFILL_NC
}

// ---------------- dt (softplus+clip) and per-chunk cumsum of dt*A ----------------
__global__ void dtcs_kernel(const float* __restrict__ dt_bias, const float* __restrict__ A_log) {
    int c = blockIdx.x, h = blockIdx.y;
    int t = threadIdx.x;
    int Lg = c * CHh + t;
    float raw = g_zx[(size_t)Lg * OUT_IN + DTRAW_OFF + h] + dt_bias[h];
    float sp = (raw > 20.f) ? raw : log1pf(expf(raw));
    float dt = fminf(fmaxf(sp, 0.f), 100.f);
    float A = -expf(A_log[h]);
    __shared__ float s[256];
    s[t] = dt * A;
    __syncthreads();
    for (int off = 1; off < 256; off <<= 1) {
        float v = (t >= off) ? s[t - off] : 0.f;
        __syncthreads();
        s[t] += v;
        __syncthreads();
    }
    int base = (c * Hh + h) * CHh;
    g_dt[base + t] = dt;
    g_acs[base + t] = s[t];
}

// ---------------- fused: causal conv + silu + xdt/BC bf16 split ----------------
__global__ void conv_fused_kernel(const float* __restrict__ cw, const float* __restrict__ cb) {
    int c = blockIdx.x * 256 + threadIdx.x;
    int l = blockIdx.y;
    float acc = cb[c];
#pragma unroll
    for (int k = 0; k < 4; k++) {
        int ll = l + k - 3;
        if (ll >= 0) acc = fmaf(g_zx[(size_t)ll * OUT_IN + XBC_OFF + c], cw[k * CONV_DIM + c], acc);
    }
    float s = acc / (1.f + expf(-acc));
    if (c < INTER) {
        int h = c >> 6;
        float dtv = g_dt[((l >> 8) * Hh + h) * CHh + (l & 255)];
        g_x[(size_t)l * INTER + c] = s;
        __nv_bfloat16 hh, ll2;
        split2(s * dtv, hh, ll2);
        g_xdth[(size_t)l * INTER + c] = hh;
        g_xdtl[(size_t)l * INTER + c] = ll2;
    } else {
        int cc = c - INTER;
        __nv_bfloat16 hh, ll2;
        split2(s, hh, ll2);
        g_bch[(size_t)l * 256 + cc] = hh;
        g_bcl[(size_t)l * 256 + cc] = ll2;
    }
}

// ---------------- HMMA states (cp.async B staging overlapped with X' compute) ----------------
extern __shared__ __align__(128) char ssm2[];
__global__ void __launch_bounds__(128, 2)
states_hmma() {
    const uint32_t sb = smem_u32(ssm2);
    const int tid = threadIdx.x, lane = tid & 31, w = tid >> 5;
    const int c = blockIdx.x, h = blockIdx.y;
    const int base = (c * Hh + h) * CHh;
    const float aend = g_acs[base + 255];
    float* wb = (float*)(ssm2 + 53248);
    for (int t = tid; t < 256; t += 128) wb[t] = expf(aend - g_acs[base + t]);

    float sacc[16][4];
#pragma unroll
    for (int j = 0; j < 16; j++)
#pragma unroll
        for (int v = 0; v < 4; v++) sacc[j][v] = 0.f;

    const uint32_t axb = sb + ((lane & 7) + (lane >> 4) * 8) * 144 + 32 * w + ((lane >> 3) & 1) * 16;
    const uint32_t bxb = sb + 18432 + ((lane & 7) + ((lane >> 3) & 1) * 8) * 272 + (lane >> 4) * 16;

    for (int kt = 0; kt < 4; kt++) {
        __syncthreads();
        int l0 = kt * 64;
        // B staging via cp.async: 64 rows x 16 16B-segments = 1024 entries (R10 bug: was 512)
        for (int e = tid; e < 1024; e += 128) {
            int row = e >> 4, s = e & 15;
            int lg = c * CHh + l0 + row;
            CP16(sb + 18432 + row * 272 + s * 16, &g_bch[(size_t)lg * 256 + s * 8]);
            CP16(sb + 35840 + row * 272 + s * 16, &g_bcl[(size_t)lg * 256 + s * 8]);
        }
        CP_COMMIT();
        // X' = decay * xdt (compute in regs, store to smem) — overlaps with B cp.async
        for (int e = tid; e < 2048; e += 128) {
            int row = e >> 5, seg = e & 31;
            int lg = c * CHh + l0 + row;
            __nv_bfloat162 xh2 = *(const __nv_bfloat162*)&g_xdth[(size_t)lg * INTER + h * 64 + seg * 2];
            __nv_bfloat162 xl2 = *(const __nv_bfloat162*)&g_xdtl[(size_t)lg * INTER + h * 64 + seg * 2];
            float wv = wb[l0 + row];
            float v0 = (__bfloat162float(xh2.x) + __bfloat162float(xl2.x)) * wv;
            float v1 = (__bfloat162float(xh2.y) + __bfloat162float(xl2.y)) * wv;
            __nv_bfloat16 a0, a1, b0, b1;
            split2(v0, a0, b0); split2(v1, a1, b1);
            *(uint32_t*)(ssm2 + row * 144 + seg * 4) = pk(a0, a1);
            *(uint32_t*)(ssm2 + 9216 + row * 144 + seg * 4) = pk(b0, b1);
        }
        CP_WAIT(0);
        __syncthreads();

#pragma unroll
        for (int t = 0; t < 4; t++) {
            uint32_t ah[4], al[4];
            ldsm_x4_t(ah[0], ah[1], ah[2], ah[3], axb + t * 2304);
            ldsm_x4_t(al[0], al[1], al[2], al[3], axb + 9216 + t * 2304);
#pragma unroll
            for (int np = 0; np < 8; np++) {
                uint32_t bh[4], bl[4];
                ldsm_x4_t(bh[0], bh[1], bh[2], bh[3], bxb + t * 4352 + np * 32);
                ldsm_x4_t(bl[0], bl[1], bl[2], bl[3], bxb + 17408 + t * 4352 + np * 32);
                mma16816(sacc[2 * np],     ah, bh[0], bh[1]);
                mma16816(sacc[2 * np + 1], ah, bh[2], bh[3]);
                mma16816(sacc[2 * np],     ah, bl[0], bl[1]);
                mma16816(sacc[2 * np + 1], ah, bl[2], bl[3]);
                mma16816(sacc[2 * np],     al, bh[0], bh[1]);
                mma16816(sacc[2 * np + 1], al, bh[2], bh[3]);
            }
        }
    }

    float* out = g_states + (size_t)(c * Hh + h) * 8192;
    int p0 = 16 * w + (lane >> 2);
#pragma unroll
    for (int j = 0; j < 16; j++) {
        int n = 8 * j + 2 * (lane & 3);
        *(float2*)&out[p0 * 128 + n]       = make_float2(sacc[j][0], sacc[j][1]);
        *(float2*)&out[(p0 + 8) * 128 + n] = make_float2(sacc[j][2], sacc[j][3]);
    }
}

// ---------------- inter-chunk state scan (emits split stin) ----------------
__global__ void scan_kernel() {
    int idx = blockIdx.x * 256 + threadIdx.x;
    int h = idx >> 13;
    int rem = idx & 8191;
    float st = 0.f;
    for (int c = 0; c < NC; c++) {
        size_t o = (size_t)(c * Hh + h) * 8192 + rem;
        __nv_bfloat16 hi, lo;
        split2(st, hi, lo);
        g_stinh[o] = hi;
        g_stinl[o] = lo;
        float cend = g_acs[(c * Hh + h) * CHh + 255];
        st = st * expf(cend) + g_states[o];
    }
}

// ---------------- HMMA fused Y kernel (cp.async staging) ----------------
#define OFF_CL  17408
#define OFF_UH  34816
#define OFF_UL  52224
#define OFF_XH  69632
#define OFF_XL  78848
#define OFF_AL  88064
#define OFF_AS  88320
extern __shared__ __align__(128) char ysm2[];
__global__ void __launch_bounds__(128, 2)
y_hmma(const float* __restrict__ Dv) {
    const uint32_t sb = smem_u32(ysm2);
    const int tid = threadIdx.x, lane = tid & 31, w = tid >> 5;
    const int lt = blockIdx.x, c = blockIdx.y, h = blockIdx.z;
    const int base = (c * Hh + h) * CHh;
    const int Lrow0 = c * CHh + lt * 64;
    float* acsl = (float*)(ysm2 + OFF_AL);
    float* acss = (float*)(ysm2 + OFF_AS);

    {
        const size_t sinb = (size_t)(c * Hh + h) * 8192;
        for (int e = tid; e < 1024; e += 128) {
            int row = e >> 4, s = e & 15;
            CP16(sb + row * 272 + s * 16,          &g_bch[(size_t)(Lrow0 + row) * 256 + 128 + s * 8]);
            CP16(sb + OFF_CL + row * 272 + s * 16, &g_bcl[(size_t)(Lrow0 + row) * 256 + 128 + s * 8]);
            CP16(sb + OFF_UH + row * 272 + s * 16, &g_stinh[sinb + row * 128 + s * 8]);
            CP16(sb + OFF_UL + row * 272 + s * 16, &g_stinl[sinb + row * 128 + s * 8]);
        }
        if (tid < 64) acsl[tid] = g_acs[base + lt * 64 + tid];
        CP_COMMIT();
        CP_WAIT(0);
    }
    __syncthreads();

    const uint32_t a_base = sb + (16 * w + (lane & 15)) * 272 + (lane >> 4) * 16;
    const uint32_t b_base = sb + OFF_UH + ((lane & 7) + (lane >> 4) * 8) * 272 + ((lane >> 3) & 1) * 16;
    const uint32_t x_base = sb + OFF_XH + ((lane & 7) + ((lane >> 3) & 1) * 8) * 144 + (lane >> 4) * 16;

    float yacc[8][4];
#pragma unroll
    for (int j = 0; j < 8; j++)
#pragma unroll
        for (int v = 0; v < 4; v++) yacc[j][v] = 0.f;

    // Y_off = C . Sin^T
#pragma unroll
    for (int kk = 0; kk < 8; kk++) {
        uint32_t ah[4], al[4];
        ldsm_x4(ah[0], ah[1], ah[2], ah[3], a_base + kk * 32);
        ldsm_x4(al[0], al[1], al[2], al[3], a_base + OFF_CL + kk * 32);
#pragma unroll
        for (int np = 0; np < 4; np++) {
            uint32_t bh[4], bl[4];
            ldsm_x4(bh[0], bh[1], bh[2], bh[3], b_base + np * 4352 + kk * 32);
            ldsm_x4(bl[0], bl[1], bl[2], bl[3], b_base + 17408 + np * 4352 + kk * 32);
            mma16816(yacc[2 * np],     ah, bh[0], bh[1]);
            mma16816(yacc[2 * np + 1], ah, bh[2], bh[3]);
            mma16816(yacc[2 * np],     ah, bl[0], bl[1]);
            mma16816(yacc[2 * np + 1], ah, bl[2], bl[3]);
            mma16816(yacc[2 * np],     al, bh[0], bh[1]);
            mma16816(yacc[2 * np + 1], al, bh[2], bh[3]);
        }
    }
    {
        float e0 = expf(acsl[16 * w + (lane >> 2)]);
        float e1 = expf(acsl[16 * w + (lane >> 2) + 8]);
#pragma unroll
        for (int j = 0; j < 8; j++) {
            yacc[j][0] *= e0; yacc[j][1] *= e0;
            yacc[j][2] *= e1; yacc[j][3] *= e1;
        }
    }

    for (int st = 0; st <= lt; st++) {
        const int Srow0 = c * CHh + st * 64;
        __syncthreads();
        for (int e = tid; e < 1024; e += 128) {
            int row = e >> 4, s = e & 15;
            CP16(sb + OFF_UH + row * 272 + s * 16, &g_bch[(size_t)(Srow0 + row) * 256 + s * 8]);
            CP16(sb + OFF_UL + row * 272 + s * 16, &g_bcl[(size_t)(Srow0 + row) * 256 + s * 8]);
        }
        for (int e = tid; e < 512; e += 128) {
            int row = e >> 3, s = e & 7;
            CP16(sb + OFF_XH + row * 144 + s * 16, &g_xdth[(size_t)(Srow0 + row) * INTER + h * 64 + s * 8]);
            CP16(sb + OFF_XL + row * 144 + s * 16, &g_xdtl[(size_t)(Srow0 + row) * INTER + h * 64 + s * 8]);
        }
        if (tid < 64) acss[tid] = g_acs[base + st * 64 + tid];
        CP_COMMIT();
        CP_WAIT(0);
        __syncthreads();

        float gacc[8][4];
#pragma unroll
        for (int j = 0; j < 8; j++)
#pragma unroll
            for (int v = 0; v < 4; v++) gacc[j][v] = 0.f;
#pragma unroll
        for (int kk = 0; kk < 8; kk++) {
            uint32_t ah[4], al[4];
            ldsm_x4(ah[0], ah[1], ah[2], ah[3], a_base + kk * 32);
            ldsm_x4(al[0], al[1], al[2], al[3], a_base + OFF_CL + kk * 32);
#pragma unroll
            for (int np = 0; np < 4; np++) {
                uint32_t bh[4], bl[4];
                ldsm_x4(bh[0], bh[1], bh[2], bh[3], b_base + np * 4352 + kk * 32);
                ldsm_x4(bl[0], bl[1], bl[2], bl[3], b_base + 17408 + np * 4352 + kk * 32);
                mma16816(gacc[2 * np],     ah, bh[0], bh[1]);
                mma16816(gacc[2 * np + 1], ah, bh[2], bh[3]);
                mma16816(gacc[2 * np],     ah, bl[0], bl[1]);
                mma16816(gacc[2 * np + 1], ah, bl[2], bl[3]);
                mma16816(gacc[2 * np],     al, bh[0], bh[1]);
                mma16816(gacc[2 * np + 1], al, bh[2], bh[3]);
            }
        }

        {
            float rA = acsl[16 * w + (lane >> 2)];
            float rB = acsl[16 * w + (lane >> 2) + 8];
            bool diag = (st == lt);
            int l0 = 16 * w + (lane >> 2);
#pragma unroll
            for (int j = 0; j < 8; j++) {
                int s0 = 8 * j + 2 * (lane & 3);
                float c0 = acss[s0], c1 = acss[s0 + 1];
                float e00 = expf(rA - c0), e01 = expf(rA - c1);
                float e10 = expf(rB - c0), e11 = expf(rB - c1);
                if (diag) {
                    if (s0 > l0)         e00 = 0.f;
                    if (s0 + 1 > l0)     e01 = 0.f;
                    if (s0 > l0 + 8)     e10 = 0.f;
                    if (s0 + 1 > l0 + 8) e11 = 0.f;
                }
                gacc[j][0] *= e00; gacc[j][1] *= e01;
                gacc[j][2] *= e10; gacc[j][3] *= e11;
            }
        }

#pragma unroll
        for (int t = 0; t < 4; t++) {
            uint32_t gah[4], gal[4];
            {
                __nv_bfloat16 h0, h1, h2, h3, l0b, l1b, l2b, l3b;
                split2(gacc[2 * t][0], h0, l0b); split2(gacc[2 * t][1], h1, l1b);
                split2(gacc[2 * t][2], h2, l2b); split2(gacc[2 * t][3], h3, l3b);
                gah[0] = pk(h0, h1); gah[1] = pk(h2, h3);
                gal[0] = pk(l0b, l1b); gal[1] = pk(l2b, l3b);
                split2(gacc[2 * t + 1][0], h0, l0b); split2(gacc[2 * t + 1][1], h1, l1b);
                split2(gacc[2 * t + 1][2], h2, l2b); split2(gacc[2 * t + 1][3], h3, l3b);
                gah[2] = pk(h0, h1); gah[3] = pk(h2, h3);
                gal[2] = pk(l0b, l1b); gal[3] = pk(l2b, l3b);
            }
#pragma unroll
            for (int np = 0; np < 4; np++) {
                uint32_t xh[4], xl[4];
                ldsm_x4_t(xh[0], xh[1], xh[2], xh[3], x_base + t * 2304 + np * 32);
                ldsm_x4_t(xl[0], xl[1], xl[2], xl[3], x_base + 9216 + t * 2304 + np * 32);
                mma16816(yacc[2 * np],     gah, xh[0], xh[1]);
                mma16816(yacc[2 * np + 1], gah, xh[2], xh[3]);
                mma16816(yacc[2 * np],     gah, xl[0], xl[1]);
                mma16816(yacc[2 * np + 1], gah, xl[2], xl[3]);
                mma16816(yacc[2 * np],     gal, xh[0], xh[1]);
                mma16816(yacc[2 * np + 1], gal, xh[2], xh[3]);
            }
        }
    }

    // epilogue: + x*D, write g_y
    float dh = Dv[h];
    int r0 = Lrow0 + 16 * w + (lane >> 2);
#pragma unroll
    for (int j = 0; j < 8; j++) {
        int p = h * 64 + 8 * j + 2 * (lane & 3);
        float2 x0 = *(const float2*)&g_x[(size_t)r0 * INTER + p];
        float2 x1 = *(const float2*)&g_x[(size_t)(r0 + 8) * INTER + p];
        *(float2*)&g_y[(size_t)r0 * INTER + p] =
            make_float2(yacc[j][0] + x0.x * dh, yacc[j][1] + x0.y * dh);
        *(float2*)&g_y[(size_t)(r0 + 8) * INTER + p] =
            make_float2(yacc[j][2] + x1.x * dh, yacc[j][3] + x1.y * dh);
    }
}

// ---------------- gated RMSNorm fused with bf16 hi/lo split ----------------
__global__ void rmsnorm_split_kernel(const float* __restrict__ nw) {
    int l = blockIdx.x;
    int tid = threadIdx.x;
    float v[16];
    float ss = 0.f;
#pragma unroll
    for (int i = 0; i < 16; i++) {
        int col = tid + i * 256;
        float y = g_y[(size_t)l * INTER + col];
        float z = g_zx[(size_t)l * OUT_IN + col];
        float yf = y * (z / (1.f + expf(-z)));
        v[i] = yf;
        ss = fmaf(yf, yf, ss);
    }
    __shared__ float red[256];
    red[tid] = ss;
    __syncthreads();
    for (int o = 128; o > 0; o >>= 1) {
        if (tid < o) red[tid] += red[tid + o];
        __syncthreads();
    }
    float scale = rsqrtf(red[0] / (float)INTER + 1e-5f);
#pragma unroll
    for (int i = 0; i < 16; i++) {
        int col = tid + i * 256;
        float yn = v[i] * scale * nw[col];
        __nv_bfloat16 h, lo;
        split2(yn, h, lo);
        gA2h[(size_t)l * INTER + col] = h;
        gA2l[(size_t)l * INTER + col] = lo;
    }
}

// ---------------- launch ----------------
extern "C" void kernel_launch(void* const* d_in, const int* in_sizes, int n_in,
                              void* d_out, int out_size) {
    const float* hs      = (const float*)d_in[0];
    const float* W_in    = (const float*)d_in[1];
    const float* conv_w  = (const float*)d_in[2];
    const float* conv_b  = (const float*)d_in[3];
    const float* dt_bias = (const float*)d_in[4];
    const float* A_log   = (const float*)d_in[5];
    const float* Dv      = (const float*)d_in[6];
    const float* norm_w  = (const float*)d_in[7];
    const float* W_out   = (const float*)d_in[8];
    float* out = (float*)d_out;

    void *p_zx;
    void *pA1h, *pA1l, *pB1h, *pB1l, *pA2h, *pA2l, *pB2h, *pB2l;
    cudaGetSymbolAddress(&p_zx, g_zx);
    cudaGetSymbolAddress(&pA1h, gA1h); cudaGetSymbolAddress(&pA1l, gA1l);
    cudaGetSymbolAddress(&pB1h, gB1h); cudaGetSymbolAddress(&pB1l, gB1l);
    cudaGetSymbolAddress(&pA2h, gA2h); cudaGetSymbolAddress(&pA2l, gA2l);
    cudaGetSymbolAddress(&pB2h, gB2h); cudaGetSymbolAddress(&pB2l, gB2l);

    const int GSMEM = NSTG * STAGE_B;   // 102400 -> 2 CTAs/SM
    cudaFuncSetAttribute(gemm_hmma, cudaFuncAttributeMaxDynamicSharedMemorySize, GSMEM);
    cudaFuncSetAttribute(y_hmma, cudaFuncAttributeMaxDynamicSharedMemorySize, 88576);
    cudaFuncSetAttribute(states_hmma, cudaFuncAttributeMaxDynamicSharedMemorySize, 54272);

    // 1) split hs -> A1
    split_kernel<<<(L_ * HIDD / 4 + 255) / 256, 256>>>(hs, (__nv_bfloat16*)pA1h, (__nv_bfloat16*)pA1l, L_ * HIDD / 4);
    // 2) transpose+split W_in -> B1
    transpose_split_kernel<<<dim3(OUT_IN_PAD / 32, HIDD / 32), dim3(32, 8)>>>(
        W_in, (__nv_bfloat16*)pB1h, (__nv_bfloat16*)pB1l, HIDD, OUT_IN);
    // 3) transpose+split W_out -> B2
    transpose_split_kernel<<<dim3(HIDD / 32, INTER / 32), dim3(32, 8)>>>(
        W_out, (__nv_bfloat16*)pB2h, (__nv_bfloat16*)pB2l, INTER, HIDD);
    // 4) zxbcdt = hs @ W_in   <-- profiled launch
    gemm_hmma<<<dim3(OUT_IN_PAD / 128, L_ / 128), 256, GSMEM>>>(
        (const __nv_bfloat16*)pA1h, (const __nv_bfloat16*)pA1l,
        (const __nv_bfloat16*)pB1h, (const __nv_bfloat16*)pB1l,
        (float*)p_zx, OUT_IN, HIDD);
    // 5) dt + per-chunk cumsum
    dtcs_kernel<<<dim3(NC, Hh), 256>>>(dt_bias, A_log);
    // 6) fused conv + silu + xdt/BC splits
    conv_fused_kernel<<<dim3(CONV_DIM / 256, L_), 256>>>(conv_w, conv_b);
    // 7) per-chunk states (HMMA, cp.async staging)
    states_hmma<<<dim3(NC, Hh), 128, 54272>>>();
    // 8) inter-chunk scan
    scan_kernel<<<(Hh * Pp * Nn) / 256, 256>>>();
    // 9) Y (HMMA, cp.async staging)
    y_hmma<<<dim3(4, NC, Hh), 128, 88576>>>(Dv);
    // 10) gated RMSNorm + split A2
    rmsnorm_split_kernel<<<L_, 256>>>(norm_w);
    // 11) out = yn @ W_out
    gemm_hmma<<<dim3(HIDD / 128, L_ / 128), 256, GSMEM>>>(
        (const __nv_bfloat16*)pA2h, (const __nv_bfloat16*)pA2l,
        (const __nv_bfloat16*)pB2h, (const __nv_bfloat16*)pB2l,
        out, HIDD, INTER);
}